// round 11
// baseline (speedup 1.0000x reference)
#include <cuda_runtime.h>
#include <cuda_fp16.h>
#include <stdint.h>
#include <math.h>

// ---------------- problem constants ----------------
#define BQ 4
#define DQ 768
#define SQ 1569                  // 1 + 8*196
#define TQ (BQ*SQ)               // 6276 tokens
#define TQPAD 6400               // padded rows for tiled A operands
#define HIDQ 3072
#define LQ 12
#define EPSQ 1e-6f
#define SCALEQ 0.125f            // 64^-0.5

// weight pool offsets (halfs) -- tiled layouts, same element counts
#define W_PATCH 0
#define W_TQW   (W_PATCH + 768*768)
#define W_TPW   (W_TQW + (size_t)LQ*3*DQ*DQ)
#define W_AQW   (W_TPW + (size_t)LQ*DQ*DQ)
#define W_APW   (W_AQW + (size_t)LQ*3*DQ*DQ)
#define W_F1W   (W_APW + (size_t)LQ*DQ*DQ)
#define W_F2W   (W_F1W + (size_t)LQ*HIDQ*DQ)
#define W_TOTAL (W_F2W + (size_t)LQ*DQ*HIDQ)

// ---------------- scratch (static device globals) ----------------
__device__ float g_xt [(size_t)TQ*DQ];
__device__ float g_qkv[(size_t)TQ*3*DQ];
__device__ float g_res[(size_t)TQ*DQ];
__device__ __half g_aH[(size_t)TQPAD*DQ],  g_aL[(size_t)TQPAD*DQ];    // zero-padded rows
__device__ __half g_hH[(size_t)TQPAD*HIDQ], g_hL[(size_t)TQPAD*HIDQ];
__device__ __half g_w [W_TOTAL];

// ---------------- tiled + swizzled index ----------------
// layout: [k>>6][row (rows total)][64], within-row 16B chunk c stored at c ^ (row&7)
__device__ __forceinline__ size_t tIdx(size_t rows, int m, int k) {
    return ((size_t)(k >> 6) * rows + m) * 64
         + ((((k >> 3) & 7) ^ (m & 7)) << 3) + (k & 7);
}

// ---------------- helpers ----------------
__device__ __forceinline__ uint32_t smem_u32(const void* p) {
    uint32_t a;
    asm("{ .reg .u64 t; cvta.to.shared.u64 t, %1; cvt.u32.u64 %0, t; }" : "=r"(a) : "l"(p));
    return a;
}

#define MBAR_INIT(addr, cnt) \
    asm volatile("mbarrier.init.shared.b64 [%0], %1;" :: "r"(addr), "r"((uint32_t)(cnt)) : "memory")
#define MBAR_EXPECT(addr, bytes) \
    asm volatile("mbarrier.arrive.expect_tx.shared.b64 _, [%0], %1;" :: "r"(addr), "r"((uint32_t)(bytes)) : "memory")
#define FENCE_ASYNC() asm volatile("fence.proxy.async.shared::cta;" ::: "memory")

__device__ __forceinline__ void mbar_wait(uint32_t mbar, uint32_t parity) {
    asm volatile(
        "{\n\t.reg .pred P;\n\t"
        "W_%=:\n\t"
        "mbarrier.try_wait.parity.acquire.cta.shared::cta.b64 P, [%0], %1, 0x989680;\n\t"
        "@P bra.uni D_%=;\n\t"
        "bra.uni W_%=;\n\t"
        "D_%=:\n\t}"
        :: "r"(mbar), "r"(parity) : "memory");
}

__device__ __forceinline__ void bulkcp(uint32_t dst, const void* src, uint32_t bytes, uint32_t mbar) {
    asm volatile("cp.async.bulk.shared::cluster.global.mbarrier::complete_tx::bytes "
                 "[%0], [%1], %2, [%3];"
                 :: "r"(dst), "l"(src), "r"(bytes), "r"(mbar) : "memory");
}

#define LDSMX4(r, addr) \
    asm volatile("ldmatrix.sync.aligned.m8n8.x4.shared.b16 {%0,%1,%2,%3}, [%4];" \
                 : "=r"((r)[0]), "=r"((r)[1]), "=r"((r)[2]), "=r"((r)[3]) : "r"(addr))

__device__ __forceinline__ void mma16816(float* c,
        uint32_t a0, uint32_t a1, uint32_t a2, uint32_t a3,
        uint32_t b0, uint32_t b1) {
    asm volatile(
        "mma.sync.aligned.m16n8k16.row.col.f32.f16.f16.f32 "
        "{%0,%1,%2,%3}, {%4,%5,%6,%7}, {%8,%9}, {%0,%1,%2,%3};\n"
        : "+f"(c[0]), "+f"(c[1]), "+f"(c[2]), "+f"(c[3])
        : "r"(a0), "r"(a1), "r"(a2), "r"(a3), "r"(b0), "r"(b1));
}

__device__ __forceinline__ void wsplit(__half* hi, __half* lo, size_t i, float v) {
    __half h = __float2half_rn(v);
    hi[i] = h;
    lo[i] = __float2half_rn(v - __half2float(h));
}

__device__ __forceinline__ float block_red(float v, int isMax) {
    __shared__ float red[8];
    int lane = threadIdx.x & 31, w = threadIdx.x >> 5;
    #pragma unroll
    for (int o = 16; o; o >>= 1) {
        float t = __shfl_xor_sync(0xffffffffu, v, o);
        v = isMax ? fmaxf(v, t) : (v + t);
    }
    __syncthreads();
    if (lane == 0) red[w] = v;
    __syncthreads();
    float t = red[0];
    #pragma unroll
    for (int i = 1; i < 8; i++) t = isMax ? fmaxf(t, red[i]) : (t + red[i]);
    return t;
}

// ---------------- weight convert fp32 -> tiled/swizzled fp16 ----------------
__global__ void cvtw_k(const float* __restrict__ w, __half* __restrict__ o,
                       int N, int K) {
    int K4 = K >> 2;
    int idx = blockIdx.x * 256 + threadIdx.x;
    if (idx >= N * K4) return;
    int n = idx / K4, kq = idx - n * K4;
    int k = kq * 4;
    float4 v = ((const float4*)w)[idx];
    __half2 a = __floats2half2_rn(v.x, v.y);
    __half2 b = __floats2half2_rn(v.z, v.w);
    uint2 r;
    r.x = *(uint32_t*)&a; r.y = *(uint32_t*)&b;
    *(uint2*)&o[tIdx(N, n, k)] = r;
}

// ---------------- im2col -> tiled split fp16 ----------------
__global__ void im2col_k(const float* __restrict__ x,
                         __half* __restrict__ oH, __half* __restrict__ oL) {
    int idx = blockIdx.x * 256 + threadIdx.x;
    if (idx >= 6272 * 768) return;
    int r = idx / 768, c = idx % 768;
    int bf = r / 196, p = r % 196;
    int ph = p / 14, pw = p % 14;
    int ch = c >> 8, rem = c & 255;
    int i = rem >> 4, j = rem & 15;
    size_t off = (((size_t)bf * 3 + ch) * 224 + ph * 16 + i) * 224 + pw * 16 + j;
    wsplit(oH, oL, tIdx(TQPAD, r, c), x[off]);
}

// ---------------- assemble tokens (fp32 xt) ----------------
__global__ void assemble_k(const float* __restrict__ pe,
                           const float* __restrict__ patch_b,
                           const float* __restrict__ cls_tok,
                           const float* __restrict__ pos,
                           const float* __restrict__ temp,
                           float* __restrict__ xt) {
    int idx = blockIdx.x * 256 + threadIdx.x;
    if (idx >= TQ * DQ) return;
    int t = idx / DQ, dd = idx % DQ;
    int b = t / SQ, s = t % SQ;
    float v;
    if (s == 0) {
        v = cls_tok[dd] + pos[dd];
    } else {
        int sp = s - 1, fr = sp / 196, p = sp % 196;
        v = pe[((size_t)(b * 8 + fr) * 196 + p) * 768 + dd] + patch_b[dd]
            + pos[(size_t)(1 + p) * 768 + dd] + temp[(size_t)fr * 768 + dd];
    }
    xt[idx] = v;
}

// ---------------- layernorm -> tiled split fp16 ----------------
__global__ void ln_k(const float* __restrict__ x, const float* __restrict__ sc,
                     const float* __restrict__ bi,
                     __half* __restrict__ oH, __half* __restrict__ oL) {
    int row = blockIdx.x, tid = threadIdx.x;
    const float* xr = x + (size_t)row * DQ;
    float r0 = xr[tid], r1 = xr[tid + 256], r2 = xr[tid + 512];
    float mean = block_red(r0 + r1 + r2, 0) * (1.f / 768.f);
    float d0 = r0 - mean, d1 = r1 - mean, d2 = r2 - mean;
    float var = block_red(d0 * d0 + d1 * d1 + d2 * d2, 0) * (1.f / 768.f);
    float inv = rsqrtf(var + EPSQ);
    wsplit(oH, oL, tIdx(TQPAD, row, tid),       d0 * inv * sc[tid]       + bi[tid]);
    wsplit(oH, oL, tIdx(TQPAD, row, tid + 256), d1 * inv * sc[tid + 256] + bi[tid + 256]);
    wsplit(oH, oL, tIdx(TQPAD, row, tid + 512), d2 * inv * sc[tid + 512] + bi[tid + 512]);
}

__global__ void final_ln_k(const float* __restrict__ xt, const float* __restrict__ sc,
                           const float* __restrict__ bi, float* __restrict__ out) {
    int b = blockIdx.x, tid = threadIdx.x;
    const float* xr = xt + (size_t)(b * SQ) * DQ;
    float r0 = xr[tid], r1 = xr[tid + 256], r2 = xr[tid + 512];
    float mean = block_red(r0 + r1 + r2, 0) * (1.f / 768.f);
    float d0 = r0 - mean, d1 = r1 - mean, d2 = r2 - mean;
    float var = block_red(d0 * d0 + d1 * d1 + d2 * d2, 0) * (1.f / 768.f);
    float inv = rsqrtf(var + EPSQ);
    float* yr = out + (size_t)b * DQ;
    yr[tid]       = d0 * inv * sc[tid]       + bi[tid];
    yr[tid + 256] = d1 * inv * sc[tid + 256] + bi[tid + 256];
    yr[tid + 512] = d2 * inv * sc[tid + 512] + bi[tid + 512];
}

// ============== HMMA GEMM v8: 128x128 tile, bulk fills, 3-stage ==============
// C[M,N] = A[M,K] @ W[N,K]^T; A fp16 hi/lo (2-term), W fp16, fp32 acc.
// 256 thr, 8 warps (2x4), warp tile 64x32, tiled+swizzled gmem operands.
#define ARR_A 16384                  // 128 rows x 128B
#define ARR_B 16384                  // 128 rows x 128B
#define STGB  (2*ARR_A + ARR_B)      // 49152
#define NSTG  3
#define GT_SMEM (NSTG*STGB)          // 147456

template<int ACT, int OS, int RS>
__global__ void __launch_bounds__(256, 1) gemm_k(
    const __half* __restrict__ aH, const __half* __restrict__ aL,
    const __half* __restrict__ wH,
    const float* __restrict__ bias, const float* __restrict__ res,
    float* __restrict__ outF,
    __half* __restrict__ oH, __half* __restrict__ oL,
    int M, int Mpad, int N, int K) {
    extern __shared__ char smem[];
    __shared__ __align__(8) uint64_t mbar_store[NSTG];
    uint32_t sb = smem_u32(smem);
    uint32_t mb = smem_u32(mbar_store);
    int tid = threadIdx.x;
    int lane = tid & 31, w = tid >> 5;
    int warpM = w >> 2, warpN = w & 3;       // 2 x 4 warps, warp tile 64x32
    int g = lane >> 2, q = lane & 3;
    int bm = blockIdx.y * 128, bn = blockIdx.x * 128;
    const int nkt = K >> 6;

    if (tid == 0) {
        #pragma unroll
        for (int s = 0; s < NSTG; s++) MBAR_INIT(mb + s * 8, 1);
        FENCE_ASYNC();
    }
    __syncthreads();

    auto fill = [&](int j) {
        int fb = j % NSTG;
        uint32_t st = sb + fb * STGB;
        uint32_t m = mb + fb * 8;
        MBAR_EXPECT(m, STGB);
        bulkcp(st,             aH + ((size_t)j * Mpad + bm) * 64, ARR_A, m);
        bulkcp(st + ARR_A,     aL + ((size_t)j * Mpad + bm) * 64, ARR_A, m);
        bulkcp(st + 2 * ARR_A, wH + ((size_t)j * N + bn) * 64,    ARR_B, m);
    };

    if (tid == 0) { fill(0); fill(1); }

    float acc[4][4][4];
    #pragma unroll
    for (int i = 0; i < 4; i++)
        #pragma unroll
        for (int j = 0; j < 4; j++)
            #pragma unroll
            for (int c = 0; c < 4; c++) acc[i][j][c] = 0.f;

    // swizzled chunk byte offsets per kk (lane-dependent, loop-invariant)
    int lane7 = lane & 7, hi = lane >> 4;
    uint32_t cb[4];
    #pragma unroll
    for (int kk = 0; kk < 4; kk++) cb[kk] = (uint32_t)(((kk * 2 + hi) ^ lane7) << 4);
    uint32_t arow_off = (uint32_t)(warpM * 64 + (lane & 15)) * 128;
    uint32_t brow_off = (uint32_t)(warpN * 32 + (lane & 15)) * 128 + 2 * ARR_A;

    for (int kt = 0; kt < nkt; kt++) {
        int d3 = kt / 3;
        int buf = kt - d3 * 3;
        mbar_wait(mb + buf * 8, (uint32_t)(d3 & 1));
        __syncthreads();
        if (tid == 0 && kt + 2 < nkt) fill(kt + 2);

        uint32_t st = sb + buf * STGB;
        #pragma unroll
        for (int kk = 0; kk < 4; kk++) {
            uint32_t ah[4][4], al[4][4];
            #pragma unroll
            for (int i = 0; i < 4; i++) {
                uint32_t addr = st + arow_off + i * 2048 + cb[kk];
                LDSMX4(ah[i], addr);
                LDSMX4(al[i], addr + ARR_A);
            }
            #pragma unroll
            for (int jj = 0; jj < 2; jj++) {
                uint32_t bh[4];
                LDSMX4(bh, st + brow_off + jj * 2048 + cb[kk]);
                #pragma unroll
                for (int sel = 0; sel < 2; sel++) {
                    int j = jj * 2 + sel;
                    uint32_t b0 = bh[sel], b1 = bh[sel + 2];
                    #pragma unroll
                    for (int i = 0; i < 4; i++) {
                        mma16816(acc[i][j], ah[i][0], ah[i][1], ah[i][2], ah[i][3], b0, b1);
                        mma16816(acc[i][j], al[i][0], al[i][1], al[i][2], al[i][3], b0, b1);
                    }
                }
            }
        }
    }

    // epilogue: m = bm + warpM*64 + i*16 + g (+8), n = bn + warpN*32 + j*8 + q*2
    #pragma unroll
    for (int i = 0; i < 4; i++) {
        int m0 = bm + warpM * 64 + i * 16 + g;
        #pragma unroll
        for (int j = 0; j < 4; j++) {
            int n0 = bn + warpN * 32 + j * 8 + q * 2;
            float bx = bias ? bias[n0] : 0.f;
            float by = bias ? bias[n0 + 1] : 0.f;
            #pragma unroll
            for (int half = 0; half < 2; half++) {
                int m = m0 + half * 8;
                if (m >= M) continue;
                float v0 = acc[i][j][half * 2 + 0] + bx;
                float v1 = acc[i][j][half * 2 + 1] + by;
                if (RS) {
                    const float* rp = res + (size_t)m * N + n0;
                    v0 += rp[0]; v1 += rp[1];
                }
                if (ACT) {
                    v0 = 0.5f * v0 * (1.f + erff(v0 * 0.70710678118654752f));
                    v1 = 0.5f * v1 * (1.f + erff(v1 * 0.70710678118654752f));
                }
                if (OS) {
                    size_t o = tIdx(TQPAD, m, n0);
                    wsplit(oH, oL, o,     v0);
                    wsplit(oH, oL, o + 1, v1);
                } else {
                    *(float2*)(outF + (size_t)m * N + n0) = make_float2(v0, v1);
                }
            }
        }
    }
}

// ---------------- cls-row attention device fn ----------------
__device__ void cls_attn_dev(const float* __restrict__ qkv,
                             __half* __restrict__ oH, __half* __restrict__ oL,
                             int bh, float* ws) {
    float* sc = ws;
    float* qv = ws + 1600;
    float* op = ws + 1664;
    int b = bh / 12, h = bh % 12;
    int tid = threadIdx.x;
    size_t base = (size_t)(b * SQ) * 2304 + (size_t)h * 64;
    if (tid < 64) qv[tid] = qkv[base + tid] * SCALEQ;
    __syncthreads();
    float lmax = -1e30f;
    for (int s = tid; s < SQ; s += 256) {
        const float* kp = qkv + (size_t)(b * SQ + s) * 2304 + 768 + h * 64;
        float d = 0.f;
        #pragma unroll
        for (int i = 0; i < 64; i++) d += qv[i] * kp[i];
        sc[s] = d; lmax = fmaxf(lmax, d);
    }
    float mx = block_red(lmax, 1);
    float lsum = 0.f;
    for (int s = tid; s < SQ; s += 256) {
        float e = expf(sc[s] - mx);
        sc[s] = e; lsum += e;
    }
    float den = block_red(lsum, 0);
    __syncthreads();
    int part = tid >> 6, d = tid & 63;
    float acc = 0.f;
    for (int s = part; s < SQ; s += 4)
        acc += sc[s] * qkv[(size_t)(b * SQ + s) * 2304 + 1536 + h * 64 + d];
    op[tid] = acc;
    __syncthreads();
    if (tid < 64) {
        float t = op[tid] + op[tid + 64] + op[tid + 128] + op[tid + 192];
        wsplit(oH, oL, tIdx(TQPAD, b * SQ, h * 64 + tid), t / den);
    }
}

// ---------------- fused time + cls attention ----------------
#define CLS_WS_BYTES (1920*4)
__global__ void time_cls_k(const float* __restrict__ qkv,
                           __half* __restrict__ oH, __half* __restrict__ oL) {
    extern __shared__ float ws[];
    if (blockIdx.x >= 1176) {
        cls_attn_dev(qkv, oH, oL, blockIdx.x - 1176, ws);
        return;
    }
    int g = blockIdx.x * 8 + (threadIdx.x >> 5);
    int lane = threadIdx.x & 31;
    int bh = g / 196, pos = g % 196;
    int b = bh / 12, h = bh % 12;
    float K0[9], K1[9], V0[9], V1[9];
    #pragma unroll
    for (int kk = 0; kk < 9; kk++) {
        int s = kk ? (1 + (kk - 1) * 196 + pos) : 0;
        size_t o = (size_t)(b * SQ + s) * 2304 + h * 64;
        K0[kk] = qkv[o + 768 + lane];  K1[kk] = qkv[o + 768 + lane + 32];
        V0[kk] = qkv[o + 1536 + lane]; V1[kk] = qkv[o + 1536 + lane + 32];
    }
    for (int fq = 0; fq < 8; fq++) {
        int sq = 1 + fq * 196 + pos;
        size_t oq = (size_t)(b * SQ + sq) * 2304 + h * 64;
        float q0 = qkv[oq + lane] * SCALEQ, q1 = qkv[oq + lane + 32] * SCALEQ;
        float sc[9];
        #pragma unroll
        for (int kk = 0; kk < 9; kk++) {
            float p = q0 * K0[kk] + q1 * K1[kk];
            #pragma unroll
            for (int o = 16; o; o >>= 1) p += __shfl_xor_sync(0xffffffffu, p, o);
            sc[kk] = p;
        }
        float mx = sc[0];
        #pragma unroll
        for (int kk = 1; kk < 9; kk++) mx = fmaxf(mx, sc[kk]);
        float den = 0.f;
        #pragma unroll
        for (int kk = 0; kk < 9; kk++) { sc[kk] = expf(sc[kk] - mx); den += sc[kk]; }
        float inv = 1.f / den;
        float a0 = 0.f, a1 = 0.f;
        #pragma unroll
        for (int kk = 0; kk < 9; kk++) { a0 += sc[kk] * V0[kk]; a1 += sc[kk] * V1[kk]; }
        int m = b * SQ + sq;
        wsplit(oH, oL, tIdx(TQPAD, m, h * 64 + lane),      a0 * inv);
        wsplit(oH, oL, tIdx(TQPAD, m, h * 64 + lane + 32), a1 * inv);
    }
}

// ---------------- fused space + cls attention ----------------
#define SPACE_SMEM ((197*65*2 + 8*197 + 8*64) * 4)
__global__ void space_cls_k(const float* __restrict__ qkv,
                            __half* __restrict__ oH, __half* __restrict__ oL) {
    extern __shared__ float sm[];
    if (blockIdx.x >= 384) {
        cls_attn_dev(qkv, oH, oL, blockIdx.x - 384, sm);
        return;
    }
    float* Ks = sm;
    float* Vs = Ks + 197 * 65;
    float* pb = Vs + 197 * 65;
    float* qb = pb + 8 * 197;
    int blk = blockIdx.x;
    int fr = blk % 8, h = (blk / 8) % 12, b = blk / 96;
    int tid = threadIdx.x, lane = tid & 31, w = tid >> 5;
    for (int idx = tid; idx < 197 * 64; idx += 256) {
        int kk = idx >> 6, d = idx & 63;
        int s = kk ? (1 + fr * 196 + kk - 1) : 0;
        size_t o = (size_t)(b * SQ + s) * 2304 + h * 64;
        Ks[kk * 65 + d] = qkv[o + 768 + d];
        Vs[kk * 65 + d] = qkv[o + 1536 + d];
    }
    __syncthreads();
    for (int qi = w; qi < 196; qi += 8) {
        int sq = 1 + fr * 196 + qi;
        size_t oq = (size_t)(b * SQ + sq) * 2304 + h * 64;
        qb[w * 64 + lane]      = qkv[oq + lane] * SCALEQ;
        qb[w * 64 + lane + 32] = qkv[oq + lane + 32] * SCALEQ;
        __syncwarp();
        float ls[7];
        float lmax = -1e30f;
        int cnt = 0;
        for (int kk = lane; kk < 197; kk += 32) {
            float s = 0.f;
            #pragma unroll
            for (int d = 0; d < 64; d++) s += qb[w * 64 + d] * Ks[kk * 65 + d];
            ls[cnt++] = s; lmax = fmaxf(lmax, s);
        }
        #pragma unroll
        for (int o = 16; o; o >>= 1) lmax = fmaxf(lmax, __shfl_xor_sync(0xffffffffu, lmax, o));
        float lsum = 0.f; cnt = 0;
        for (int kk = lane; kk < 197; kk += 32) {
            float e = expf(ls[cnt++] - lmax);
            pb[w * 197 + kk] = e; lsum += e;
        }
        #pragma unroll
        for (int o = 16; o; o >>= 1) lsum += __shfl_xor_sync(0xffffffffu, lsum, o);
        float inv = 1.f / lsum;
        __syncwarp();
        float a0 = 0.f, a1 = 0.f;
        for (int kk = 0; kk < 197; kk++) {
            float p = pb[w * 197 + kk];
            a0 += p * Vs[kk * 65 + lane];
            a1 += p * Vs[kk * 65 + lane + 32];
        }
        int m = b * SQ + sq;
        wsplit(oH, oL, tIdx(TQPAD, m, h * 64 + lane),      a0 * inv);
        wsplit(oH, oL, tIdx(TQPAD, m, h * 64 + lane + 32), a1 * inv);
        __syncwarp();
    }
}

// ================== host orchestration ==================
// mode: 0 fp32 out, 1 fp32 out + residual, 2 gelu + tiled split-fp16 out
static void gemm(const __half* aH, const __half* aL, const __half* wHp,
                 const float* bias, const float* res,
                 float* outF, __half* oH, __half* oL,
                 int M, int Mpad, int N, int K, int mode) {
    dim3 g(N / 128, (M + 127) / 128);
    if (mode == 0)
        gemm_k<0,0,0><<<g, 256, GT_SMEM>>>(aH, aL, wHp, bias, res, outF, oH, oL, M, Mpad, N, K);
    else if (mode == 1)
        gemm_k<0,0,1><<<g, 256, GT_SMEM>>>(aH, aL, wHp, bias, res, outF, oH, oL, M, Mpad, N, K);
    else
        gemm_k<1,1,0><<<g, 256, GT_SMEM>>>(aH, aL, wHp, bias, res, outF, oH, oL, M, Mpad, N, K);
}

extern "C" void kernel_launch(void* const* d_in, const int* in_sizes, int n_in,
                              void* d_out, int out_size) {
    const float* x       = (const float*)d_in[0];
    const float* patch_w = (const float*)d_in[1];
    const float* patch_b = (const float*)d_in[2];
    const float* cls_tok = (const float*)d_in[3];
    const float* pos     = (const float*)d_in[4];
    const float* temp    = (const float*)d_in[5];
    const float* n1s = (const float*)d_in[6],  *n1b = (const float*)d_in[7];
    const float* n2s = (const float*)d_in[8],  *n2b = (const float*)d_in[9];
    const float* n3s = (const float*)d_in[10], *n3b = (const float*)d_in[11];
    const float* aqw = (const float*)d_in[12], *aqb = (const float*)d_in[13];
    const float* apw = (const float*)d_in[14], *apb = (const float*)d_in[15];
    const float* tqw = (const float*)d_in[16], *tqb = (const float*)d_in[17];
    const float* tpw = (const float*)d_in[18], *tpb = (const float*)d_in[19];
    const float* f1w = (const float*)d_in[20], *f1b = (const float*)d_in[21];
    const float* f2w = (const float*)d_in[22], *f2b = (const float*)d_in[23];
    const float* nfs = (const float*)d_in[24], *nfb = (const float*)d_in[25];
    float* out = (float*)d_out;

    float *xt, *qkv, *res;
    __half *aH, *aL, *hH, *hL, *wp;
    cudaGetSymbolAddress((void**)&xt,  g_xt);
    cudaGetSymbolAddress((void**)&qkv, g_qkv);
    cudaGetSymbolAddress((void**)&res, g_res);
    cudaGetSymbolAddress((void**)&aH,  g_aH);
    cudaGetSymbolAddress((void**)&aL,  g_aL);
    cudaGetSymbolAddress((void**)&hH,  g_hH);
    cudaGetSymbolAddress((void**)&hL,  g_hL);
    cudaGetSymbolAddress((void**)&wp,  g_w);

    cudaFuncSetAttribute(space_cls_k, cudaFuncAttributeMaxDynamicSharedMemorySize, SPACE_SMEM);
    cudaFuncSetAttribute(gemm_k<0,0,0>, cudaFuncAttributeMaxDynamicSharedMemorySize, GT_SMEM);
    cudaFuncSetAttribute(gemm_k<0,0,1>, cudaFuncAttributeMaxDynamicSharedMemorySize, GT_SMEM);
    cudaFuncSetAttribute(gemm_k<1,1,0>, cudaFuncAttributeMaxDynamicSharedMemorySize, GT_SMEM);

    // ---- one-shot weight conversion (fp32 -> tiled/swizzled fp16 pool) ----
    {
        {
            int n4 = 768 * 768 / 4;
            cvtw_k<<<(n4 + 255) / 256, 256>>>(patch_w, wp + W_PATCH, 768, 768);
        }
        for (int l = 0; l < LQ; l++) {
            { int n4 = 3*DQ*DQ/4;
              cvtw_k<<<(n4+255)/256, 256>>>(tqw + (size_t)l*3*DQ*DQ, wp + W_TQW + (size_t)l*3*DQ*DQ, 3*DQ, DQ); }
            { int n4 = DQ*DQ/4;
              cvtw_k<<<(n4+255)/256, 256>>>(tpw + (size_t)l*DQ*DQ, wp + W_TPW + (size_t)l*DQ*DQ, DQ, DQ); }
            { int n4 = 3*DQ*DQ/4;
              cvtw_k<<<(n4+255)/256, 256>>>(aqw + (size_t)l*3*DQ*DQ, wp + W_AQW + (size_t)l*3*DQ*DQ, 3*DQ, DQ); }
            { int n4 = DQ*DQ/4;
              cvtw_k<<<(n4+255)/256, 256>>>(apw + (size_t)l*DQ*DQ, wp + W_APW + (size_t)l*DQ*DQ, DQ, DQ); }
            { int n4 = HIDQ*DQ/4;
              cvtw_k<<<(n4+255)/256, 256>>>(f1w + (size_t)l*HIDQ*DQ, wp + W_F1W + (size_t)l*HIDQ*DQ, HIDQ, DQ); }
            { int n4 = DQ*HIDQ/4;
              cvtw_k<<<(n4+255)/256, 256>>>(f2w + (size_t)l*DQ*HIDQ, wp + W_F2W + (size_t)l*DQ*HIDQ, DQ, HIDQ); }
        }
    }

    // ---- patch embedding ----
    im2col_k<<<(6272 * 768 + 255) / 256, 256>>>(x, hH, hL);
    gemm(hH, hL, wp + W_PATCH, nullptr, nullptr, qkv, nullptr, nullptr,
         6272, TQPAD, 768, 768, 0);
    assemble_k<<<(TQ * DQ + 255) / 256, 256>>>(qkv, patch_b, cls_tok, pos, temp, xt);

    for (int l = 0; l < LQ; l++) {
        // ---- time attention ----
        ln_k<<<TQ, 256>>>(xt, n3s + (size_t)l * DQ, n3b + (size_t)l * DQ, aH, aL);
        gemm(aH, aL, wp + W_TQW + (size_t)l * 3 * DQ * DQ, tqb + (size_t)l * 3 * DQ,
             nullptr, qkv, nullptr, nullptr, TQ, TQPAD, 3 * DQ, DQ, 0);
        time_cls_k<<<1176 + 48, 256, CLS_WS_BYTES>>>(qkv, aH, aL);
        gemm(aH, aL, wp + W_TPW + (size_t)l * DQ * DQ, tpb + (size_t)l * DQ,
             xt, res, nullptr, nullptr, TQ, TQPAD, DQ, DQ, 1);      // time_res
        // ---- space attention ----
        ln_k<<<TQ, 256>>>(res, n1s + (size_t)l * DQ, n1b + (size_t)l * DQ, aH, aL);
        gemm(aH, aL, wp + W_AQW + (size_t)l * 3 * DQ * DQ, aqb + (size_t)l * 3 * DQ,
             nullptr, qkv, nullptr, nullptr, TQ, TQPAD, 3 * DQ, DQ, 0);
        space_cls_k<<<384 + 48, 256, SPACE_SMEM>>>(qkv, aH, aL);
        gemm(aH, aL, wp + W_APW + (size_t)l * DQ * DQ, apb + (size_t)l * DQ,
             xt, res, nullptr, nullptr, TQ, TQPAD, DQ, DQ, 1);      // space_res
        // ---- MLP ----
        ln_k<<<TQ, 256>>>(res, n2s + (size_t)l * DQ, n2b + (size_t)l * DQ, aH, aL);
        gemm(aH, aL, wp + W_F1W + (size_t)l * HIDQ * DQ, f1b + (size_t)l * HIDQ,
             nullptr, nullptr, hH, hL, TQ, TQPAD, HIDQ, DQ, 2);     // gelu -> tiled split
        gemm(hH, hL, wp + W_F2W + (size_t)l * DQ * HIDQ, f2b + (size_t)l * DQ,
             res, xt, nullptr, nullptr, TQ, TQPAD, DQ, HIDQ, 1);    // xt = res + mlp
    }

    final_ln_k<<<BQ, 256>>>(xt, nfs, nfb, out);
}

// round 12
// speedup vs baseline: 1.0839x; 1.0839x over previous
#include <cuda_runtime.h>
#include <cuda_fp16.h>
#include <stdint.h>
#include <math.h>

// ---------------- problem constants ----------------
#define BQ 4
#define DQ 768
#define SQ 1569                  // 1 + 8*196
#define TQ (BQ*SQ)               // 6276 tokens
#define TQPAD 6400               // padded rows for tiled A operands
#define HIDQ 3072
#define LQ 12
#define EPSQ 1e-6f
#define SCALEQ 0.125f            // 64^-0.5

// weight pool offsets (halfs) -- tiled layouts, same element counts
#define W_PATCH 0
#define W_TQW   (W_PATCH + 768*768)
#define W_TPW   (W_TQW + (size_t)LQ*3*DQ*DQ)
#define W_AQW   (W_TPW + (size_t)LQ*DQ*DQ)
#define W_APW   (W_AQW + (size_t)LQ*3*DQ*DQ)
#define W_F1W   (W_APW + (size_t)LQ*DQ*DQ)
#define W_F2W   (W_F1W + (size_t)LQ*HIDQ*DQ)
#define W_TOTAL (W_F2W + (size_t)LQ*DQ*HIDQ)

// ---------------- scratch (static device globals) ----------------
__device__ float g_xt [(size_t)TQ*DQ];
__device__ float g_qkv[(size_t)TQ*3*DQ];
__device__ float g_res[(size_t)TQ*DQ];
__device__ __half g_aH[(size_t)TQPAD*DQ],  g_aL[(size_t)TQPAD*DQ];    // zero-padded rows
__device__ __half g_hH[(size_t)TQPAD*HIDQ], g_hL[(size_t)TQPAD*HIDQ];
__device__ __half g_w [W_TOTAL];

// ---------------- tiled + swizzled index ----------------
// layout: [k>>6][row (rows total)][64], within-row 16B chunk c stored at c ^ (row&7)
__device__ __forceinline__ size_t tIdx(size_t rows, int m, int k) {
    return ((size_t)(k >> 6) * rows + m) * 64
         + ((((k >> 3) & 7) ^ (m & 7)) << 3) + (k & 7);
}

// ---------------- helpers ----------------
__device__ __forceinline__ uint32_t smem_u32(const void* p) {
    uint32_t a;
    asm("{ .reg .u64 t; cvta.to.shared.u64 t, %1; cvt.u32.u64 %0, t; }" : "=r"(a) : "l"(p));
    return a;
}

#define MBAR_INIT(addr, cnt) \
    asm volatile("mbarrier.init.shared.b64 [%0], %1;" :: "r"(addr), "r"((uint32_t)(cnt)) : "memory")
#define MBAR_EXPECT(addr, bytes) \
    asm volatile("mbarrier.arrive.expect_tx.shared.b64 _, [%0], %1;" :: "r"(addr), "r"((uint32_t)(bytes)) : "memory")
#define FENCE_ASYNC() asm volatile("fence.proxy.async.shared::cta;" ::: "memory")

__device__ __forceinline__ void mbar_wait(uint32_t mbar, uint32_t parity) {
    asm volatile(
        "{\n\t.reg .pred P;\n\t"
        "W_%=:\n\t"
        "mbarrier.try_wait.parity.acquire.cta.shared::cta.b64 P, [%0], %1, 0x989680;\n\t"
        "@P bra.uni D_%=;\n\t"
        "bra.uni W_%=;\n\t"
        "D_%=:\n\t}"
        :: "r"(mbar), "r"(parity) : "memory");
}

__device__ __forceinline__ void bulkcp(uint32_t dst, const void* src, uint32_t bytes, uint32_t mbar) {
    asm volatile("cp.async.bulk.shared::cluster.global.mbarrier::complete_tx::bytes "
                 "[%0], [%1], %2, [%3];"
                 :: "r"(dst), "l"(src), "r"(bytes), "r"(mbar) : "memory");
}

#define LDSMX4(r, addr) \
    asm volatile("ldmatrix.sync.aligned.m8n8.x4.shared.b16 {%0,%1,%2,%3}, [%4];" \
                 : "=r"((r)[0]), "=r"((r)[1]), "=r"((r)[2]), "=r"((r)[3]) : "r"(addr))

__device__ __forceinline__ void mma16816(float* c,
        uint32_t a0, uint32_t a1, uint32_t a2, uint32_t a3,
        uint32_t b0, uint32_t b1) {
    asm volatile(
        "mma.sync.aligned.m16n8k16.row.col.f32.f16.f16.f32 "
        "{%0,%1,%2,%3}, {%4,%5,%6,%7}, {%8,%9}, {%0,%1,%2,%3};\n"
        : "+f"(c[0]), "+f"(c[1]), "+f"(c[2]), "+f"(c[3])
        : "r"(a0), "r"(a1), "r"(a2), "r"(a3), "r"(b0), "r"(b1));
}

__device__ __forceinline__ void wsplit(__half* hi, __half* lo, size_t i, float v) {
    __half h = __float2half_rn(v);
    hi[i] = h;
    lo[i] = __float2half_rn(v - __half2float(h));
}

__device__ __forceinline__ float block_red(float v, int isMax) {
    __shared__ float red[8];
    int lane = threadIdx.x & 31, w = threadIdx.x >> 5;
    #pragma unroll
    for (int o = 16; o; o >>= 1) {
        float t = __shfl_xor_sync(0xffffffffu, v, o);
        v = isMax ? fmaxf(v, t) : (v + t);
    }
    __syncthreads();
    if (lane == 0) red[w] = v;
    __syncthreads();
    float t = red[0];
    #pragma unroll
    for (int i = 1; i < 8; i++) t = isMax ? fmaxf(t, red[i]) : (t + red[i]);
    return t;
}

// ---------------- batched weight convert fp32 -> tiled/swizzled fp16 ----------------
// all layers of one weight type in one launch
__global__ void cvtw_k(const float* __restrict__ w, __half* __restrict__ o,
                       int N, int K, int layers) {
    int perL4 = N * (K >> 2);
    int idx = blockIdx.x * 256 + threadIdx.x;
    if (idx >= layers * perL4) return;
    int l = idx / perL4, rem = idx - l * perL4;
    int K4 = K >> 2;
    int n = rem / K4, kq = rem - n * K4;
    int k = kq * 4;
    float4 v = ((const float4*)w)[idx];
    __half2 a = __floats2half2_rn(v.x, v.y);
    __half2 b = __floats2half2_rn(v.z, v.w);
    uint2 r;
    r.x = *(uint32_t*)&a; r.y = *(uint32_t*)&b;
    *(uint2*)&o[(size_t)l * N * K + tIdx(N, n, k)] = r;
}

// ---------------- im2col -> tiled split fp16 ----------------
__global__ void im2col_k(const float* __restrict__ x,
                         __half* __restrict__ oH, __half* __restrict__ oL) {
    int idx = blockIdx.x * 256 + threadIdx.x;
    if (idx >= 6272 * 768) return;
    int r = idx / 768, c = idx % 768;
    int bf = r / 196, p = r % 196;
    int ph = p / 14, pw = p % 14;
    int ch = c >> 8, rem = c & 255;
    int i = rem >> 4, j = rem & 15;
    size_t off = (((size_t)bf * 3 + ch) * 224 + ph * 16 + i) * 224 + pw * 16 + j;
    wsplit(oH, oL, tIdx(TQPAD, r, c), x[off]);
}

// ---------------- assemble tokens (fp32 xt) ----------------
__global__ void assemble_k(const float* __restrict__ pe,
                           const float* __restrict__ patch_b,
                           const float* __restrict__ cls_tok,
                           const float* __restrict__ pos,
                           const float* __restrict__ temp,
                           float* __restrict__ xt) {
    int idx = blockIdx.x * 256 + threadIdx.x;
    if (idx >= TQ * DQ) return;
    int t = idx / DQ, dd = idx % DQ;
    int b = t / SQ, s = t % SQ;
    float v;
    if (s == 0) {
        v = cls_tok[dd] + pos[dd];
    } else {
        int sp = s - 1, fr = sp / 196, p = sp % 196;
        v = pe[((size_t)(b * 8 + fr) * 196 + p) * 768 + dd] + patch_b[dd]
            + pos[(size_t)(1 + p) * 768 + dd] + temp[(size_t)fr * 768 + dd];
    }
    xt[idx] = v;
}

// ---------------- layernorm -> tiled split fp16 ----------------
__global__ void ln_k(const float* __restrict__ x, const float* __restrict__ sc,
                     const float* __restrict__ bi,
                     __half* __restrict__ oH, __half* __restrict__ oL) {
    int row = blockIdx.x, tid = threadIdx.x;
    const float* xr = x + (size_t)row * DQ;
    float r0 = xr[tid], r1 = xr[tid + 256], r2 = xr[tid + 512];
    float mean = block_red(r0 + r1 + r2, 0) * (1.f / 768.f);
    float d0 = r0 - mean, d1 = r1 - mean, d2 = r2 - mean;
    float var = block_red(d0 * d0 + d1 * d1 + d2 * d2, 0) * (1.f / 768.f);
    float inv = rsqrtf(var + EPSQ);
    wsplit(oH, oL, tIdx(TQPAD, row, tid),       d0 * inv * sc[tid]       + bi[tid]);
    wsplit(oH, oL, tIdx(TQPAD, row, tid + 256), d1 * inv * sc[tid + 256] + bi[tid + 256]);
    wsplit(oH, oL, tIdx(TQPAD, row, tid + 512), d2 * inv * sc[tid + 512] + bi[tid + 512]);
}

__global__ void final_ln_k(const float* __restrict__ xt, const float* __restrict__ sc,
                           const float* __restrict__ bi, float* __restrict__ out) {
    int b = blockIdx.x, tid = threadIdx.x;
    const float* xr = xt + (size_t)(b * SQ) * DQ;
    float r0 = xr[tid], r1 = xr[tid + 256], r2 = xr[tid + 512];
    float mean = block_red(r0 + r1 + r2, 0) * (1.f / 768.f);
    float d0 = r0 - mean, d1 = r1 - mean, d2 = r2 - mean;
    float var = block_red(d0 * d0 + d1 * d1 + d2 * d2, 0) * (1.f / 768.f);
    float inv = rsqrtf(var + EPSQ);
    float* yr = out + (size_t)b * DQ;
    yr[tid]       = d0 * inv * sc[tid]       + bi[tid];
    yr[tid + 256] = d1 * inv * sc[tid + 256] + bi[tid + 256];
    yr[tid + 512] = d2 * inv * sc[tid + 512] + bi[tid + 512];
}

// ============== HMMA GEMM v9: 128x128 tile, bulk fills, 2-stage, 2 CTAs/SM ==============
// C[M,N] = A[M,K] @ W[N,K]^T; A fp16 hi/lo (2-term), W fp16, fp32 acc.
// 256 thr, 8 warps (2x4), warp tile 64x32, tiled+swizzled gmem operands.
#define ARR_A 16384                  // 128 rows x 128B
#define ARR_B 16384                  // 128 rows x 128B
#define STGB  (2*ARR_A + ARR_B)      // 49152
#define NSTG  2
#define GT_SMEM (NSTG*STGB)          // 98304 -> 2 CTAs/SM

template<int ACT, int OS, int RS>
__global__ void __launch_bounds__(256, 2) gemm_k(
    const __half* __restrict__ aH, const __half* __restrict__ aL,
    const __half* __restrict__ wH,
    const float* __restrict__ bias, const float* __restrict__ res,
    float* __restrict__ outF,
    __half* __restrict__ oH, __half* __restrict__ oL,
    int M, int Mpad, int N, int K) {
    extern __shared__ char smem[];
    __shared__ __align__(8) uint64_t mbar_store[NSTG];
    uint32_t sb = smem_u32(smem);
    uint32_t mb = smem_u32(mbar_store);
    int tid = threadIdx.x;
    int lane = tid & 31, w = tid >> 5;
    int warpM = w >> 2, warpN = w & 3;       // 2 x 4 warps, warp tile 64x32
    int g = lane >> 2, q = lane & 3;
    int bm = blockIdx.y * 128, bn = blockIdx.x * 128;
    const int nkt = K >> 6;

    if (tid == 0) {
        #pragma unroll
        for (int s = 0; s < NSTG; s++) MBAR_INIT(mb + s * 8, 1);
        FENCE_ASYNC();
    }
    __syncthreads();

    auto fill = [&](int j) {
        int fb = j & 1;
        uint32_t st = sb + fb * STGB;
        uint32_t m = mb + fb * 8;
        MBAR_EXPECT(m, STGB);
        bulkcp(st,             aH + ((size_t)j * Mpad + bm) * 64, ARR_A, m);
        bulkcp(st + ARR_A,     aL + ((size_t)j * Mpad + bm) * 64, ARR_A, m);
        bulkcp(st + 2 * ARR_A, wH + ((size_t)j * N + bn) * 64,    ARR_B, m);
    };

    if (tid == 0) fill(0);

    float acc[4][4][4];
    #pragma unroll
    for (int i = 0; i < 4; i++)
        #pragma unroll
        for (int j = 0; j < 4; j++)
            #pragma unroll
            for (int c = 0; c < 4; c++) acc[i][j][c] = 0.f;

    // swizzled chunk byte offsets per kk (lane-dependent, loop-invariant)
    int lane7 = lane & 7, hi = lane >> 4;
    uint32_t cb[4];
    #pragma unroll
    for (int kk = 0; kk < 4; kk++) cb[kk] = (uint32_t)(((kk * 2 + hi) ^ lane7) << 4);
    uint32_t arow_off = (uint32_t)(warpM * 64 + (lane & 15)) * 128;
    uint32_t brow_off = (uint32_t)(warpN * 32 + (lane & 15)) * 128 + 2 * ARR_A;

    for (int kt = 0; kt < nkt; kt++) {
        int buf = kt & 1;
        mbar_wait(mb + buf * 8, (uint32_t)((kt >> 1) & 1));
        __syncthreads();                      // all warps done with buf^1 (iter kt-1)
        if (tid == 0 && kt + 1 < nkt) fill(kt + 1);

        uint32_t st = sb + buf * STGB;
        #pragma unroll
        for (int kk = 0; kk < 4; kk++) {
            uint32_t ah[4][4], al[4][4];
            #pragma unroll
            for (int i = 0; i < 4; i++) {
                uint32_t addr = st + arow_off + i * 2048 + cb[kk];
                LDSMX4(ah[i], addr);
                LDSMX4(al[i], addr + ARR_A);
            }
            #pragma unroll
            for (int jj = 0; jj < 2; jj++) {
                uint32_t bh[4];
                LDSMX4(bh, st + brow_off + jj * 2048 + cb[kk]);
                #pragma unroll
                for (int sel = 0; sel < 2; sel++) {
                    int j = jj * 2 + sel;
                    uint32_t b0 = bh[sel], b1 = bh[sel + 2];
                    #pragma unroll
                    for (int i = 0; i < 4; i++) {
                        mma16816(acc[i][j], ah[i][0], ah[i][1], ah[i][2], ah[i][3], b0, b1);
                        mma16816(acc[i][j], al[i][0], al[i][1], al[i][2], al[i][3], b0, b1);
                    }
                }
            }
        }
    }

    // epilogue: m = bm + warpM*64 + i*16 + g (+8), n = bn + warpN*32 + j*8 + q*2
    #pragma unroll
    for (int i = 0; i < 4; i++) {
        int m0 = bm + warpM * 64 + i * 16 + g;
        #pragma unroll
        for (int j = 0; j < 4; j++) {
            int n0 = bn + warpN * 32 + j * 8 + q * 2;
            float bx = bias ? bias[n0] : 0.f;
            float by = bias ? bias[n0 + 1] : 0.f;
            #pragma unroll
            for (int half = 0; half < 2; half++) {
                int m = m0 + half * 8;
                if (m >= M) continue;
                float v0 = acc[i][j][half * 2 + 0] + bx;
                float v1 = acc[i][j][half * 2 + 1] + by;
                if (RS) {
                    const float* rp = res + (size_t)m * N + n0;
                    v0 += rp[0]; v1 += rp[1];
                }
                if (ACT) {
                    v0 = 0.5f * v0 * (1.f + erff(v0 * 0.70710678118654752f));
                    v1 = 0.5f * v1 * (1.f + erff(v1 * 0.70710678118654752f));
                }
                if (OS) {
                    size_t o = tIdx(TQPAD, m, n0);
                    wsplit(oH, oL, o,     v0);
                    wsplit(oH, oL, o + 1, v1);
                } else {
                    *(float2*)(outF + (size_t)m * N + n0) = make_float2(v0, v1);
                }
            }
        }
    }
}

// ---------------- cls-row attention device fn ----------------
__device__ void cls_attn_dev(const float* __restrict__ qkv,
                             __half* __restrict__ oH, __half* __restrict__ oL,
                             int bh, float* ws) {
    float* sc = ws;
    float* qv = ws + 1600;
    float* op = ws + 1664;
    int b = bh / 12, h = bh % 12;
    int tid = threadIdx.x;
    size_t base = (size_t)(b * SQ) * 2304 + (size_t)h * 64;
    if (tid < 64) qv[tid] = qkv[base + tid] * SCALEQ;
    __syncthreads();
    float lmax = -1e30f;
    for (int s = tid; s < SQ; s += 256) {
        const float* kp = qkv + (size_t)(b * SQ + s) * 2304 + 768 + h * 64;
        float d = 0.f;
        #pragma unroll
        for (int i = 0; i < 64; i++) d += qv[i] * kp[i];
        sc[s] = d; lmax = fmaxf(lmax, d);
    }
    float mx = block_red(lmax, 1);
    float lsum = 0.f;
    for (int s = tid; s < SQ; s += 256) {
        float e = expf(sc[s] - mx);
        sc[s] = e; lsum += e;
    }
    float den = block_red(lsum, 0);
    __syncthreads();
    int part = tid >> 6, d = tid & 63;
    float acc = 0.f;
    for (int s = part; s < SQ; s += 4)
        acc += sc[s] * qkv[(size_t)(b * SQ + s) * 2304 + 1536 + h * 64 + d];
    op[tid] = acc;
    __syncthreads();
    if (tid < 64) {
        float t = op[tid] + op[tid + 64] + op[tid + 128] + op[tid + 192];
        wsplit(oH, oL, tIdx(TQPAD, b * SQ, h * 64 + tid), t / den);
    }
}

// ---------------- fused time + cls attention ----------------
#define CLS_WS_BYTES (1920*4)
__global__ void time_cls_k(const float* __restrict__ qkv,
                           __half* __restrict__ oH, __half* __restrict__ oL) {
    extern __shared__ float ws[];
    if (blockIdx.x >= 1176) {
        cls_attn_dev(qkv, oH, oL, blockIdx.x - 1176, ws);
        return;
    }
    int g = blockIdx.x * 8 + (threadIdx.x >> 5);
    int lane = threadIdx.x & 31;
    int bh = g / 196, pos = g % 196;
    int b = bh / 12, h = bh % 12;
    float K0[9], K1[9], V0[9], V1[9];
    #pragma unroll
    for (int kk = 0; kk < 9; kk++) {
        int s = kk ? (1 + (kk - 1) * 196 + pos) : 0;
        size_t o = (size_t)(b * SQ + s) * 2304 + h * 64;
        K0[kk] = qkv[o + 768 + lane];  K1[kk] = qkv[o + 768 + lane + 32];
        V0[kk] = qkv[o + 1536 + lane]; V1[kk] = qkv[o + 1536 + lane + 32];
    }
    for (int fq = 0; fq < 8; fq++) {
        int sq = 1 + fq * 196 + pos;
        size_t oq = (size_t)(b * SQ + sq) * 2304 + h * 64;
        float q0 = qkv[oq + lane] * SCALEQ, q1 = qkv[oq + lane + 32] * SCALEQ;
        float sc[9];
        #pragma unroll
        for (int kk = 0; kk < 9; kk++) {
            float p = q0 * K0[kk] + q1 * K1[kk];
            #pragma unroll
            for (int o = 16; o; o >>= 1) p += __shfl_xor_sync(0xffffffffu, p, o);
            sc[kk] = p;
        }
        float mx = sc[0];
        #pragma unroll
        for (int kk = 1; kk < 9; kk++) mx = fmaxf(mx, sc[kk]);
        float den = 0.f;
        #pragma unroll
        for (int kk = 0; kk < 9; kk++) { sc[kk] = expf(sc[kk] - mx); den += sc[kk]; }
        float inv = 1.f / den;
        float a0 = 0.f, a1 = 0.f;
        #pragma unroll
        for (int kk = 0; kk < 9; kk++) { a0 += sc[kk] * V0[kk]; a1 += sc[kk] * V1[kk]; }
        int m = b * SQ + sq;
        wsplit(oH, oL, tIdx(TQPAD, m, h * 64 + lane),      a0 * inv);
        wsplit(oH, oL, tIdx(TQPAD, m, h * 64 + lane + 32), a1 * inv);
    }
}

// ---------------- fused space + cls attention ----------------
#define SPACE_SMEM ((197*65*2 + 8*197 + 8*64) * 4)
__global__ void space_cls_k(const float* __restrict__ qkv,
                            __half* __restrict__ oH, __half* __restrict__ oL) {
    extern __shared__ float sm[];
    if (blockIdx.x >= 384) {
        cls_attn_dev(qkv, oH, oL, blockIdx.x - 384, sm);
        return;
    }
    float* Ks = sm;
    float* Vs = Ks + 197 * 65;
    float* pb = Vs + 197 * 65;
    float* qb = pb + 8 * 197;
    int blk = blockIdx.x;
    int fr = blk % 8, h = (blk / 8) % 12, b = blk / 96;
    int tid = threadIdx.x, lane = tid & 31, w = tid >> 5;
    for (int idx = tid; idx < 197 * 64; idx += 256) {
        int kk = idx >> 6, d = idx & 63;
        int s = kk ? (1 + fr * 196 + kk - 1) : 0;
        size_t o = (size_t)(b * SQ + s) * 2304 + h * 64;
        Ks[kk * 65 + d] = qkv[o + 768 + d];
        Vs[kk * 65 + d] = qkv[o + 1536 + d];
    }
    __syncthreads();
    for (int qi = w; qi < 196; qi += 8) {
        int sq = 1 + fr * 196 + qi;
        size_t oq = (size_t)(b * SQ + sq) * 2304 + h * 64;
        qb[w * 64 + lane]      = qkv[oq + lane] * SCALEQ;
        qb[w * 64 + lane + 32] = qkv[oq + lane + 32] * SCALEQ;
        __syncwarp();
        float ls[7];
        float lmax = -1e30f;
        int cnt = 0;
        for (int kk = lane; kk < 197; kk += 32) {
            float s = 0.f;
            #pragma unroll
            for (int d = 0; d < 64; d++) s += qb[w * 64 + d] * Ks[kk * 65 + d];
            ls[cnt++] = s; lmax = fmaxf(lmax, s);
        }
        #pragma unroll
        for (int o = 16; o; o >>= 1) lmax = fmaxf(lmax, __shfl_xor_sync(0xffffffffu, lmax, o));
        float lsum = 0.f; cnt = 0;
        for (int kk = lane; kk < 197; kk += 32) {
            float e = expf(ls[cnt++] - lmax);
            pb[w * 197 + kk] = e; lsum += e;
        }
        #pragma unroll
        for (int o = 16; o; o >>= 1) lsum += __shfl_xor_sync(0xffffffffu, lsum, o);
        float inv = 1.f / lsum;
        __syncwarp();
        float a0 = 0.f, a1 = 0.f;
        for (int kk = 0; kk < 197; kk++) {
            float p = pb[w * 197 + kk];
            a0 += p * Vs[kk * 65 + lane];
            a1 += p * Vs[kk * 65 + lane + 32];
        }
        int m = b * SQ + sq;
        wsplit(oH, oL, tIdx(TQPAD, m, h * 64 + lane),      a0 * inv);
        wsplit(oH, oL, tIdx(TQPAD, m, h * 64 + lane + 32), a1 * inv);
        __syncwarp();
    }
}

// ================== host orchestration ==================
// mode: 0 fp32 out, 1 fp32 out + residual, 2 gelu + tiled split-fp16 out
static void gemm(const __half* aH, const __half* aL, const __half* wHp,
                 const float* bias, const float* res,
                 float* outF, __half* oH, __half* oL,
                 int M, int Mpad, int N, int K, int mode) {
    dim3 g(N / 128, (M + 127) / 128);
    if (mode == 0)
        gemm_k<0,0,0><<<g, 256, GT_SMEM>>>(aH, aL, wHp, bias, res, outF, oH, oL, M, Mpad, N, K);
    else if (mode == 1)
        gemm_k<0,0,1><<<g, 256, GT_SMEM>>>(aH, aL, wHp, bias, res, outF, oH, oL, M, Mpad, N, K);
    else
        gemm_k<1,1,0><<<g, 256, GT_SMEM>>>(aH, aL, wHp, bias, res, outF, oH, oL, M, Mpad, N, K);
}

extern "C" void kernel_launch(void* const* d_in, const int* in_sizes, int n_in,
                              void* d_out, int out_size) {
    const float* x       = (const float*)d_in[0];
    const float* patch_w = (const float*)d_in[1];
    const float* patch_b = (const float*)d_in[2];
    const float* cls_tok = (const float*)d_in[3];
    const float* pos     = (const float*)d_in[4];
    const float* temp    = (const float*)d_in[5];
    const float* n1s = (const float*)d_in[6],  *n1b = (const float*)d_in[7];
    const float* n2s = (const float*)d_in[8],  *n2b = (const float*)d_in[9];
    const float* n3s = (const float*)d_in[10], *n3b = (const float*)d_in[11];
    const float* aqw = (const float*)d_in[12], *aqb = (const float*)d_in[13];
    const float* apw = (const float*)d_in[14], *apb = (const float*)d_in[15];
    const float* tqw = (const float*)d_in[16], *tqb = (const float*)d_in[17];
    const float* tpw = (const float*)d_in[18], *tpb = (const float*)d_in[19];
    const float* f1w = (const float*)d_in[20], *f1b = (const float*)d_in[21];
    const float* f2w = (const float*)d_in[22], *f2b = (const float*)d_in[23];
    const float* nfs = (const float*)d_in[24], *nfb = (const float*)d_in[25];
    float* out = (float*)d_out;

    float *xt, *qkv, *res;
    __half *aH, *aL, *hH, *hL, *wp;
    cudaGetSymbolAddress((void**)&xt,  g_xt);
    cudaGetSymbolAddress((void**)&qkv, g_qkv);
    cudaGetSymbolAddress((void**)&res, g_res);
    cudaGetSymbolAddress((void**)&aH,  g_aH);
    cudaGetSymbolAddress((void**)&aL,  g_aL);
    cudaGetSymbolAddress((void**)&hH,  g_hH);
    cudaGetSymbolAddress((void**)&hL,  g_hL);
    cudaGetSymbolAddress((void**)&wp,  g_w);

    cudaFuncSetAttribute(space_cls_k, cudaFuncAttributeMaxDynamicSharedMemorySize, SPACE_SMEM);
    cudaFuncSetAttribute(gemm_k<0,0,0>, cudaFuncAttributeMaxDynamicSharedMemorySize, GT_SMEM);
    cudaFuncSetAttribute(gemm_k<0,0,1>, cudaFuncAttributeMaxDynamicSharedMemorySize, GT_SMEM);
    cudaFuncSetAttribute(gemm_k<1,1,0>, cudaFuncAttributeMaxDynamicSharedMemorySize, GT_SMEM);

    // ---- one-shot weight conversion (fp32 -> tiled/swizzled fp16 pool), batched ----
    {
        auto launch = [&](const float* src, __half* dst, int N, int K, int layers) {
            int tot = layers * N * (K >> 2);
            cvtw_k<<<(tot + 255) / 256, 256>>>(src, dst, N, K, layers);
        };
        launch(patch_w, wp + W_PATCH, 768, 768, 1);
        launch(tqw, wp + W_TQW, 3 * DQ, DQ, LQ);
        launch(tpw, wp + W_TPW, DQ, DQ, LQ);
        launch(aqw, wp + W_AQW, 3 * DQ, DQ, LQ);
        launch(apw, wp + W_APW, DQ, DQ, LQ);
        launch(f1w, wp + W_F1W, HIDQ, DQ, LQ);
        launch(f2w, wp + W_F2W, DQ, HIDQ, LQ);
    }

    // ---- patch embedding ----
    im2col_k<<<(6272 * 768 + 255) / 256, 256>>>(x, hH, hL);
    gemm(hH, hL, wp + W_PATCH, nullptr, nullptr, qkv, nullptr, nullptr,
         6272, TQPAD, 768, 768, 0);
    assemble_k<<<(TQ * DQ + 255) / 256, 256>>>(qkv, patch_b, cls_tok, pos, temp, xt);

    for (int l = 0; l < LQ; l++) {
        // ---- time attention ----
        ln_k<<<TQ, 256>>>(xt, n3s + (size_t)l * DQ, n3b + (size_t)l * DQ, aH, aL);
        gemm(aH, aL, wp + W_TQW + (size_t)l * 3 * DQ * DQ, tqb + (size_t)l * 3 * DQ,
             nullptr, qkv, nullptr, nullptr, TQ, TQPAD, 3 * DQ, DQ, 0);
        time_cls_k<<<1176 + 48, 256, CLS_WS_BYTES>>>(qkv, aH, aL);
        gemm(aH, aL, wp + W_TPW + (size_t)l * DQ * DQ, tpb + (size_t)l * DQ,
             xt, res, nullptr, nullptr, TQ, TQPAD, DQ, DQ, 1);      // time_res
        // ---- space attention ----
        ln_k<<<TQ, 256>>>(res, n1s + (size_t)l * DQ, n1b + (size_t)l * DQ, aH, aL);
        gemm(aH, aL, wp + W_AQW + (size_t)l * 3 * DQ * DQ, aqb + (size_t)l * 3 * DQ,
             nullptr, qkv, nullptr, nullptr, TQ, TQPAD, 3 * DQ, DQ, 0);
        space_cls_k<<<384 + 48, 256, SPACE_SMEM>>>(qkv, aH, aL);
        gemm(aH, aL, wp + W_APW + (size_t)l * DQ * DQ, apb + (size_t)l * DQ,
             xt, res, nullptr, nullptr, TQ, TQPAD, DQ, DQ, 1);      // space_res
        // ---- MLP ----
        ln_k<<<TQ, 256>>>(res, n2s + (size_t)l * DQ, n2b + (size_t)l * DQ, aH, aL);
        gemm(aH, aL, wp + W_F1W + (size_t)l * HIDQ * DQ, f1b + (size_t)l * HIDQ,
             nullptr, nullptr, hH, hL, TQ, TQPAD, HIDQ, DQ, 2);     // gelu -> tiled split
        gemm(hH, hL, wp + W_F2W + (size_t)l * DQ * HIDQ, f2b + (size_t)l * DQ,
             res, xt, nullptr, nullptr, TQ, TQPAD, DQ, HIDQ, 1);    // xt = res + mlp
    }

    final_ln_k<<<BQ, 256>>>(xt, nfs, nfb, out);
}

// round 13
// speedup vs baseline: 1.0949x; 1.0102x over previous
#include <cuda_runtime.h>
#include <cuda_fp16.h>
#include <stdint.h>
#include <math.h>

// ---------------- problem constants ----------------
#define BQ 4
#define DQ 768
#define SQ 1569                  // 1 + 8*196
#define TQ (BQ*SQ)               // 6276 tokens
#define TQPAD 6400               // padded rows for tiled A operands
#define HIDQ 3072
#define LQ 12
#define EPSQ 1e-6f
#define SCALEQ 0.125f            // 64^-0.5

// weight pool offsets (halfs) -- tiled layouts
#define W_PATCH 0
#define W_TQW   (W_PATCH + 768*768)
#define W_TPW   (W_TQW + (size_t)LQ*3*DQ*DQ)
#define W_AQW   (W_TPW + (size_t)LQ*DQ*DQ)
#define W_APW   (W_AQW + (size_t)LQ*3*DQ*DQ)
#define W_F1W   (W_APW + (size_t)LQ*DQ*DQ)
#define W_F2W   (W_F1W + (size_t)LQ*HIDQ*DQ)
#define W_TOTAL (W_F2W + (size_t)LQ*DQ*HIDQ)

// ---------------- scratch (static device globals) ----------------
__device__ float g_xt [(size_t)TQ*DQ];
__device__ float g_qkv[(size_t)TQ*3*DQ];
__device__ float g_res[(size_t)TQ*DQ];
__device__ __half g_aH[(size_t)TQPAD*DQ],  g_aL[(size_t)TQPAD*DQ];
__device__ __half g_hH[(size_t)TQPAD*HIDQ], g_hL[(size_t)TQPAD*HIDQ];
__device__ __half g_w [W_TOTAL];

// ---------------- tiled + swizzled index ----------------
__device__ __forceinline__ size_t tIdx(size_t rows, int m, int k) {
    return ((size_t)(k >> 6) * rows + m) * 64
         + ((((k >> 3) & 7) ^ (m & 7)) << 3) + (k & 7);
}

// ---------------- helpers ----------------
__device__ __forceinline__ uint32_t smem_u32(const void* p) {
    uint32_t a;
    asm("{ .reg .u64 t; cvta.to.shared.u64 t, %1; cvt.u32.u64 %0, t; }" : "=r"(a) : "l"(p));
    return a;
}

#define MBAR_INIT(addr, cnt) \
    asm volatile("mbarrier.init.shared.b64 [%0], %1;" :: "r"(addr), "r"((uint32_t)(cnt)) : "memory")
#define MBAR_EXPECT(addr, bytes) \
    asm volatile("mbarrier.arrive.expect_tx.shared.b64 _, [%0], %1;" :: "r"(addr), "r"((uint32_t)(bytes)) : "memory")
#define FENCE_ASYNC() asm volatile("fence.proxy.async.shared::cta;" ::: "memory")

__device__ __forceinline__ void mbar_wait(uint32_t mbar, uint32_t parity) {
    asm volatile(
        "{\n\t.reg .pred P;\n\t"
        "W_%=:\n\t"
        "mbarrier.try_wait.parity.acquire.cta.shared::cta.b64 P, [%0], %1, 0x989680;\n\t"
        "@P bra.uni D_%=;\n\t"
        "bra.uni W_%=;\n\t"
        "D_%=:\n\t}"
        :: "r"(mbar), "r"(parity) : "memory");
}

__device__ __forceinline__ void bulkcp(uint32_t dst, const void* src, uint32_t bytes, uint32_t mbar) {
    asm volatile("cp.async.bulk.shared::cluster.global.mbarrier::complete_tx::bytes "
                 "[%0], [%1], %2, [%3];"
                 :: "r"(dst), "l"(src), "r"(bytes), "r"(mbar) : "memory");
}

#define LDSMX4(r, addr) \
    asm volatile("ldmatrix.sync.aligned.m8n8.x4.shared.b16 {%0,%1,%2,%3}, [%4];" \
                 : "=r"((r)[0]), "=r"((r)[1]), "=r"((r)[2]), "=r"((r)[3]) : "r"(addr))

__device__ __forceinline__ void mma16816(float* c,
        uint32_t a0, uint32_t a1, uint32_t a2, uint32_t a3,
        uint32_t b0, uint32_t b1) {
    asm volatile(
        "mma.sync.aligned.m16n8k16.row.col.f32.f16.f16.f32 "
        "{%0,%1,%2,%3}, {%4,%5,%6,%7}, {%8,%9}, {%0,%1,%2,%3};\n"
        : "+f"(c[0]), "+f"(c[1]), "+f"(c[2]), "+f"(c[3])
        : "r"(a0), "r"(a1), "r"(a2), "r"(a3), "r"(b0), "r"(b1));
}

__device__ __forceinline__ void wsplit(__half* hi, __half* lo, size_t i, float v) {
    __half h = __float2half_rn(v);
    hi[i] = h;
    lo[i] = __float2half_rn(v - __half2float(h));
}

// branch-free GELU: erf via Abramowitz-Stegun 7.1.26 (abs err < 1.5e-7)
__device__ __forceinline__ float gelu_f(float v) {
    float z = fabsf(v) * 0.70710678118654752f;
    float t = __frcp_rn(1.f + 0.3275911f * z);
    float p = t * (0.254829592f + t * (-0.284496736f + t * (1.421413741f
            + t * (-1.453152027f + t * 1.061405429f))));
    float erfz = 1.f - p * __expf(-z * z);
    erfz = copysignf(erfz, v);
    return 0.5f * v * (1.f + erfz);
}

__device__ __forceinline__ float block_red(float v, int isMax) {
    __shared__ float red[8];
    int lane = threadIdx.x & 31, w = threadIdx.x >> 5;
    #pragma unroll
    for (int o = 16; o; o >>= 1) {
        float t = __shfl_xor_sync(0xffffffffu, v, o);
        v = isMax ? fmaxf(v, t) : (v + t);
    }
    __syncthreads();
    if (lane == 0) red[w] = v;
    __syncthreads();
    float t = red[0];
    #pragma unroll
    for (int i = 1; i < 8; i++) t = isMax ? fmaxf(t, red[i]) : (t + red[i]);
    return t;
}

// ---------------- batched weight convert fp32 -> tiled/swizzled fp16 ----------------
__global__ void cvtw_k(const float* __restrict__ w, __half* __restrict__ o,
                       int N, int K, int layers) {
    int perL4 = N * (K >> 2);
    int idx = blockIdx.x * 256 + threadIdx.x;
    if (idx >= layers * perL4) return;
    int l = idx / perL4, rem = idx - l * perL4;
    int K4 = K >> 2;
    int n = rem / K4, kq = rem - n * K4;
    int k = kq * 4;
    float4 v = ((const float4*)w)[idx];
    __half2 a = __floats2half2_rn(v.x, v.y);
    __half2 b = __floats2half2_rn(v.z, v.w);
    uint2 r;
    r.x = *(uint32_t*)&a; r.y = *(uint32_t*)&b;
    *(uint2*)&o[(size_t)l * N * K + tIdx(N, n, k)] = r;
}

// ---------------- im2col -> tiled split fp16 ----------------
__global__ void im2col_k(const float* __restrict__ x,
                         __half* __restrict__ oH, __half* __restrict__ oL) {
    int idx = blockIdx.x * 256 + threadIdx.x;
    if (idx >= 6272 * 768) return;
    int r = idx / 768, c = idx % 768;
    int bf = r / 196, p = r % 196;
    int ph = p / 14, pw = p % 14;
    int ch = c >> 8, rem = c & 255;
    int i = rem >> 4, j = rem & 15;
    size_t off = (((size_t)bf * 3 + ch) * 224 + ph * 16 + i) * 224 + pw * 16 + j;
    wsplit(oH, oL, tIdx(TQPAD, r, c), x[off]);
}

// ---------------- assemble tokens (fp32 xt) ----------------
__global__ void assemble_k(const float* __restrict__ pe,
                           const float* __restrict__ patch_b,
                           const float* __restrict__ cls_tok,
                           const float* __restrict__ pos,
                           const float* __restrict__ temp,
                           float* __restrict__ xt) {
    int idx = blockIdx.x * 256 + threadIdx.x;
    if (idx >= TQ * DQ) return;
    int t = idx / DQ, dd = idx % DQ;
    int b = t / SQ, s = t % SQ;
    float v;
    if (s == 0) {
        v = cls_tok[dd] + pos[dd];
    } else {
        int sp = s - 1, fr = sp / 196, p = sp % 196;
        v = pe[((size_t)(b * 8 + fr) * 196 + p) * 768 + dd] + patch_b[dd]
            + pos[(size_t)(1 + p) * 768 + dd] + temp[(size_t)fr * 768 + dd];
    }
    xt[idx] = v;
}

// ---------------- layernorm -> tiled split fp16 ----------------
__global__ void ln_k(const float* __restrict__ x, const float* __restrict__ sc,
                     const float* __restrict__ bi,
                     __half* __restrict__ oH, __half* __restrict__ oL) {
    int row = blockIdx.x, tid = threadIdx.x;
    const float* xr = x + (size_t)row * DQ;
    float r0 = xr[tid], r1 = xr[tid + 256], r2 = xr[tid + 512];
    float mean = block_red(r0 + r1 + r2, 0) * (1.f / 768.f);
    float d0 = r0 - mean, d1 = r1 - mean, d2 = r2 - mean;
    float var = block_red(d0 * d0 + d1 * d1 + d2 * d2, 0) * (1.f / 768.f);
    float inv = rsqrtf(var + EPSQ);
    wsplit(oH, oL, tIdx(TQPAD, row, tid),       d0 * inv * sc[tid]       + bi[tid]);
    wsplit(oH, oL, tIdx(TQPAD, row, tid + 256), d1 * inv * sc[tid + 256] + bi[tid + 256]);
    wsplit(oH, oL, tIdx(TQPAD, row, tid + 512), d2 * inv * sc[tid + 512] + bi[tid + 512]);
}

__global__ void final_ln_k(const float* __restrict__ xt, const float* __restrict__ sc,
                           const float* __restrict__ bi, float* __restrict__ out) {
    int b = blockIdx.x, tid = threadIdx.x;
    const float* xr = xt + (size_t)(b * SQ) * DQ;
    float r0 = xr[tid], r1 = xr[tid + 256], r2 = xr[tid + 512];
    float mean = block_red(r0 + r1 + r2, 0) * (1.f / 768.f);
    float d0 = r0 - mean, d1 = r1 - mean, d2 = r2 - mean;
    float var = block_red(d0 * d0 + d1 * d1 + d2 * d2, 0) * (1.f / 768.f);
    float inv = rsqrtf(var + EPSQ);
    float* yr = out + (size_t)b * DQ;
    yr[tid]       = d0 * inv * sc[tid]       + bi[tid];
    yr[tid + 256] = d1 * inv * sc[tid + 256] + bi[tid + 256];
    yr[tid + 512] = d2 * inv * sc[tid + 512] + bi[tid + 512];
}

// ============== HMMA GEMM v9: 128x128 tile, bulk fills, 2-stage, 2 CTAs/SM ==============
#define ARR_A 16384
#define ARR_B 16384
#define STGB  (2*ARR_A + ARR_B)      // 49152
#define NSTG  2
#define GT_SMEM (NSTG*STGB)          // 98304 -> 2 CTAs/SM

template<int ACT, int OS, int RS>
__global__ void __launch_bounds__(256, 2) gemm_k(
    const __half* __restrict__ aH, const __half* __restrict__ aL,
    const __half* __restrict__ wH,
    const float* __restrict__ bias, const float* __restrict__ res,
    float* __restrict__ outF,
    __half* __restrict__ oH, __half* __restrict__ oL,
    int M, int Mpad, int N, int K) {
    extern __shared__ char smem[];
    __shared__ __align__(8) uint64_t mbar_store[NSTG];
    uint32_t sb = smem_u32(smem);
    uint32_t mb = smem_u32(mbar_store);
    int tid = threadIdx.x;
    int lane = tid & 31, w = tid >> 5;
    int warpM = w >> 2, warpN = w & 3;
    int g = lane >> 2, q = lane & 3;
    int bm = blockIdx.y * 128, bn = blockIdx.x * 128;
    const int nkt = K >> 6;

    if (tid == 0) {
        #pragma unroll
        for (int s = 0; s < NSTG; s++) MBAR_INIT(mb + s * 8, 1);
        FENCE_ASYNC();
    }
    __syncthreads();

    auto fill = [&](int j) {
        int fb = j & 1;
        uint32_t st = sb + fb * STGB;
        uint32_t m = mb + fb * 8;
        MBAR_EXPECT(m, STGB);
        bulkcp(st,             aH + ((size_t)j * Mpad + bm) * 64, ARR_A, m);
        bulkcp(st + ARR_A,     aL + ((size_t)j * Mpad + bm) * 64, ARR_A, m);
        bulkcp(st + 2 * ARR_A, wH + ((size_t)j * N + bn) * 64,    ARR_B, m);
    };

    if (tid == 0) fill(0);

    float acc[4][4][4];
    #pragma unroll
    for (int i = 0; i < 4; i++)
        #pragma unroll
        for (int j = 0; j < 4; j++)
            #pragma unroll
            for (int c = 0; c < 4; c++) acc[i][j][c] = 0.f;

    int lane7 = lane & 7, hi = lane >> 4;
    uint32_t cb[4];
    #pragma unroll
    for (int kk = 0; kk < 4; kk++) cb[kk] = (uint32_t)(((kk * 2 + hi) ^ lane7) << 4);
    uint32_t arow_off = (uint32_t)(warpM * 64 + (lane & 15)) * 128;
    uint32_t brow_off = (uint32_t)(warpN * 32 + (lane & 15)) * 128 + 2 * ARR_A;

    for (int kt = 0; kt < nkt; kt++) {
        int buf = kt & 1;
        mbar_wait(mb + buf * 8, (uint32_t)((kt >> 1) & 1));
        __syncthreads();
        if (tid == 0 && kt + 1 < nkt) fill(kt + 1);

        uint32_t st = sb + buf * STGB;
        #pragma unroll
        for (int kk = 0; kk < 4; kk++) {
            uint32_t ah[4][4], al[4][4];
            #pragma unroll
            for (int i = 0; i < 4; i++) {
                uint32_t addr = st + arow_off + i * 2048 + cb[kk];
                LDSMX4(ah[i], addr);
                LDSMX4(al[i], addr + ARR_A);
            }
            #pragma unroll
            for (int jj = 0; jj < 2; jj++) {
                uint32_t bh[4];
                LDSMX4(bh, st + brow_off + jj * 2048 + cb[kk]);
                #pragma unroll
                for (int sel = 0; sel < 2; sel++) {
                    int j = jj * 2 + sel;
                    uint32_t b0 = bh[sel], b1 = bh[sel + 2];
                    #pragma unroll
                    for (int i = 0; i < 4; i++) {
                        mma16816(acc[i][j], ah[i][0], ah[i][1], ah[i][2], ah[i][3], b0, b1);
                        mma16816(acc[i][j], al[i][0], al[i][1], al[i][2], al[i][3], b0, b1);
                    }
                }
            }
        }
    }

    #pragma unroll
    for (int i = 0; i < 4; i++) {
        int m0 = bm + warpM * 64 + i * 16 + g;
        #pragma unroll
        for (int j = 0; j < 4; j++) {
            int n0 = bn + warpN * 32 + j * 8 + q * 2;
            float bx = bias ? bias[n0] : 0.f;
            float by = bias ? bias[n0 + 1] : 0.f;
            #pragma unroll
            for (int half = 0; half < 2; half++) {
                int m = m0 + half * 8;
                if (m >= M) continue;
                float v0 = acc[i][j][half * 2 + 0] + bx;
                float v1 = acc[i][j][half * 2 + 1] + by;
                if (RS) {
                    const float* rp = res + (size_t)m * N + n0;
                    v0 += rp[0]; v1 += rp[1];
                }
                if (ACT) {
                    v0 = gelu_f(v0);
                    v1 = gelu_f(v1);
                }
                if (OS) {
                    size_t o = tIdx(TQPAD, m, n0);
                    wsplit(oH, oL, o,     v0);
                    wsplit(oH, oL, o + 1, v1);
                } else {
                    *(float2*)(outF + (size_t)m * N + n0) = make_float2(v0, v1);
                }
            }
        }
    }
}

// ---------------- cls-row attention device fn ----------------
__device__ void cls_attn_dev(const float* __restrict__ qkv,
                             __half* __restrict__ oH, __half* __restrict__ oL,
                             int bh, float* ws) {
    float* sc = ws;
    float* qv = ws + 1600;
    float* op = ws + 1664;
    int b = bh / 12, h = bh % 12;
    int tid = threadIdx.x;
    size_t base = (size_t)(b * SQ) * 2304 + (size_t)h * 64;
    if (tid < 64) qv[tid] = qkv[base + tid] * SCALEQ;
    __syncthreads();
    float lmax = -1e30f;
    for (int s = tid; s < SQ; s += 256) {
        const float* kp = qkv + (size_t)(b * SQ + s) * 2304 + 768 + h * 64;
        float d = 0.f;
        #pragma unroll
        for (int i = 0; i < 64; i++) d += qv[i] * kp[i];
        sc[s] = d; lmax = fmaxf(lmax, d);
    }
    float mx = block_red(lmax, 1);
    float lsum = 0.f;
    for (int s = tid; s < SQ; s += 256) {
        float e = __expf(sc[s] - mx);
        sc[s] = e; lsum += e;
    }
    float den = block_red(lsum, 0);
    __syncthreads();
    int part = tid >> 6, d = tid & 63;
    float acc = 0.f;
    for (int s = part; s < SQ; s += 4)
        acc += sc[s] * qkv[(size_t)(b * SQ + s) * 2304 + 1536 + h * 64 + d];
    op[tid] = acc;
    __syncthreads();
    if (tid < 64) {
        float t = op[tid] + op[tid + 64] + op[tid + 128] + op[tid + 192];
        wsplit(oH, oL, tIdx(TQPAD, b * SQ, h * 64 + tid), t / den);
    }
}

// ---------------- fused time + cls attention ----------------
#define CLS_WS_BYTES (1920*4)
__global__ void time_cls_k(const float* __restrict__ qkv,
                           __half* __restrict__ oH, __half* __restrict__ oL) {
    extern __shared__ float ws[];
    if (blockIdx.x >= 1176) {
        cls_attn_dev(qkv, oH, oL, blockIdx.x - 1176, ws);
        return;
    }
    int g = blockIdx.x * 8 + (threadIdx.x >> 5);
    int lane = threadIdx.x & 31;
    int bh = g / 196, pos = g % 196;
    int b = bh / 12, h = bh % 12;
    float K0[9], K1[9], V0[9], V1[9];
    #pragma unroll
    for (int kk = 0; kk < 9; kk++) {
        int s = kk ? (1 + (kk - 1) * 196 + pos) : 0;
        size_t o = (size_t)(b * SQ + s) * 2304 + h * 64;
        K0[kk] = qkv[o + 768 + lane];  K1[kk] = qkv[o + 768 + lane + 32];
        V0[kk] = qkv[o + 1536 + lane]; V1[kk] = qkv[o + 1536 + lane + 32];
    }
    for (int fq = 0; fq < 8; fq++) {
        int sq = 1 + fq * 196 + pos;
        size_t oq = (size_t)(b * SQ + sq) * 2304 + h * 64;
        float q0 = qkv[oq + lane] * SCALEQ, q1 = qkv[oq + lane + 32] * SCALEQ;
        float sc[9];
        #pragma unroll
        for (int kk = 0; kk < 9; kk++) {
            float p = q0 * K0[kk] + q1 * K1[kk];
            #pragma unroll
            for (int o = 16; o; o >>= 1) p += __shfl_xor_sync(0xffffffffu, p, o);
            sc[kk] = p;
        }
        float mx = sc[0];
        #pragma unroll
        for (int kk = 1; kk < 9; kk++) mx = fmaxf(mx, sc[kk]);
        float den = 0.f;
        #pragma unroll
        for (int kk = 0; kk < 9; kk++) { sc[kk] = __expf(sc[kk] - mx); den += sc[kk]; }
        float inv = 1.f / den;
        float a0 = 0.f, a1 = 0.f;
        #pragma unroll
        for (int kk = 0; kk < 9; kk++) { a0 += sc[kk] * V0[kk]; a1 += sc[kk] * V1[kk]; }
        int m = b * SQ + sq;
        wsplit(oH, oL, tIdx(TQPAD, m, h * 64 + lane),      a0 * inv);
        wsplit(oH, oL, tIdx(TQPAD, m, h * 64 + lane + 32), a1 * inv);
    }
}

// ---------------- fused space + cls attention ----------------
#define SPACE_SMEM ((197*65*2 + 8*197 + 8*64) * 4)
__global__ void space_cls_k(const float* __restrict__ qkv,
                            __half* __restrict__ oH, __half* __restrict__ oL) {
    extern __shared__ float sm[];
    if (blockIdx.x >= 384) {
        cls_attn_dev(qkv, oH, oL, blockIdx.x - 384, sm);
        return;
    }
    float* Ks = sm;
    float* Vs = Ks + 197 * 65;
    float* pb = Vs + 197 * 65;
    float* qb = pb + 8 * 197;
    int blk = blockIdx.x;
    int fr = blk % 8, h = (blk / 8) % 12, b = blk / 96;
    int tid = threadIdx.x, lane = tid & 31, w = tid >> 5;
    for (int idx = tid; idx < 197 * 64; idx += 256) {
        int kk = idx >> 6, d = idx & 63;
        int s = kk ? (1 + fr * 196 + kk - 1) : 0;
        size_t o = (size_t)(b * SQ + s) * 2304 + h * 64;
        Ks[kk * 65 + d] = qkv[o + 768 + d];
        Vs[kk * 65 + d] = qkv[o + 1536 + d];
    }
    __syncthreads();
    for (int qi = w; qi < 196; qi += 8) {
        int sq = 1 + fr * 196 + qi;
        size_t oq = (size_t)(b * SQ + sq) * 2304 + h * 64;
        qb[w * 64 + lane]      = qkv[oq + lane] * SCALEQ;
        qb[w * 64 + lane + 32] = qkv[oq + lane + 32] * SCALEQ;
        __syncwarp();
        float ls[7];
        float lmax = -1e30f;
        int cnt = 0;
        for (int kk = lane; kk < 197; kk += 32) {
            float s = 0.f;
            #pragma unroll
            for (int d = 0; d < 64; d++) s += qb[w * 64 + d] * Ks[kk * 65 + d];
            ls[cnt++] = s; lmax = fmaxf(lmax, s);
        }
        #pragma unroll
        for (int o = 16; o; o >>= 1) lmax = fmaxf(lmax, __shfl_xor_sync(0xffffffffu, lmax, o));
        float lsum = 0.f; cnt = 0;
        for (int kk = lane; kk < 197; kk += 32) {
            float e = __expf(ls[cnt++] - lmax);
            pb[w * 197 + kk] = e; lsum += e;
        }
        #pragma unroll
        for (int o = 16; o; o >>= 1) lsum += __shfl_xor_sync(0xffffffffu, lsum, o);
        float inv = 1.f / lsum;
        __syncwarp();
        float a0 = 0.f, a1 = 0.f;
        for (int kk = 0; kk < 197; kk++) {
            float p = pb[w * 197 + kk];
            a0 += p * Vs[kk * 65 + lane];
            a1 += p * Vs[kk * 65 + lane + 32];
        }
        int m = b * SQ + sq;
        wsplit(oH, oL, tIdx(TQPAD, m, h * 64 + lane),      a0 * inv);
        wsplit(oH, oL, tIdx(TQPAD, m, h * 64 + lane + 32), a1 * inv);
        __syncwarp();
    }
}

// ================== host orchestration ==================
static void gemm(const __half* aH, const __half* aL, const __half* wHp,
                 const float* bias, const float* res,
                 float* outF, __half* oH, __half* oL,
                 int M, int Mpad, int N, int K, int mode) {
    dim3 g(N / 128, (M + 127) / 128);
    if (mode == 0)
        gemm_k<0,0,0><<<g, 256, GT_SMEM>>>(aH, aL, wHp, bias, res, outF, oH, oL, M, Mpad, N, K);
    else if (mode == 1)
        gemm_k<0,0,1><<<g, 256, GT_SMEM>>>(aH, aL, wHp, bias, res, outF, oH, oL, M, Mpad, N, K);
    else
        gemm_k<1,1,0><<<g, 256, GT_SMEM>>>(aH, aL, wHp, bias, res, outF, oH, oL, M, Mpad, N, K);
}

extern "C" void kernel_launch(void* const* d_in, const int* in_sizes, int n_in,
                              void* d_out, int out_size) {
    const float* x       = (const float*)d_in[0];
    const float* patch_w = (const float*)d_in[1];
    const float* patch_b = (const float*)d_in[2];
    const float* cls_tok = (const float*)d_in[3];
    const float* pos     = (const float*)d_in[4];
    const float* temp    = (const float*)d_in[5];
    const float* n1s = (const float*)d_in[6],  *n1b = (const float*)d_in[7];
    const float* n2s = (const float*)d_in[8],  *n2b = (const float*)d_in[9];
    const float* n3s = (const float*)d_in[10], *n3b = (const float*)d_in[11];
    const float* aqw = (const float*)d_in[12], *aqb = (const float*)d_in[13];
    const float* apw = (const float*)d_in[14], *apb = (const float*)d_in[15];
    const float* tqw = (const float*)d_in[16], *tqb = (const float*)d_in[17];
    const float* tpw = (const float*)d_in[18], *tpb = (const float*)d_in[19];
    const float* f1w = (const float*)d_in[20], *f1b = (const float*)d_in[21];
    const float* f2w = (const float*)d_in[22], *f2b = (const float*)d_in[23];
    const float* nfs = (const float*)d_in[24], *nfb = (const float*)d_in[25];
    float* out = (float*)d_out;

    float *xt, *qkv, *res;
    __half *aH, *aL, *hH, *hL, *wp;
    cudaGetSymbolAddress((void**)&xt,  g_xt);
    cudaGetSymbolAddress((void**)&qkv, g_qkv);
    cudaGetSymbolAddress((void**)&res, g_res);
    cudaGetSymbolAddress((void**)&aH,  g_aH);
    cudaGetSymbolAddress((void**)&aL,  g_aL);
    cudaGetSymbolAddress((void**)&hH,  g_hH);
    cudaGetSymbolAddress((void**)&hL,  g_hL);
    cudaGetSymbolAddress((void**)&wp,  g_w);

    cudaFuncSetAttribute(space_cls_k, cudaFuncAttributeMaxDynamicSharedMemorySize, SPACE_SMEM);
    cudaFuncSetAttribute(gemm_k<0,0,0>, cudaFuncAttributeMaxDynamicSharedMemorySize, GT_SMEM);
    cudaFuncSetAttribute(gemm_k<0,0,1>, cudaFuncAttributeMaxDynamicSharedMemorySize, GT_SMEM);
    cudaFuncSetAttribute(gemm_k<1,1,0>, cudaFuncAttributeMaxDynamicSharedMemorySize, GT_SMEM);

    // ---- one-shot weight conversion, batched per weight type ----
    {
        auto launch = [&](const float* src, __half* dst, int N, int K, int layers) {
            int tot = layers * N * (K >> 2);
            cvtw_k<<<(tot + 255) / 256, 256>>>(src, dst, N, K, layers);
        };
        launch(patch_w, wp + W_PATCH, 768, 768, 1);
        launch(tqw, wp + W_TQW, 3 * DQ, DQ, LQ);
        launch(tpw, wp + W_TPW, DQ, DQ, LQ);
        launch(aqw, wp + W_AQW, 3 * DQ, DQ, LQ);
        launch(apw, wp + W_APW, DQ, DQ, LQ);
        launch(f1w, wp + W_F1W, HIDQ, DQ, LQ);
        launch(f2w, wp + W_F2W, DQ, HIDQ, LQ);
    }

    // ---- patch embedding ----
    im2col_k<<<(6272 * 768 + 255) / 256, 256>>>(x, hH, hL);
    gemm(hH, hL, wp + W_PATCH, nullptr, nullptr, qkv, nullptr, nullptr,
         6272, TQPAD, 768, 768, 0);
    assemble_k<<<(TQ * DQ + 255) / 256, 256>>>(qkv, patch_b, cls_tok, pos, temp, xt);

    for (int l = 0; l < LQ; l++) {
        // ---- time attention ----
        ln_k<<<TQ, 256>>>(xt, n3s + (size_t)l * DQ, n3b + (size_t)l * DQ, aH, aL);
        gemm(aH, aL, wp + W_TQW + (size_t)l * 3 * DQ * DQ, tqb + (size_t)l * 3 * DQ,
             nullptr, qkv, nullptr, nullptr, TQ, TQPAD, 3 * DQ, DQ, 0);
        time_cls_k<<<1176 + 48, 256, CLS_WS_BYTES>>>(qkv, aH, aL);
        gemm(aH, aL, wp + W_TPW + (size_t)l * DQ * DQ, tpb + (size_t)l * DQ,
             xt, res, nullptr, nullptr, TQ, TQPAD, DQ, DQ, 1);      // time_res
        // ---- space attention ----
        ln_k<<<TQ, 256>>>(res, n1s + (size_t)l * DQ, n1b + (size_t)l * DQ, aH, aL);
        gemm(aH, aL, wp + W_AQW + (size_t)l * 3 * DQ * DQ, aqb + (size_t)l * 3 * DQ,
             nullptr, qkv, nullptr, nullptr, TQ, TQPAD, 3 * DQ, DQ, 0);
        space_cls_k<<<384 + 48, 256, SPACE_SMEM>>>(qkv, aH, aL);
        gemm(aH, aL, wp + W_APW + (size_t)l * DQ * DQ, apb + (size_t)l * DQ,
             xt, res, nullptr, nullptr, TQ, TQPAD, DQ, DQ, 1);      // space_res
        // ---- MLP ----
        ln_k<<<TQ, 256>>>(res, n2s + (size_t)l * DQ, n2b + (size_t)l * DQ, aH, aL);
        gemm(aH, aL, wp + W_F1W + (size_t)l * HIDQ * DQ, f1b + (size_t)l * HIDQ,
             nullptr, nullptr, hH, hL, TQ, TQPAD, HIDQ, DQ, 2);     // gelu -> tiled split
        gemm(hH, hL, wp + W_F2W + (size_t)l * DQ * HIDQ, f2b + (size_t)l * DQ,
             res, xt, nullptr, nullptr, TQ, TQPAD, DQ, HIDQ, 1);    // xt = res + mlp
    }

    final_ln_k<<<BQ, 256>>>(xt, nfs, nfb, out);
}

// round 14
// speedup vs baseline: 1.2709x; 1.1608x over previous
#include <cuda_runtime.h>
#include <cuda_fp16.h>
#include <stdint.h>
#include <math.h>

// ---------------- problem constants ----------------
#define BQ 4
#define DQ 768
#define SQ 1569                  // 1 + 8*196
#define TQ (BQ*SQ)               // 6276 tokens
#define TQPAD 6400               // padded rows for tiled A operands
#define HIDQ 3072
#define LQ 12
#define EPSQ 1e-6f
#define SCALEQ 0.125f            // 64^-0.5

// weight pool offsets (halfs) -- tiled layouts
#define W_PATCH 0
#define W_TQW   (W_PATCH + 768*768)
#define W_TPW   (W_TQW + (size_t)LQ*3*DQ*DQ)
#define W_AQW   (W_TPW + (size_t)LQ*DQ*DQ)
#define W_APW   (W_AQW + (size_t)LQ*3*DQ*DQ)
#define W_F1W   (W_APW + (size_t)LQ*DQ*DQ)
#define W_F2W   (W_F1W + (size_t)LQ*HIDQ*DQ)
#define W_TOTAL (W_F2W + (size_t)LQ*DQ*HIDQ)

// ---------------- scratch (static device globals) ----------------
__device__ float g_xt [(size_t)TQ*DQ];
__device__ float g_qkv[(size_t)TQ*3*DQ];
__device__ float g_res[(size_t)TQ*DQ];
__device__ __half g_aH[(size_t)TQPAD*DQ],  g_aL[(size_t)TQPAD*DQ];
__device__ __half g_hH[(size_t)TQPAD*HIDQ];          // fc2 input, 1-term
__device__ __half g_w [W_TOTAL];

// ---------------- tiled + swizzled index ----------------
__device__ __forceinline__ size_t tIdx(size_t rows, int m, int k) {
    return ((size_t)(k >> 6) * rows + m) * 64
         + ((((k >> 3) & 7) ^ (m & 7)) << 3) + (k & 7);
}

// ---------------- helpers ----------------
__device__ __forceinline__ uint32_t smem_u32(const void* p) {
    uint32_t a;
    asm("{ .reg .u64 t; cvta.to.shared.u64 t, %1; cvt.u32.u64 %0, t; }" : "=r"(a) : "l"(p));
    return a;
}

#define MBAR_INIT(addr, cnt) \
    asm volatile("mbarrier.init.shared.b64 [%0], %1;" :: "r"(addr), "r"((uint32_t)(cnt)) : "memory")
#define MBAR_EXPECT(addr, bytes) \
    asm volatile("mbarrier.arrive.expect_tx.shared.b64 _, [%0], %1;" :: "r"(addr), "r"((uint32_t)(bytes)) : "memory")
#define FENCE_ASYNC() asm volatile("fence.proxy.async.shared::cta;" ::: "memory")

__device__ __forceinline__ void mbar_wait(uint32_t mbar, uint32_t parity) {
    asm volatile(
        "{\n\t.reg .pred P;\n\t"
        "W_%=:\n\t"
        "mbarrier.try_wait.parity.acquire.cta.shared::cta.b64 P, [%0], %1, 0x989680;\n\t"
        "@P bra.uni D_%=;\n\t"
        "bra.uni W_%=;\n\t"
        "D_%=:\n\t}"
        :: "r"(mbar), "r"(parity) : "memory");
}

__device__ __forceinline__ void bulkcp(uint32_t dst, const void* src, uint32_t bytes, uint32_t mbar) {
    asm volatile("cp.async.bulk.shared::cluster.global.mbarrier::complete_tx::bytes "
                 "[%0], [%1], %2, [%3];"
                 :: "r"(dst), "l"(src), "r"(bytes), "r"(mbar) : "memory");
}

#define LDSMX4(r, addr) \
    asm volatile("ldmatrix.sync.aligned.m8n8.x4.shared.b16 {%0,%1,%2,%3}, [%4];" \
                 : "=r"((r)[0]), "=r"((r)[1]), "=r"((r)[2]), "=r"((r)[3]) : "r"(addr))

__device__ __forceinline__ void mma16816(float* c,
        uint32_t a0, uint32_t a1, uint32_t a2, uint32_t a3,
        uint32_t b0, uint32_t b1) {
    asm volatile(
        "mma.sync.aligned.m16n8k16.row.col.f32.f16.f16.f32 "
        "{%0,%1,%2,%3}, {%4,%5,%6,%7}, {%8,%9}, {%0,%1,%2,%3};\n"
        : "+f"(c[0]), "+f"(c[1]), "+f"(c[2]), "+f"(c[3])
        : "r"(a0), "r"(a1), "r"(a2), "r"(a3), "r"(b0), "r"(b1));
}

__device__ __forceinline__ void wsplit(__half* hi, __half* lo, size_t i, float v) {
    __half h = __float2half_rn(v);
    hi[i] = h;
    lo[i] = __float2half_rn(v - __half2float(h));
}

// branch-free GELU: erf via Abramowitz-Stegun 7.1.26 (abs err < 1.5e-7)
__device__ __forceinline__ float gelu_f(float v) {
    float z = fabsf(v) * 0.70710678118654752f;
    float t = __frcp_rn(1.f + 0.3275911f * z);
    float p = t * (0.254829592f + t * (-0.284496736f + t * (1.421413741f
            + t * (-1.453152027f + t * 1.061405429f))));
    float erfz = 1.f - p * __expf(-z * z);
    erfz = copysignf(erfz, v);
    return 0.5f * v * (1.f + erfz);
}

__device__ __forceinline__ float block_red(float v, int isMax) {
    __shared__ float red[8];
    int lane = threadIdx.x & 31, w = threadIdx.x >> 5;
    #pragma unroll
    for (int o = 16; o; o >>= 1) {
        float t = __shfl_xor_sync(0xffffffffu, v, o);
        v = isMax ? fmaxf(v, t) : (v + t);
    }
    __syncthreads();
    if (lane == 0) red[w] = v;
    __syncthreads();
    float t = red[0];
    #pragma unroll
    for (int i = 1; i < 8; i++) t = isMax ? fmaxf(t, red[i]) : (t + red[i]);
    return t;
}

// ---------------- batched weight convert fp32 -> tiled/swizzled fp16 ----------------
__global__ void cvtw_k(const float* __restrict__ w, __half* __restrict__ o,
                       int N, int K, int layers) {
    int perL4 = N * (K >> 2);
    int idx = blockIdx.x * 256 + threadIdx.x;
    if (idx >= layers * perL4) return;
    int l = idx / perL4, rem = idx - l * perL4;
    int K4 = K >> 2;
    int n = rem / K4, kq = rem - n * K4;
    int k = kq * 4;
    float4 v = ((const float4*)w)[idx];
    __half2 a = __floats2half2_rn(v.x, v.y);
    __half2 b = __floats2half2_rn(v.z, v.w);
    uint2 r;
    r.x = *(uint32_t*)&a; r.y = *(uint32_t*)&b;
    *(uint2*)&o[(size_t)l * N * K + tIdx(N, n, k)] = r;
}

// ---------------- im2col -> tiled split fp16 ----------------
__global__ void im2col_k(const float* __restrict__ x,
                         __half* __restrict__ oH, __half* __restrict__ oL) {
    int idx = blockIdx.x * 256 + threadIdx.x;
    if (idx >= 6272 * 768) return;
    int r = idx / 768, c = idx % 768;
    int bf = r / 196, p = r % 196;
    int ph = p / 14, pw = p % 14;
    int ch = c >> 8, rem = c & 255;
    int i = rem >> 4, j = rem & 15;
    size_t off = (((size_t)bf * 3 + ch) * 224 + ph * 16 + i) * 224 + pw * 16 + j;
    wsplit(oH, oL, tIdx(TQPAD, r, c), x[off]);
}

// ---------------- assemble tokens (fp32 xt) ----------------
__global__ void assemble_k(const float* __restrict__ pe,
                           const float* __restrict__ patch_b,
                           const float* __restrict__ cls_tok,
                           const float* __restrict__ pos,
                           const float* __restrict__ temp,
                           float* __restrict__ xt) {
    int idx = blockIdx.x * 256 + threadIdx.x;
    if (idx >= TQ * DQ) return;
    int t = idx / DQ, dd = idx % DQ;
    int b = t / SQ, s = t % SQ;
    float v;
    if (s == 0) {
        v = cls_tok[dd] + pos[dd];
    } else {
        int sp = s - 1, fr = sp / 196, p = sp % 196;
        v = pe[((size_t)(b * 8 + fr) * 196 + p) * 768 + dd] + patch_b[dd]
            + pos[(size_t)(1 + p) * 768 + dd] + temp[(size_t)fr * 768 + dd];
    }
    xt[idx] = v;
}

// ---------------- layernorm -> tiled split fp16 ----------------
__global__ void ln_k(const float* __restrict__ x, const float* __restrict__ sc,
                     const float* __restrict__ bi,
                     __half* __restrict__ oH, __half* __restrict__ oL) {
    int row = blockIdx.x, tid = threadIdx.x;
    const float* xr = x + (size_t)row * DQ;
    float r0 = xr[tid], r1 = xr[tid + 256], r2 = xr[tid + 512];
    float mean = block_red(r0 + r1 + r2, 0) * (1.f / 768.f);
    float d0 = r0 - mean, d1 = r1 - mean, d2 = r2 - mean;
    float var = block_red(d0 * d0 + d1 * d1 + d2 * d2, 0) * (1.f / 768.f);
    float inv = rsqrtf(var + EPSQ);
    wsplit(oH, oL, tIdx(TQPAD, row, tid),       d0 * inv * sc[tid]       + bi[tid]);
    wsplit(oH, oL, tIdx(TQPAD, row, tid + 256), d1 * inv * sc[tid + 256] + bi[tid + 256]);
    wsplit(oH, oL, tIdx(TQPAD, row, tid + 512), d2 * inv * sc[tid + 512] + bi[tid + 512]);
}

__global__ void final_ln_k(const float* __restrict__ xt, const float* __restrict__ sc,
                           const float* __restrict__ bi, float* __restrict__ out) {
    int b = blockIdx.x, tid = threadIdx.x;
    const float* xr = xt + (size_t)(b * SQ) * DQ;
    float r0 = xr[tid], r1 = xr[tid + 256], r2 = xr[tid + 512];
    float mean = block_red(r0 + r1 + r2, 0) * (1.f / 768.f);
    float d0 = r0 - mean, d1 = r1 - mean, d2 = r2 - mean;
    float var = block_red(d0 * d0 + d1 * d1 + d2 * d2, 0) * (1.f / 768.f);
    float inv = rsqrtf(var + EPSQ);
    float* yr = out + (size_t)b * DQ;
    yr[tid]       = d0 * inv * sc[tid]       + bi[tid];
    yr[tid + 256] = d1 * inv * sc[tid + 256] + bi[tid + 256];
    yr[tid + 512] = d2 * inv * sc[tid + 512] + bi[tid + 512];
}

// ============== HMMA GEMM v10: 128x128 tile, bulk fills, 2-stage, 2 CTAs/SM ==============
// T2: 2-term A (hi+lo) vs 1-term A (hi only)
#define ARR_A 16384
#define ARR_B 16384
#define STGB  (2*ARR_A + ARR_B)      // 49152 (slot layout fixed; T2=0 leaves Al slot unused)
#define NSTG  2
#define GT_SMEM (NSTG*STGB)          // 98304 -> 2 CTAs/SM

template<int ACT, int OS, int RS, int T2>
__global__ void __launch_bounds__(256, 2) gemm_k(
    const __half* __restrict__ aH, const __half* __restrict__ aL,
    const __half* __restrict__ wH,
    const float* __restrict__ bias, const float* __restrict__ res,
    float* __restrict__ outF,
    __half* __restrict__ oH,
    int M, int Mpad, int N, int K) {
    extern __shared__ char smem[];
    __shared__ __align__(8) uint64_t mbar_store[NSTG];
    uint32_t sb = smem_u32(smem);
    uint32_t mb = smem_u32(mbar_store);
    int tid = threadIdx.x;
    int lane = tid & 31, w = tid >> 5;
    int warpM = w >> 2, warpN = w & 3;
    int g = lane >> 2, q = lane & 3;
    int bm = blockIdx.y * 128, bn = blockIdx.x * 128;
    const int nkt = K >> 6;

    if (tid == 0) {
        #pragma unroll
        for (int s = 0; s < NSTG; s++) MBAR_INIT(mb + s * 8, 1);
        FENCE_ASYNC();
    }
    __syncthreads();

    auto fill = [&](int j) {
        int fb = j & 1;
        uint32_t st = sb + fb * STGB;
        uint32_t m = mb + fb * 8;
        MBAR_EXPECT(m, T2 ? STGB : (ARR_A + ARR_B));
        bulkcp(st,             aH + ((size_t)j * Mpad + bm) * 64, ARR_A, m);
        if (T2)
            bulkcp(st + ARR_A, aL + ((size_t)j * Mpad + bm) * 64, ARR_A, m);
        bulkcp(st + 2 * ARR_A, wH + ((size_t)j * N + bn) * 64,    ARR_B, m);
    };

    if (tid == 0) fill(0);

    float acc[4][4][4];
    #pragma unroll
    for (int i = 0; i < 4; i++)
        #pragma unroll
        for (int j = 0; j < 4; j++)
            #pragma unroll
            for (int c = 0; c < 4; c++) acc[i][j][c] = 0.f;

    int lane7 = lane & 7, hi = lane >> 4;
    uint32_t cb[4];
    #pragma unroll
    for (int kk = 0; kk < 4; kk++) cb[kk] = (uint32_t)(((kk * 2 + hi) ^ lane7) << 4);
    uint32_t arow_off = (uint32_t)(warpM * 64 + (lane & 15)) * 128;
    uint32_t brow_off = (uint32_t)(warpN * 32 + (lane & 15)) * 128 + 2 * ARR_A;

    for (int kt = 0; kt < nkt; kt++) {
        int buf = kt & 1;
        mbar_wait(mb + buf * 8, (uint32_t)((kt >> 1) & 1));
        __syncthreads();
        if (tid == 0 && kt + 1 < nkt) fill(kt + 1);

        uint32_t st = sb + buf * STGB;
        #pragma unroll
        for (int kk = 0; kk < 4; kk++) {
            uint32_t ah[4][4], al[4][4];
            #pragma unroll
            for (int i = 0; i < 4; i++) {
                uint32_t addr = st + arow_off + i * 2048 + cb[kk];
                LDSMX4(ah[i], addr);
                if (T2) LDSMX4(al[i], addr + ARR_A);
            }
            #pragma unroll
            for (int jj = 0; jj < 2; jj++) {
                uint32_t bh[4];
                LDSMX4(bh, st + brow_off + jj * 2048 + cb[kk]);
                #pragma unroll
                for (int sel = 0; sel < 2; sel++) {
                    int j = jj * 2 + sel;
                    uint32_t b0 = bh[sel], b1 = bh[sel + 2];
                    #pragma unroll
                    for (int i = 0; i < 4; i++) {
                        mma16816(acc[i][j], ah[i][0], ah[i][1], ah[i][2], ah[i][3], b0, b1);
                        if (T2)
                            mma16816(acc[i][j], al[i][0], al[i][1], al[i][2], al[i][3], b0, b1);
                    }
                }
            }
        }
    }

    #pragma unroll
    for (int i = 0; i < 4; i++) {
        int m0 = bm + warpM * 64 + i * 16 + g;
        #pragma unroll
        for (int j = 0; j < 4; j++) {
            int n0 = bn + warpN * 32 + j * 8 + q * 2;
            float bx = bias ? bias[n0] : 0.f;
            float by = bias ? bias[n0 + 1] : 0.f;
            #pragma unroll
            for (int half = 0; half < 2; half++) {
                int m = m0 + half * 8;
                if (m >= M) continue;
                float v0 = acc[i][j][half * 2 + 0] + bx;
                float v1 = acc[i][j][half * 2 + 1] + by;
                if (RS) {
                    const float* rp = res + (size_t)m * N + n0;
                    v0 += rp[0]; v1 += rp[1];
                }
                if (ACT) {
                    v0 = gelu_f(v0);
                    v1 = gelu_f(v1);
                }
                if (OS) {
                    // 1-term consumer: hi plane only (n0 even, same 16B chunk)
                    __half2 hp = __floats2half2_rn(v0, v1);
                    *(__half2*)&oH[tIdx(TQPAD, m, n0)] = hp;
                } else {
                    *(float2*)(outF + (size_t)m * N + n0) = make_float2(v0, v1);
                }
            }
        }
    }
}

// ---------------- cls-row attention device fn ----------------
__device__ void cls_attn_dev(const float* __restrict__ qkv,
                             __half* __restrict__ oH, __half* __restrict__ oL,
                             int bh, float* ws) {
    float* sc = ws;
    float* qv = ws + 1600;
    float* op = ws + 1664;
    int b = bh / 12, h = bh % 12;
    int tid = threadIdx.x;
    size_t base = (size_t)(b * SQ) * 2304 + (size_t)h * 64;
    if (tid < 64) qv[tid] = qkv[base + tid] * SCALEQ;
    __syncthreads();
    float lmax = -1e30f;
    for (int s = tid; s < SQ; s += 256) {
        const float* kp = qkv + (size_t)(b * SQ + s) * 2304 + 768 + h * 64;
        float d = 0.f;
        #pragma unroll
        for (int i = 0; i < 64; i++) d += qv[i] * kp[i];
        sc[s] = d; lmax = fmaxf(lmax, d);
    }
    float mx = block_red(lmax, 1);
    float lsum = 0.f;
    for (int s = tid; s < SQ; s += 256) {
        float e = __expf(sc[s] - mx);
        sc[s] = e; lsum += e;
    }
    float den = block_red(lsum, 0);
    __syncthreads();
    int part = tid >> 6, d = tid & 63;
    float acc = 0.f;
    for (int s = part; s < SQ; s += 4)
        acc += sc[s] * qkv[(size_t)(b * SQ + s) * 2304 + 1536 + h * 64 + d];
    op[tid] = acc;
    __syncthreads();
    if (tid < 64) {
        float t = op[tid] + op[tid + 64] + op[tid + 128] + op[tid + 192];
        wsplit(oH, oL, tIdx(TQPAD, b * SQ, h * 64 + tid), t / den);
    }
}

// ---------------- fused time + cls attention ----------------
#define CLS_WS_BYTES (1920*4)
__global__ void time_cls_k(const float* __restrict__ qkv,
                           __half* __restrict__ oH, __half* __restrict__ oL) {
    extern __shared__ float ws[];
    if (blockIdx.x >= 1176) {
        cls_attn_dev(qkv, oH, oL, blockIdx.x - 1176, ws);
        return;
    }
    int g = blockIdx.x * 8 + (threadIdx.x >> 5);
    int lane = threadIdx.x & 31;
    int bh = g / 196, pos = g % 196;
    int b = bh / 12, h = bh % 12;
    float K0[9], K1[9], V0[9], V1[9];
    #pragma unroll
    for (int kk = 0; kk < 9; kk++) {
        int s = kk ? (1 + (kk - 1) * 196 + pos) : 0;
        size_t o = (size_t)(b * SQ + s) * 2304 + h * 64;
        K0[kk] = qkv[o + 768 + lane];  K1[kk] = qkv[o + 768 + lane + 32];
        V0[kk] = qkv[o + 1536 + lane]; V1[kk] = qkv[o + 1536 + lane + 32];
    }
    for (int fq = 0; fq < 8; fq++) {
        int sq = 1 + fq * 196 + pos;
        size_t oq = (size_t)(b * SQ + sq) * 2304 + h * 64;
        float q0 = qkv[oq + lane] * SCALEQ, q1 = qkv[oq + lane + 32] * SCALEQ;
        float sc[9];
        #pragma unroll
        for (int kk = 0; kk < 9; kk++) {
            float p = q0 * K0[kk] + q1 * K1[kk];
            #pragma unroll
            for (int o = 16; o; o >>= 1) p += __shfl_xor_sync(0xffffffffu, p, o);
            sc[kk] = p;
        }
        float mx = sc[0];
        #pragma unroll
        for (int kk = 1; kk < 9; kk++) mx = fmaxf(mx, sc[kk]);
        float den = 0.f;
        #pragma unroll
        for (int kk = 0; kk < 9; kk++) { sc[kk] = __expf(sc[kk] - mx); den += sc[kk]; }
        float inv = 1.f / den;
        float a0 = 0.f, a1 = 0.f;
        #pragma unroll
        for (int kk = 0; kk < 9; kk++) { a0 += sc[kk] * V0[kk]; a1 += sc[kk] * V1[kk]; }
        int m = b * SQ + sq;
        wsplit(oH, oL, tIdx(TQPAD, m, h * 64 + lane),      a0 * inv);
        wsplit(oH, oL, tIdx(TQPAD, m, h * 64 + lane + 32), a1 * inv);
    }
}

// ---------------- fused space + cls attention ----------------
#define SPACE_SMEM ((197*65*2 + 8*197 + 8*64) * 4)
__global__ void space_cls_k(const float* __restrict__ qkv,
                            __half* __restrict__ oH, __half* __restrict__ oL) {
    extern __shared__ float sm[];
    if (blockIdx.x >= 384) {
        cls_attn_dev(qkv, oH, oL, blockIdx.x - 384, sm);
        return;
    }
    float* Ks = sm;
    float* Vs = Ks + 197 * 65;
    float* pb = Vs + 197 * 65;
    float* qb = pb + 8 * 197;
    int blk = blockIdx.x;
    int fr = blk % 8, h = (blk / 8) % 12, b = blk / 96;
    int tid = threadIdx.x, lane = tid & 31, w = tid >> 5;
    for (int idx = tid; idx < 197 * 64; idx += 256) {
        int kk = idx >> 6, d = idx & 63;
        int s = kk ? (1 + fr * 196 + kk - 1) : 0;
        size_t o = (size_t)(b * SQ + s) * 2304 + h * 64;
        Ks[kk * 65 + d] = qkv[o + 768 + d];
        Vs[kk * 65 + d] = qkv[o + 1536 + d];
    }
    __syncthreads();
    for (int qi = w; qi < 196; qi += 8) {
        int sq = 1 + fr * 196 + qi;
        size_t oq = (size_t)(b * SQ + sq) * 2304 + h * 64;
        qb[w * 64 + lane]      = qkv[oq + lane] * SCALEQ;
        qb[w * 64 + lane + 32] = qkv[oq + lane + 32] * SCALEQ;
        __syncwarp();
        float ls[7];
        float lmax = -1e30f;
        int cnt = 0;
        for (int kk = lane; kk < 197; kk += 32) {
            float s = 0.f;
            #pragma unroll
            for (int d = 0; d < 64; d++) s += qb[w * 64 + d] * Ks[kk * 65 + d];
            ls[cnt++] = s; lmax = fmaxf(lmax, s);
        }
        #pragma unroll
        for (int o = 16; o; o >>= 1) lmax = fmaxf(lmax, __shfl_xor_sync(0xffffffffu, lmax, o));
        float lsum = 0.f; cnt = 0;
        for (int kk = lane; kk < 197; kk += 32) {
            float e = __expf(ls[cnt++] - lmax);
            pb[w * 197 + kk] = e; lsum += e;
        }
        #pragma unroll
        for (int o = 16; o; o >>= 1) lsum += __shfl_xor_sync(0xffffffffu, lsum, o);
        float inv = 1.f / lsum;
        __syncwarp();
        float a0 = 0.f, a1 = 0.f;
        for (int kk = 0; kk < 197; kk++) {
            float p = pb[w * 197 + kk];
            a0 += p * Vs[kk * 65 + lane];
            a1 += p * Vs[kk * 65 + lane + 32];
        }
        int m = b * SQ + sq;
        wsplit(oH, oL, tIdx(TQPAD, m, h * 64 + lane),      a0 * inv);
        wsplit(oH, oL, tIdx(TQPAD, m, h * 64 + lane + 32), a1 * inv);
        __syncwarp();
    }
}

// ================== host orchestration ==================
// mode: 0 fp32 out (2-term), 1 fp32+res (2-term), 2 gelu->fp16 hi (1-term), 3 fp32+res (1-term)
static void gemm(const __half* aH, const __half* aL, const __half* wHp,
                 const float* bias, const float* res,
                 float* outF, __half* oH,
                 int M, int Mpad, int N, int K, int mode) {
    dim3 g(N / 128, (M + 127) / 128);
    if (mode == 0)
        gemm_k<0,0,0,1><<<g, 256, GT_SMEM>>>(aH, aL, wHp, bias, res, outF, oH, M, Mpad, N, K);
    else if (mode == 1)
        gemm_k<0,0,1,1><<<g, 256, GT_SMEM>>>(aH, aL, wHp, bias, res, outF, oH, M, Mpad, N, K);
    else if (mode == 2)
        gemm_k<1,1,0,0><<<g, 256, GT_SMEM>>>(aH, aL, wHp, bias, res, outF, oH, M, Mpad, N, K);
    else
        gemm_k<0,0,1,0><<<g, 256, GT_SMEM>>>(aH, aL, wHp, bias, res, outF, oH, M, Mpad, N, K);
}

extern "C" void kernel_launch(void* const* d_in, const int* in_sizes, int n_in,
                              void* d_out, int out_size) {
    const float* x       = (const float*)d_in[0];
    const float* patch_w = (const float*)d_in[1];
    const float* patch_b = (const float*)d_in[2];
    const float* cls_tok = (const float*)d_in[3];
    const float* pos     = (const float*)d_in[4];
    const float* temp    = (const float*)d_in[5];
    const float* n1s = (const float*)d_in[6],  *n1b = (const float*)d_in[7];
    const float* n2s = (const float*)d_in[8],  *n2b = (const float*)d_in[9];
    const float* n3s = (const float*)d_in[10], *n3b = (const float*)d_in[11];
    const float* aqw = (const float*)d_in[12], *aqb = (const float*)d_in[13];
    const float* apw = (const float*)d_in[14], *apb = (const float*)d_in[15];
    const float* tqw = (const float*)d_in[16], *tqb = (const float*)d_in[17];
    const float* tpw = (const float*)d_in[18], *tpb = (const float*)d_in[19];
    const float* f1w = (const float*)d_in[20], *f1b = (const float*)d_in[21];
    const float* f2w = (const float*)d_in[22], *f2b = (const float*)d_in[23];
    const float* nfs = (const float*)d_in[24], *nfb = (const float*)d_in[25];
    float* out = (float*)d_out;

    float *xt, *qkv, *res;
    __half *aH, *aL, *hH, *wp;
    cudaGetSymbolAddress((void**)&xt,  g_xt);
    cudaGetSymbolAddress((void**)&qkv, g_qkv);
    cudaGetSymbolAddress((void**)&res, g_res);
    cudaGetSymbolAddress((void**)&aH,  g_aH);
    cudaGetSymbolAddress((void**)&aL,  g_aL);
    cudaGetSymbolAddress((void**)&hH,  g_hH);
    cudaGetSymbolAddress((void**)&wp,  g_w);

    cudaFuncSetAttribute(space_cls_k, cudaFuncAttributeMaxDynamicSharedMemorySize, SPACE_SMEM);
    cudaFuncSetAttribute(gemm_k<0,0,0,1>, cudaFuncAttributeMaxDynamicSharedMemorySize, GT_SMEM);
    cudaFuncSetAttribute(gemm_k<0,0,1,1>, cudaFuncAttributeMaxDynamicSharedMemorySize, GT_SMEM);
    cudaFuncSetAttribute(gemm_k<1,1,0,0>, cudaFuncAttributeMaxDynamicSharedMemorySize, GT_SMEM);
    cudaFuncSetAttribute(gemm_k<0,0,1,0>, cudaFuncAttributeMaxDynamicSharedMemorySize, GT_SMEM);

    // ---- one-shot weight conversion, batched per weight type ----
    {
        auto launch = [&](const float* src, __half* dst, int N, int K, int layers) {
            int tot = layers * N * (K >> 2);
            cvtw_k<<<(tot + 255) / 256, 256>>>(src, dst, N, K, layers);
        };
        launch(patch_w, wp + W_PATCH, 768, 768, 1);
        launch(tqw, wp + W_TQW, 3 * DQ, DQ, LQ);
        launch(tpw, wp + W_TPW, DQ, DQ, LQ);
        launch(aqw, wp + W_AQW, 3 * DQ, DQ, LQ);
        launch(apw, wp + W_APW, DQ, DQ, LQ);
        launch(f1w, wp + W_F1W, HIDQ, DQ, LQ);
        launch(f2w, wp + W_F2W, DQ, HIDQ, LQ);
    }

    // ---- patch embedding (2-term via aH/aL planes of token scratch) ----
    im2col_k<<<(6272 * 768 + 255) / 256, 256>>>(x, aH, aL);
    gemm(aH, aL, wp + W_PATCH, nullptr, nullptr, qkv, nullptr,
         6272, TQPAD, 768, 768, 0);
    assemble_k<<<(TQ * DQ + 255) / 256, 256>>>(qkv, patch_b, cls_tok, pos, temp, xt);

    for (int l = 0; l < LQ; l++) {
        // ---- time attention ----
        ln_k<<<TQ, 256>>>(xt, n3s + (size_t)l * DQ, n3b + (size_t)l * DQ, aH, aL);
        gemm(aH, aL, wp + W_TQW + (size_t)l * 3 * DQ * DQ, tqb + (size_t)l * 3 * DQ,
             nullptr, qkv, nullptr, TQ, TQPAD, 3 * DQ, DQ, 0);
        time_cls_k<<<1176 + 48, 256, CLS_WS_BYTES>>>(qkv, aH, aL);
        gemm(aH, aL, wp + W_TPW + (size_t)l * DQ * DQ, tpb + (size_t)l * DQ,
             xt, res, nullptr, TQ, TQPAD, DQ, DQ, 1);               // time_res
        // ---- space attention ----
        ln_k<<<TQ, 256>>>(res, n1s + (size_t)l * DQ, n1b + (size_t)l * DQ, aH, aL);
        gemm(aH, aL, wp + W_AQW + (size_t)l * 3 * DQ * DQ, aqb + (size_t)l * 3 * DQ,
             nullptr, qkv, nullptr, TQ, TQPAD, 3 * DQ, DQ, 0);
        space_cls_k<<<384 + 48, 256, SPACE_SMEM>>>(qkv, aH, aL);
        gemm(aH, aL, wp + W_APW + (size_t)l * DQ * DQ, apb + (size_t)l * DQ,
             xt, res, nullptr, TQ, TQPAD, DQ, DQ, 1);               // space_res
        // ---- MLP (1-term GEMMs) ----
        ln_k<<<TQ, 256>>>(res, n2s + (size_t)l * DQ, n2b + (size_t)l * DQ, aH, aL);
        gemm(aH, nullptr, wp + W_F1W + (size_t)l * HIDQ * DQ, f1b + (size_t)l * HIDQ,
             nullptr, nullptr, hH, TQ, TQPAD, HIDQ, DQ, 2);         // gelu -> fp16 hi
        gemm(hH, nullptr, wp + W_F2W + (size_t)l * DQ * HIDQ, f2b + (size_t)l * DQ,
             res, xt, nullptr, TQ, TQPAD, DQ, HIDQ, 3);             // xt = res + mlp
    }

    final_ln_k<<<BQ, 256>>>(xt, nfs, nfb, out);
}

// round 15
// speedup vs baseline: 1.4293x; 1.1246x over previous
#include <cuda_runtime.h>
#include <cuda_fp16.h>
#include <stdint.h>
#include <math.h>

// ---------------- problem constants ----------------
#define BQ 4
#define DQ 768
#define SQ 1569                  // 1 + 8*196
#define TQ (BQ*SQ)               // 6276 tokens
#define TQPAD 6400               // padded rows for tiled A operands
#define HIDQ 3072
#define LQ 12
#define EPSQ 1e-6f
#define SCALEQ 0.125f            // 64^-0.5

// weight pool offsets (halfs) -- tiled layouts
#define W_PATCH 0
#define W_TQW   (W_PATCH + 768*768)
#define W_TPW   (W_TQW + (size_t)LQ*3*DQ*DQ)
#define W_AQW   (W_TPW + (size_t)LQ*DQ*DQ)
#define W_APW   (W_AQW + (size_t)LQ*3*DQ*DQ)
#define W_F1W   (W_APW + (size_t)LQ*DQ*DQ)
#define W_F2W   (W_F1W + (size_t)LQ*HIDQ*DQ)
#define W_TOTAL (W_F2W + (size_t)LQ*DQ*HIDQ)

// ---------------- scratch (static device globals) ----------------
__device__ float g_xt [(size_t)TQ*DQ];
__device__ float g_qkv[(size_t)TQ*3*DQ];
__device__ float g_res[(size_t)TQ*DQ];
__device__ __half g_aH[(size_t)TQPAD*DQ],  g_aL[(size_t)TQPAD*DQ];
__device__ __half g_hH[(size_t)TQPAD*HIDQ];          // fc2 input, 1-term
__device__ __half g_w [W_TOTAL];

// ---------------- tiled + swizzled index ----------------
__device__ __forceinline__ size_t tIdx(size_t rows, int m, int k) {
    return ((size_t)(k >> 6) * rows + m) * 64
         + ((((k >> 3) & 7) ^ (m & 7)) << 3) + (k & 7);
}

// ---------------- helpers ----------------
__device__ __forceinline__ uint32_t smem_u32(const void* p) {
    uint32_t a;
    asm("{ .reg .u64 t; cvta.to.shared.u64 t, %1; cvt.u32.u64 %0, t; }" : "=r"(a) : "l"(p));
    return a;
}

#define MBAR_INIT(addr, cnt) \
    asm volatile("mbarrier.init.shared.b64 [%0], %1;" :: "r"(addr), "r"((uint32_t)(cnt)) : "memory")
#define MBAR_EXPECT(addr, bytes) \
    asm volatile("mbarrier.arrive.expect_tx.shared.b64 _, [%0], %1;" :: "r"(addr), "r"((uint32_t)(bytes)) : "memory")
#define FENCE_ASYNC() asm volatile("fence.proxy.async.shared::cta;" ::: "memory")

__device__ __forceinline__ void mbar_wait(uint32_t mbar, uint32_t parity) {
    asm volatile(
        "{\n\t.reg .pred P;\n\t"
        "W_%=:\n\t"
        "mbarrier.try_wait.parity.acquire.cta.shared::cta.b64 P, [%0], %1, 0x989680;\n\t"
        "@P bra.uni D_%=;\n\t"
        "bra.uni W_%=;\n\t"
        "D_%=:\n\t}"
        :: "r"(mbar), "r"(parity) : "memory");
}

__device__ __forceinline__ void bulkcp(uint32_t dst, const void* src, uint32_t bytes, uint32_t mbar) {
    asm volatile("cp.async.bulk.shared::cluster.global.mbarrier::complete_tx::bytes "
                 "[%0], [%1], %2, [%3];"
                 :: "r"(dst), "l"(src), "r"(bytes), "r"(mbar) : "memory");
}

#define LDSMX4(r, addr) \
    asm volatile("ldmatrix.sync.aligned.m8n8.x4.shared.b16 {%0,%1,%2,%3}, [%4];" \
                 : "=r"((r)[0]), "=r"((r)[1]), "=r"((r)[2]), "=r"((r)[3]) : "r"(addr))

__device__ __forceinline__ void mma16816(float* c,
        uint32_t a0, uint32_t a1, uint32_t a2, uint32_t a3,
        uint32_t b0, uint32_t b1) {
    asm volatile(
        "mma.sync.aligned.m16n8k16.row.col.f32.f16.f16.f32 "
        "{%0,%1,%2,%3}, {%4,%5,%6,%7}, {%8,%9}, {%0,%1,%2,%3};\n"
        : "+f"(c[0]), "+f"(c[1]), "+f"(c[2]), "+f"(c[3])
        : "r"(a0), "r"(a1), "r"(a2), "r"(a3), "r"(b0), "r"(b1));
}

__device__ __forceinline__ void wsplit(__half* hi, __half* lo, size_t i, float v) {
    __half h = __float2half_rn(v);
    hi[i] = h;
    lo[i] = __float2half_rn(v - __half2float(h));
}

// branch-free GELU: erf via Abramowitz-Stegun 7.1.26 (abs err < 1.5e-7)
__device__ __forceinline__ float gelu_f(float v) {
    float z = fabsf(v) * 0.70710678118654752f;
    float t = __frcp_rn(1.f + 0.3275911f * z);
    float p = t * (0.254829592f + t * (-0.284496736f + t * (1.421413741f
            + t * (-1.453152027f + t * 1.061405429f))));
    float erfz = 1.f - p * __expf(-z * z);
    erfz = copysignf(erfz, v);
    return 0.5f * v * (1.f + erfz);
}

__device__ __forceinline__ float block_red(float v, int isMax) {
    __shared__ float red[8];
    int lane = threadIdx.x & 31, w = threadIdx.x >> 5;
    #pragma unroll
    for (int o = 16; o; o >>= 1) {
        float t = __shfl_xor_sync(0xffffffffu, v, o);
        v = isMax ? fmaxf(v, t) : (v + t);
    }
    __syncthreads();
    if (lane == 0) red[w] = v;
    __syncthreads();
    float t = red[0];
    #pragma unroll
    for (int i = 1; i < 8; i++) t = isMax ? fmaxf(t, red[i]) : (t + red[i]);
    return t;
}

// ---------------- batched weight convert fp32 -> tiled/swizzled fp16 ----------------
__global__ void cvtw_k(const float* __restrict__ w, __half* __restrict__ o,
                       int N, int K, int layers) {
    int perL4 = N * (K >> 2);
    int idx = blockIdx.x * 256 + threadIdx.x;
    if (idx >= layers * perL4) return;
    int l = idx / perL4, rem = idx - l * perL4;
    int K4 = K >> 2;
    int n = rem / K4, kq = rem - n * K4;
    int k = kq * 4;
    float4 v = ((const float4*)w)[idx];
    __half2 a = __floats2half2_rn(v.x, v.y);
    __half2 b = __floats2half2_rn(v.z, v.w);
    uint2 r;
    r.x = *(uint32_t*)&a; r.y = *(uint32_t*)&b;
    *(uint2*)&o[(size_t)l * N * K + tIdx(N, n, k)] = r;
}

// ---------------- im2col -> tiled split fp16 ----------------
__global__ void im2col_k(const float* __restrict__ x,
                         __half* __restrict__ oH, __half* __restrict__ oL) {
    int idx = blockIdx.x * 256 + threadIdx.x;
    if (idx >= 6272 * 768) return;
    int r = idx / 768, c = idx % 768;
    int bf = r / 196, p = r % 196;
    int ph = p / 14, pw = p % 14;
    int ch = c >> 8, rem = c & 255;
    int i = rem >> 4, j = rem & 15;
    size_t off = (((size_t)bf * 3 + ch) * 224 + ph * 16 + i) * 224 + pw * 16 + j;
    wsplit(oH, oL, tIdx(TQPAD, r, c), x[off]);
}

// ---------------- assemble tokens (fp32 xt) ----------------
__global__ void assemble_k(const float* __restrict__ pe,
                           const float* __restrict__ patch_b,
                           const float* __restrict__ cls_tok,
                           const float* __restrict__ pos,
                           const float* __restrict__ temp,
                           float* __restrict__ xt) {
    int idx = blockIdx.x * 256 + threadIdx.x;
    if (idx >= TQ * DQ) return;
    int t = idx / DQ, dd = idx % DQ;
    int b = t / SQ, s = t % SQ;
    float v;
    if (s == 0) {
        v = cls_tok[dd] + pos[dd];
    } else {
        int sp = s - 1, fr = sp / 196, p = sp % 196;
        v = pe[((size_t)(b * 8 + fr) * 196 + p) * 768 + dd] + patch_b[dd]
            + pos[(size_t)(1 + p) * 768 + dd] + temp[(size_t)fr * 768 + dd];
    }
    xt[idx] = v;
}

// ---------------- layernorm -> tiled fp16 (hi plane only; consumers are 1-term) ----------------
__global__ void ln_k(const float* __restrict__ x, const float* __restrict__ sc,
                     const float* __restrict__ bi,
                     __half* __restrict__ oH) {
    int row = blockIdx.x, tid = threadIdx.x;
    const float* xr = x + (size_t)row * DQ;
    float r0 = xr[tid], r1 = xr[tid + 256], r2 = xr[tid + 512];
    float mean = block_red(r0 + r1 + r2, 0) * (1.f / 768.f);
    float d0 = r0 - mean, d1 = r1 - mean, d2 = r2 - mean;
    float var = block_red(d0 * d0 + d1 * d1 + d2 * d2, 0) * (1.f / 768.f);
    float inv = rsqrtf(var + EPSQ);
    oH[tIdx(TQPAD, row, tid)]       = __float2half_rn(d0 * inv * sc[tid]       + bi[tid]);
    oH[tIdx(TQPAD, row, tid + 256)] = __float2half_rn(d1 * inv * sc[tid + 256] + bi[tid + 256]);
    oH[tIdx(TQPAD, row, tid + 512)] = __float2half_rn(d2 * inv * sc[tid + 512] + bi[tid + 512]);
}

__global__ void final_ln_k(const float* __restrict__ xt, const float* __restrict__ sc,
                           const float* __restrict__ bi, float* __restrict__ out) {
    int b = blockIdx.x, tid = threadIdx.x;
    const float* xr = xt + (size_t)(b * SQ) * DQ;
    float r0 = xr[tid], r1 = xr[tid + 256], r2 = xr[tid + 512];
    float mean = block_red(r0 + r1 + r2, 0) * (1.f / 768.f);
    float d0 = r0 - mean, d1 = r1 - mean, d2 = r2 - mean;
    float var = block_red(d0 * d0 + d1 * d1 + d2 * d2, 0) * (1.f / 768.f);
    float inv = rsqrtf(var + EPSQ);
    float* yr = out + (size_t)b * DQ;
    yr[tid]       = d0 * inv * sc[tid]       + bi[tid];
    yr[tid + 256] = d1 * inv * sc[tid + 256] + bi[tid + 256];
    yr[tid + 512] = d2 * inv * sc[tid + 512] + bi[tid + 512];
}

// ============== HMMA GEMM v10: 128x128 tile, bulk fills, 2-stage, 2 CTAs/SM ==============
// T2: 2-term A (hi+lo) vs 1-term A (hi only)
#define ARR_A 16384
#define ARR_B 16384
#define STGB  (2*ARR_A + ARR_B)      // 49152 (slot layout fixed; T2=0 leaves Al slot unused)
#define NSTG  2
#define GT_SMEM (NSTG*STGB)          // 98304 -> 2 CTAs/SM

template<int ACT, int OS, int RS, int T2>
__global__ void __launch_bounds__(256, 2) gemm_k(
    const __half* __restrict__ aH, const __half* __restrict__ aL,
    const __half* __restrict__ wH,
    const float* __restrict__ bias, const float* __restrict__ res,
    float* __restrict__ outF,
    __half* __restrict__ oH,
    int M, int Mpad, int N, int K) {
    extern __shared__ char smem[];
    __shared__ __align__(8) uint64_t mbar_store[NSTG];
    uint32_t sb = smem_u32(smem);
    uint32_t mb = smem_u32(mbar_store);
    int tid = threadIdx.x;
    int lane = tid & 31, w = tid >> 5;
    int warpM = w >> 2, warpN = w & 3;
    int g = lane >> 2, q = lane & 3;
    int bm = blockIdx.y * 128, bn = blockIdx.x * 128;
    const int nkt = K >> 6;

    if (tid == 0) {
        #pragma unroll
        for (int s = 0; s < NSTG; s++) MBAR_INIT(mb + s * 8, 1);
        FENCE_ASYNC();
    }
    __syncthreads();

    auto fill = [&](int j) {
        int fb = j & 1;
        uint32_t st = sb + fb * STGB;
        uint32_t m = mb + fb * 8;
        MBAR_EXPECT(m, T2 ? STGB : (ARR_A + ARR_B));
        bulkcp(st,             aH + ((size_t)j * Mpad + bm) * 64, ARR_A, m);
        if (T2)
            bulkcp(st + ARR_A, aL + ((size_t)j * Mpad + bm) * 64, ARR_A, m);
        bulkcp(st + 2 * ARR_A, wH + ((size_t)j * N + bn) * 64,    ARR_B, m);
    };

    if (tid == 0) fill(0);

    float acc[4][4][4];
    #pragma unroll
    for (int i = 0; i < 4; i++)
        #pragma unroll
        for (int j = 0; j < 4; j++)
            #pragma unroll
            for (int c = 0; c < 4; c++) acc[i][j][c] = 0.f;

    int lane7 = lane & 7, hi = lane >> 4;
    uint32_t cb[4];
    #pragma unroll
    for (int kk = 0; kk < 4; kk++) cb[kk] = (uint32_t)(((kk * 2 + hi) ^ lane7) << 4);
    uint32_t arow_off = (uint32_t)(warpM * 64 + (lane & 15)) * 128;
    uint32_t brow_off = (uint32_t)(warpN * 32 + (lane & 15)) * 128 + 2 * ARR_A;

    for (int kt = 0; kt < nkt; kt++) {
        int buf = kt & 1;
        mbar_wait(mb + buf * 8, (uint32_t)((kt >> 1) & 1));
        __syncthreads();
        if (tid == 0 && kt + 1 < nkt) fill(kt + 1);

        uint32_t st = sb + buf * STGB;
        #pragma unroll
        for (int kk = 0; kk < 4; kk++) {
            uint32_t ah[4][4], al[4][4];
            #pragma unroll
            for (int i = 0; i < 4; i++) {
                uint32_t addr = st + arow_off + i * 2048 + cb[kk];
                LDSMX4(ah[i], addr);
                if (T2) LDSMX4(al[i], addr + ARR_A);
            }
            #pragma unroll
            for (int jj = 0; jj < 2; jj++) {
                uint32_t bh[4];
                LDSMX4(bh, st + brow_off + jj * 2048 + cb[kk]);
                #pragma unroll
                for (int sel = 0; sel < 2; sel++) {
                    int j = jj * 2 + sel;
                    uint32_t b0 = bh[sel], b1 = bh[sel + 2];
                    #pragma unroll
                    for (int i = 0; i < 4; i++) {
                        mma16816(acc[i][j], ah[i][0], ah[i][1], ah[i][2], ah[i][3], b0, b1);
                        if (T2)
                            mma16816(acc[i][j], al[i][0], al[i][1], al[i][2], al[i][3], b0, b1);
                    }
                }
            }
        }
    }

    #pragma unroll
    for (int i = 0; i < 4; i++) {
        int m0 = bm + warpM * 64 + i * 16 + g;
        #pragma unroll
        for (int j = 0; j < 4; j++) {
            int n0 = bn + warpN * 32 + j * 8 + q * 2;
            float bx = bias ? bias[n0] : 0.f;
            float by = bias ? bias[n0 + 1] : 0.f;
            #pragma unroll
            for (int half = 0; half < 2; half++) {
                int m = m0 + half * 8;
                if (m >= M) continue;
                float v0 = acc[i][j][half * 2 + 0] + bx;
                float v1 = acc[i][j][half * 2 + 1] + by;
                if (RS) {
                    const float* rp = res + (size_t)m * N + n0;
                    v0 += rp[0]; v1 += rp[1];
                }
                if (ACT) {
                    v0 = gelu_f(v0);
                    v1 = gelu_f(v1);
                }
                if (OS) {
                    __half2 hp = __floats2half2_rn(v0, v1);
                    *(__half2*)&oH[tIdx(TQPAD, m, n0)] = hp;
                } else {
                    *(float2*)(outF + (size_t)m * N + n0) = make_float2(v0, v1);
                }
            }
        }
    }
}

// ---------------- cls-row attention device fn (writes hi+lo for 2-term proj) ----------------
__device__ void cls_attn_dev(const float* __restrict__ qkv,
                             __half* __restrict__ oH, __half* __restrict__ oL,
                             int bh, float* ws) {
    float* sc = ws;
    float* qv = ws + 1600;
    float* op = ws + 1664;
    int b = bh / 12, h = bh % 12;
    int tid = threadIdx.x;
    size_t base = (size_t)(b * SQ) * 2304 + (size_t)h * 64;
    if (tid < 64) qv[tid] = qkv[base + tid] * SCALEQ;
    __syncthreads();
    float lmax = -1e30f;
    for (int s = tid; s < SQ; s += 256) {
        const float* kp = qkv + (size_t)(b * SQ + s) * 2304 + 768 + h * 64;
        float d = 0.f;
        #pragma unroll
        for (int i = 0; i < 64; i++) d += qv[i] * kp[i];
        sc[s] = d; lmax = fmaxf(lmax, d);
    }
    float mx = block_red(lmax, 1);
    float lsum = 0.f;
    for (int s = tid; s < SQ; s += 256) {
        float e = __expf(sc[s] - mx);
        sc[s] = e; lsum += e;
    }
    float den = block_red(lsum, 0);
    __syncthreads();
    int part = tid >> 6, d = tid & 63;
    float acc = 0.f;
    for (int s = part; s < SQ; s += 4)
        acc += sc[s] * qkv[(size_t)(b * SQ + s) * 2304 + 1536 + h * 64 + d];
    op[tid] = acc;
    __syncthreads();
    if (tid < 64) {
        float t = op[tid] + op[tid + 64] + op[tid + 128] + op[tid + 192];
        wsplit(oH, oL, tIdx(TQPAD, b * SQ, h * 64 + tid), t / den);
    }
}

// ---------------- fused time + cls attention ----------------
#define CLS_WS_BYTES (1920*4)
__global__ void time_cls_k(const float* __restrict__ qkv,
                           __half* __restrict__ oH, __half* __restrict__ oL) {
    extern __shared__ float ws[];
    if (blockIdx.x >= 1176) {
        cls_attn_dev(qkv, oH, oL, blockIdx.x - 1176, ws);
        return;
    }
    int g = blockIdx.x * 8 + (threadIdx.x >> 5);
    int lane = threadIdx.x & 31;
    int bh = g / 196, pos = g % 196;
    int b = bh / 12, h = bh % 12;
    float K0[9], K1[9], V0[9], V1[9];
    #pragma unroll
    for (int kk = 0; kk < 9; kk++) {
        int s = kk ? (1 + (kk - 1) * 196 + pos) : 0;
        size_t o = (size_t)(b * SQ + s) * 2304 + h * 64;
        K0[kk] = qkv[o + 768 + lane];  K1[kk] = qkv[o + 768 + lane + 32];
        V0[kk] = qkv[o + 1536 + lane]; V1[kk] = qkv[o + 1536 + lane + 32];
    }
    for (int fq = 0; fq < 8; fq++) {
        int sq = 1 + fq * 196 + pos;
        size_t oq = (size_t)(b * SQ + sq) * 2304 + h * 64;
        float q0 = qkv[oq + lane] * SCALEQ, q1 = qkv[oq + lane + 32] * SCALEQ;
        float sc[9];
        #pragma unroll
        for (int kk = 0; kk < 9; kk++) {
            float p = q0 * K0[kk] + q1 * K1[kk];
            #pragma unroll
            for (int o = 16; o; o >>= 1) p += __shfl_xor_sync(0xffffffffu, p, o);
            sc[kk] = p;
        }
        float mx = sc[0];
        #pragma unroll
        for (int kk = 1; kk < 9; kk++) mx = fmaxf(mx, sc[kk]);
        float den = 0.f;
        #pragma unroll
        for (int kk = 0; kk < 9; kk++) { sc[kk] = __expf(sc[kk] - mx); den += sc[kk]; }
        float inv = 1.f / den;
        float a0 = 0.f, a1 = 0.f;
        #pragma unroll
        for (int kk = 0; kk < 9; kk++) { a0 += sc[kk] * V0[kk]; a1 += sc[kk] * V1[kk]; }
        int m = b * SQ + sq;
        wsplit(oH, oL, tIdx(TQPAD, m, h * 64 + lane),      a0 * inv);
        wsplit(oH, oL, tIdx(TQPAD, m, h * 64 + lane + 32), a1 * inv);
    }
}

// ---------------- fused space + cls attention ----------------
#define SPACE_SMEM ((197*65*2 + 8*197 + 8*64) * 4)
__global__ void space_cls_k(const float* __restrict__ qkv,
                            __half* __restrict__ oH, __half* __restrict__ oL) {
    extern __shared__ float sm[];
    if (blockIdx.x >= 384) {
        cls_attn_dev(qkv, oH, oL, blockIdx.x - 384, sm);
        return;
    }
    float* Ks = sm;
    float* Vs = Ks + 197 * 65;
    float* pb = Vs + 197 * 65;
    float* qb = pb + 8 * 197;
    int blk = blockIdx.x;
    int fr = blk % 8, h = (blk / 8) % 12, b = blk / 96;
    int tid = threadIdx.x, lane = tid & 31, w = tid >> 5;
    for (int idx = tid; idx < 197 * 64; idx += 256) {
        int kk = idx >> 6, d = idx & 63;
        int s = kk ? (1 + fr * 196 + kk - 1) : 0;
        size_t o = (size_t)(b * SQ + s) * 2304 + h * 64;
        Ks[kk * 65 + d] = qkv[o + 768 + d];
        Vs[kk * 65 + d] = qkv[o + 1536 + d];
    }
    __syncthreads();
    for (int qi = w; qi < 196; qi += 8) {
        int sq = 1 + fr * 196 + qi;
        size_t oq = (size_t)(b * SQ + sq) * 2304 + h * 64;
        qb[w * 64 + lane]      = qkv[oq + lane] * SCALEQ;
        qb[w * 64 + lane + 32] = qkv[oq + lane + 32] * SCALEQ;
        __syncwarp();
        float ls[7];
        float lmax = -1e30f;
        int cnt = 0;
        for (int kk = lane; kk < 197; kk += 32) {
            float s = 0.f;
            #pragma unroll
            for (int d = 0; d < 64; d++) s += qb[w * 64 + d] * Ks[kk * 65 + d];
            ls[cnt++] = s; lmax = fmaxf(lmax, s);
        }
        #pragma unroll
        for (int o = 16; o; o >>= 1) lmax = fmaxf(lmax, __shfl_xor_sync(0xffffffffu, lmax, o));
        float lsum = 0.f; cnt = 0;
        for (int kk = lane; kk < 197; kk += 32) {
            float e = __expf(ls[cnt++] - lmax);
            pb[w * 197 + kk] = e; lsum += e;
        }
        #pragma unroll
        for (int o = 16; o; o >>= 1) lsum += __shfl_xor_sync(0xffffffffu, lsum, o);
        float inv = 1.f / lsum;
        __syncwarp();
        float a0 = 0.f, a1 = 0.f;
        for (int kk = 0; kk < 197; kk++) {
            float p = pb[w * 197 + kk];
            a0 += p * Vs[kk * 65 + lane];
            a1 += p * Vs[kk * 65 + lane + 32];
        }
        int m = b * SQ + sq;
        wsplit(oH, oL, tIdx(TQPAD, m, h * 64 + lane),      a0 * inv);
        wsplit(oH, oL, tIdx(TQPAD, m, h * 64 + lane + 32), a1 * inv);
        __syncwarp();
    }
}

// ================== host orchestration ==================
// mode: 0 fp32 out (2-term), 1 fp32+res (2-term), 2 gelu->fp16 hi (1-term),
//       3 fp32+res (1-term), 4 fp32 out (1-term)
static void gemm(const __half* aH, const __half* aL, const __half* wHp,
                 const float* bias, const float* res,
                 float* outF, __half* oH,
                 int M, int Mpad, int N, int K, int mode) {
    dim3 g(N / 128, (M + 127) / 128);
    if (mode == 0)
        gemm_k<0,0,0,1><<<g, 256, GT_SMEM>>>(aH, aL, wHp, bias, res, outF, oH, M, Mpad, N, K);
    else if (mode == 1)
        gemm_k<0,0,1,1><<<g, 256, GT_SMEM>>>(aH, aL, wHp, bias, res, outF, oH, M, Mpad, N, K);
    else if (mode == 2)
        gemm_k<1,1,0,0><<<g, 256, GT_SMEM>>>(aH, aL, wHp, bias, res, outF, oH, M, Mpad, N, K);
    else if (mode == 3)
        gemm_k<0,0,1,0><<<g, 256, GT_SMEM>>>(aH, aL, wHp, bias, res, outF, oH, M, Mpad, N, K);
    else
        gemm_k<0,0,0,0><<<g, 256, GT_SMEM>>>(aH, aL, wHp, bias, res, outF, oH, M, Mpad, N, K);
}

extern "C" void kernel_launch(void* const* d_in, const int* in_sizes, int n_in,
                              void* d_out, int out_size) {
    const float* x       = (const float*)d_in[0];
    const float* patch_w = (const float*)d_in[1];
    const float* patch_b = (const float*)d_in[2];
    const float* cls_tok = (const float*)d_in[3];
    const float* pos     = (const float*)d_in[4];
    const float* temp    = (const float*)d_in[5];
    const float* n1s = (const float*)d_in[6],  *n1b = (const float*)d_in[7];
    const float* n2s = (const float*)d_in[8],  *n2b = (const float*)d_in[9];
    const float* n3s = (const float*)d_in[10], *n3b = (const float*)d_in[11];
    const float* aqw = (const float*)d_in[12], *aqb = (const float*)d_in[13];
    const float* apw = (const float*)d_in[14], *apb = (const float*)d_in[15];
    const float* tqw = (const float*)d_in[16], *tqb = (const float*)d_in[17];
    const float* tpw = (const float*)d_in[18], *tpb = (const float*)d_in[19];
    const float* f1w = (const float*)d_in[20], *f1b = (const float*)d_in[21];
    const float* f2w = (const float*)d_in[22], *f2b = (const float*)d_in[23];
    const float* nfs = (const float*)d_in[24], *nfb = (const float*)d_in[25];
    float* out = (float*)d_out;

    float *xt, *qkv, *res;
    __half *aH, *aL, *hH, *wp;
    cudaGetSymbolAddress((void**)&xt,  g_xt);
    cudaGetSymbolAddress((void**)&qkv, g_qkv);
    cudaGetSymbolAddress((void**)&res, g_res);
    cudaGetSymbolAddress((void**)&aH,  g_aH);
    cudaGetSymbolAddress((void**)&aL,  g_aL);
    cudaGetSymbolAddress((void**)&hH,  g_hH);
    cudaGetSymbolAddress((void**)&wp,  g_w);

    cudaFuncSetAttribute(space_cls_k, cudaFuncAttributeMaxDynamicSharedMemorySize, SPACE_SMEM);
    cudaFuncSetAttribute(gemm_k<0,0,0,1>, cudaFuncAttributeMaxDynamicSharedMemorySize, GT_SMEM);
    cudaFuncSetAttribute(gemm_k<0,0,1,1>, cudaFuncAttributeMaxDynamicSharedMemorySize, GT_SMEM);
    cudaFuncSetAttribute(gemm_k<1,1,0,0>, cudaFuncAttributeMaxDynamicSharedMemorySize, GT_SMEM);
    cudaFuncSetAttribute(gemm_k<0,0,1,0>, cudaFuncAttributeMaxDynamicSharedMemorySize, GT_SMEM);
    cudaFuncSetAttribute(gemm_k<0,0,0,0>, cudaFuncAttributeMaxDynamicSharedMemorySize, GT_SMEM);

    // ---- one-shot weight conversion, batched per weight type ----
    {
        auto launch = [&](const float* src, __half* dst, int N, int K, int layers) {
            int tot = layers * N * (K >> 2);
            cvtw_k<<<(tot + 255) / 256, 256>>>(src, dst, N, K, layers);
        };
        launch(patch_w, wp + W_PATCH, 768, 768, 1);
        launch(tqw, wp + W_TQW, 3 * DQ, DQ, LQ);
        launch(tpw, wp + W_TPW, DQ, DQ, LQ);
        launch(aqw, wp + W_AQW, 3 * DQ, DQ, LQ);
        launch(apw, wp + W_APW, DQ, DQ, LQ);
        launch(f1w, wp + W_F1W, HIDQ, DQ, LQ);
        launch(f2w, wp + W_F2W, DQ, HIDQ, LQ);
    }

    // ---- patch embedding (2-term) ----
    im2col_k<<<(6272 * 768 + 255) / 256, 256>>>(x, aH, aL);
    gemm(aH, aL, wp + W_PATCH, nullptr, nullptr, qkv, nullptr,
         6272, TQPAD, 768, 768, 0);
    assemble_k<<<(TQ * DQ + 255) / 256, 256>>>(qkv, patch_b, cls_tok, pos, temp, xt);

    for (int l = 0; l < LQ; l++) {
        // ---- time attention (qkv: 1-term) ----
        ln_k<<<TQ, 256>>>(xt, n3s + (size_t)l * DQ, n3b + (size_t)l * DQ, aH);
        gemm(aH, nullptr, wp + W_TQW + (size_t)l * 3 * DQ * DQ, tqb + (size_t)l * 3 * DQ,
             nullptr, qkv, nullptr, TQ, TQPAD, 3 * DQ, DQ, 4);
        time_cls_k<<<1176 + 48, 256, CLS_WS_BYTES>>>(qkv, aH, aL);
        gemm(aH, aL, wp + W_TPW + (size_t)l * DQ * DQ, tpb + (size_t)l * DQ,
             xt, res, nullptr, TQ, TQPAD, DQ, DQ, 1);               // time_res (2-term)
        // ---- space attention (qkv: 1-term) ----
        ln_k<<<TQ, 256>>>(res, n1s + (size_t)l * DQ, n1b + (size_t)l * DQ, aH);
        gemm(aH, nullptr, wp + W_AQW + (size_t)l * 3 * DQ * DQ, aqb + (size_t)l * 3 * DQ,
             nullptr, qkv, nullptr, TQ, TQPAD, 3 * DQ, DQ, 4);
        space_cls_k<<<384 + 48, 256, SPACE_SMEM>>>(qkv, aH, aL);
        gemm(aH, aL, wp + W_APW + (size_t)l * DQ * DQ, apb + (size_t)l * DQ,
             xt, res, nullptr, TQ, TQPAD, DQ, DQ, 1);               // space_res (2-term)
        // ---- MLP (1-term GEMMs) ----
        ln_k<<<TQ, 256>>>(res, n2s + (size_t)l * DQ, n2b + (size_t)l * DQ, aH);
        gemm(aH, nullptr, wp + W_F1W + (size_t)l * HIDQ * DQ, f1b + (size_t)l * HIDQ,
             nullptr, nullptr, hH, TQ, TQPAD, HIDQ, DQ, 2);         // gelu -> fp16 hi
        gemm(hH, nullptr, wp + W_F2W + (size_t)l * DQ * HIDQ, f2b + (size_t)l * DQ,
             res, xt, nullptr, TQ, TQPAD, DQ, HIDQ, 3);             // xt = res + mlp
    }

    final_ln_k<<<BQ, 256>>>(xt, nfs, nfb, out);
}

// round 16
// speedup vs baseline: 1.4891x; 1.0419x over previous
#include <cuda_runtime.h>
#include <cuda_fp16.h>
#include <stdint.h>
#include <math.h>

// ---------------- problem constants ----------------
#define BQ 4
#define DQ 768
#define SQ 1569                  // 1 + 8*196
#define TQ (BQ*SQ)               // 6276 tokens
#define TQPAD 6400               // padded rows for tiled A operands
#define HIDQ 3072
#define LQ 12
#define EPSQ 1e-6f
#define SCALEQ 0.125f            // 64^-0.5

// weight pool offsets (halfs) -- tiled layouts
#define W_PATCH 0
#define W_TQW   (W_PATCH + 768*768)
#define W_TPW   (W_TQW + (size_t)LQ*3*DQ*DQ)
#define W_AQW   (W_TPW + (size_t)LQ*DQ*DQ)
#define W_APW   (W_AQW + (size_t)LQ*3*DQ*DQ)
#define W_F1W   (W_APW + (size_t)LQ*DQ*DQ)
#define W_F2W   (W_F1W + (size_t)LQ*HIDQ*DQ)
#define W_TOTAL (W_F2W + (size_t)LQ*DQ*HIDQ)

// ---------------- scratch (static device globals) ----------------
__device__ float g_xt [(size_t)TQ*DQ];
__device__ float g_qkv[(size_t)TQ*3*DQ];
__device__ float g_res[(size_t)TQ*DQ];
__device__ __half g_aH[(size_t)TQPAD*DQ],  g_aL[(size_t)TQPAD*DQ];   // aL used by patch embed only
__device__ __half g_hH[(size_t)TQPAD*HIDQ];
__device__ __half g_w [W_TOTAL];

// ---------------- tiled + swizzled index ----------------
__device__ __forceinline__ size_t tIdx(size_t rows, int m, int k) {
    return ((size_t)(k >> 6) * rows + m) * 64
         + ((((k >> 3) & 7) ^ (m & 7)) << 3) + (k & 7);
}

// ---------------- helpers ----------------
__device__ __forceinline__ uint32_t smem_u32(const void* p) {
    uint32_t a;
    asm("{ .reg .u64 t; cvta.to.shared.u64 t, %1; cvt.u32.u64 %0, t; }" : "=r"(a) : "l"(p));
    return a;
}

#define MBAR_INIT(addr, cnt) \
    asm volatile("mbarrier.init.shared.b64 [%0], %1;" :: "r"(addr), "r"((uint32_t)(cnt)) : "memory")
#define MBAR_EXPECT(addr, bytes) \
    asm volatile("mbarrier.arrive.expect_tx.shared.b64 _, [%0], %1;" :: "r"(addr), "r"((uint32_t)(bytes)) : "memory")
#define FENCE_ASYNC() asm volatile("fence.proxy.async.shared::cta;" ::: "memory")

__device__ __forceinline__ void mbar_wait(uint32_t mbar, uint32_t parity) {
    asm volatile(
        "{\n\t.reg .pred P;\n\t"
        "W_%=:\n\t"
        "mbarrier.try_wait.parity.acquire.cta.shared::cta.b64 P, [%0], %1, 0x989680;\n\t"
        "@P bra.uni D_%=;\n\t"
        "bra.uni W_%=;\n\t"
        "D_%=:\n\t}"
        :: "r"(mbar), "r"(parity) : "memory");
}

__device__ __forceinline__ void bulkcp(uint32_t dst, const void* src, uint32_t bytes, uint32_t mbar) {
    asm volatile("cp.async.bulk.shared::cluster.global.mbarrier::complete_tx::bytes "
                 "[%0], [%1], %2, [%3];"
                 :: "r"(dst), "l"(src), "r"(bytes), "r"(mbar) : "memory");
}

#define LDSMX4(r, addr) \
    asm volatile("ldmatrix.sync.aligned.m8n8.x4.shared.b16 {%0,%1,%2,%3}, [%4];" \
                 : "=r"((r)[0]), "=r"((r)[1]), "=r"((r)[2]), "=r"((r)[3]) : "r"(addr))

__device__ __forceinline__ void mma16816(float* c,
        uint32_t a0, uint32_t a1, uint32_t a2, uint32_t a3,
        uint32_t b0, uint32_t b1) {
    asm volatile(
        "mma.sync.aligned.m16n8k16.row.col.f32.f16.f16.f32 "
        "{%0,%1,%2,%3}, {%4,%5,%6,%7}, {%8,%9}, {%0,%1,%2,%3};\n"
        : "+f"(c[0]), "+f"(c[1]), "+f"(c[2]), "+f"(c[3])
        : "r"(a0), "r"(a1), "r"(a2), "r"(a3), "r"(b0), "r"(b1));
}

__device__ __forceinline__ void wsplit(__half* hi, __half* lo, size_t i, float v) {
    __half h = __float2half_rn(v);
    hi[i] = h;
    lo[i] = __float2half_rn(v - __half2float(h));
}

// branch-free GELU: erf via Abramowitz-Stegun 7.1.26 (abs err < 1.5e-7)
__device__ __forceinline__ float gelu_f(float v) {
    float z = fabsf(v) * 0.70710678118654752f;
    float t = __frcp_rn(1.f + 0.3275911f * z);
    float p = t * (0.254829592f + t * (-0.284496736f + t * (1.421413741f
            + t * (-1.453152027f + t * 1.061405429f))));
    float erfz = 1.f - p * __expf(-z * z);
    erfz = copysignf(erfz, v);
    return 0.5f * v * (1.f + erfz);
}

__device__ __forceinline__ float block_red(float v, int isMax) {
    __shared__ float red[8];
    int lane = threadIdx.x & 31, w = threadIdx.x >> 5;
    #pragma unroll
    for (int o = 16; o; o >>= 1) {
        float t = __shfl_xor_sync(0xffffffffu, v, o);
        v = isMax ? fmaxf(v, t) : (v + t);
    }
    __syncthreads();
    if (lane == 0) red[w] = v;
    __syncthreads();
    float t = red[0];
    #pragma unroll
    for (int i = 1; i < 8; i++) t = isMax ? fmaxf(t, red[i]) : (t + red[i]);
    return t;
}

// ---------------- batched weight convert fp32 -> tiled/swizzled fp16 ----------------
__global__ void cvtw_k(const float* __restrict__ w, __half* __restrict__ o,
                       int N, int K, int layers) {
    int perL4 = N * (K >> 2);
    int idx = blockIdx.x * 256 + threadIdx.x;
    if (idx >= layers * perL4) return;
    int l = idx / perL4, rem = idx - l * perL4;
    int K4 = K >> 2;
    int n = rem / K4, kq = rem - n * K4;
    int k = kq * 4;
    float4 v = ((const float4*)w)[idx];
    __half2 a = __floats2half2_rn(v.x, v.y);
    __half2 b = __floats2half2_rn(v.z, v.w);
    uint2 r;
    r.x = *(uint32_t*)&a; r.y = *(uint32_t*)&b;
    *(uint2*)&o[(size_t)l * N * K + tIdx(N, n, k)] = r;
}

// ---------------- im2col -> tiled split fp16 (2-term for patch embed) ----------------
__global__ void im2col_k(const float* __restrict__ x,
                         __half* __restrict__ oH, __half* __restrict__ oL) {
    int idx = blockIdx.x * 256 + threadIdx.x;
    if (idx >= 6272 * 768) return;
    int r = idx / 768, c = idx % 768;
    int bf = r / 196, p = r % 196;
    int ph = p / 14, pw = p % 14;
    int ch = c >> 8, rem = c & 255;
    int i = rem >> 4, j = rem & 15;
    size_t off = (((size_t)bf * 3 + ch) * 224 + ph * 16 + i) * 224 + pw * 16 + j;
    wsplit(oH, oL, tIdx(TQPAD, r, c), x[off]);
}

// ---------------- assemble tokens (fp32 xt) ----------------
__global__ void assemble_k(const float* __restrict__ pe,
                           const float* __restrict__ patch_b,
                           const float* __restrict__ cls_tok,
                           const float* __restrict__ pos,
                           const float* __restrict__ temp,
                           float* __restrict__ xt) {
    int idx = blockIdx.x * 256 + threadIdx.x;
    if (idx >= TQ * DQ) return;
    int t = idx / DQ, dd = idx % DQ;
    int b = t / SQ, s = t % SQ;
    float v;
    if (s == 0) {
        v = cls_tok[dd] + pos[dd];
    } else {
        int sp = s - 1, fr = sp / 196, p = sp % 196;
        v = pe[((size_t)(b * 8 + fr) * 196 + p) * 768 + dd] + patch_b[dd]
            + pos[(size_t)(1 + p) * 768 + dd] + temp[(size_t)fr * 768 + dd];
    }
    xt[idx] = v;
}

// ---------------- layernorm -> tiled fp16 (hi plane only) ----------------
__global__ void ln_k(const float* __restrict__ x, const float* __restrict__ sc,
                     const float* __restrict__ bi,
                     __half* __restrict__ oH) {
    int row = blockIdx.x, tid = threadIdx.x;
    const float* xr = x + (size_t)row * DQ;
    float r0 = xr[tid], r1 = xr[tid + 256], r2 = xr[tid + 512];
    float mean = block_red(r0 + r1 + r2, 0) * (1.f / 768.f);
    float d0 = r0 - mean, d1 = r1 - mean, d2 = r2 - mean;
    float var = block_red(d0 * d0 + d1 * d1 + d2 * d2, 0) * (1.f / 768.f);
    float inv = rsqrtf(var + EPSQ);
    oH[tIdx(TQPAD, row, tid)]       = __float2half_rn(d0 * inv * sc[tid]       + bi[tid]);
    oH[tIdx(TQPAD, row, tid + 256)] = __float2half_rn(d1 * inv * sc[tid + 256] + bi[tid + 256]);
    oH[tIdx(TQPAD, row, tid + 512)] = __float2half_rn(d2 * inv * sc[tid + 512] + bi[tid + 512]);
}

__global__ void final_ln_k(const float* __restrict__ xt, const float* __restrict__ sc,
                           const float* __restrict__ bi, float* __restrict__ out) {
    int b = blockIdx.x, tid = threadIdx.x;
    const float* xr = xt + (size_t)(b * SQ) * DQ;
    float r0 = xr[tid], r1 = xr[tid + 256], r2 = xr[tid + 512];
    float mean = block_red(r0 + r1 + r2, 0) * (1.f / 768.f);
    float d0 = r0 - mean, d1 = r1 - mean, d2 = r2 - mean;
    float var = block_red(d0 * d0 + d1 * d1 + d2 * d2, 0) * (1.f / 768.f);
    float inv = rsqrtf(var + EPSQ);
    float* yr = out + (size_t)b * DQ;
    yr[tid]       = d0 * inv * sc[tid]       + bi[tid];
    yr[tid + 256] = d1 * inv * sc[tid + 256] + bi[tid + 256];
    yr[tid + 512] = d2 * inv * sc[tid + 512] + bi[tid + 512];
}

// ============== HMMA GEMM v11: 128x128 tile, bulk fills, 2-stage, 2 CTAs/SM ==============
// T2: 2-term A (hi+lo) vs 1-term A (hi only). Prologue now fills both stages concurrently.
#define ARR_A 16384
#define ARR_B 16384
#define STGB  (2*ARR_A + ARR_B)      // 49152
#define NSTG  2
#define GT_SMEM (NSTG*STGB)          // 98304 -> 2 CTAs/SM

template<int ACT, int OS, int RS, int T2>
__global__ void __launch_bounds__(256, 2) gemm_k(
    const __half* __restrict__ aH, const __half* __restrict__ aL,
    const __half* __restrict__ wH,
    const float* __restrict__ bias, const float* __restrict__ res,
    float* __restrict__ outF,
    __half* __restrict__ oH,
    int M, int Mpad, int N, int K) {
    extern __shared__ char smem[];
    __shared__ __align__(8) uint64_t mbar_store[NSTG];
    uint32_t sb = smem_u32(smem);
    uint32_t mb = smem_u32(mbar_store);
    int tid = threadIdx.x;
    int lane = tid & 31, w = tid >> 5;
    int warpM = w >> 2, warpN = w & 3;
    int g = lane >> 2, q = lane & 3;
    int bm = blockIdx.y * 128, bn = blockIdx.x * 128;
    const int nkt = K >> 6;              // >= 2 for all our GEMMs

    if (tid == 0) {
        #pragma unroll
        for (int s = 0; s < NSTG; s++) MBAR_INIT(mb + s * 8, 1);
        FENCE_ASYNC();
    }
    __syncthreads();

    auto fill = [&](int j) {
        int fb = j & 1;
        uint32_t st = sb + fb * STGB;
        uint32_t m = mb + fb * 8;
        MBAR_EXPECT(m, T2 ? STGB : (ARR_A + ARR_B));
        bulkcp(st,             aH + ((size_t)j * Mpad + bm) * 64, ARR_A, m);
        if (T2)
            bulkcp(st + ARR_A, aL + ((size_t)j * Mpad + bm) * 64, ARR_A, m);
        bulkcp(st + 2 * ARR_A, wH + ((size_t)j * N + bn) * 64,    ARR_B, m);
    };

    if (tid == 0) { fill(0); fill(1); }      // both stages in flight

    float acc[4][4][4];
    #pragma unroll
    for (int i = 0; i < 4; i++)
        #pragma unroll
        for (int j = 0; j < 4; j++)
            #pragma unroll
            for (int c = 0; c < 4; c++) acc[i][j][c] = 0.f;

    int lane7 = lane & 7, hi = lane >> 4;
    uint32_t cb[4];
    #pragma unroll
    for (int kk = 0; kk < 4; kk++) cb[kk] = (uint32_t)(((kk * 2 + hi) ^ lane7) << 4);
    uint32_t arow_off = (uint32_t)(warpM * 64 + (lane & 15)) * 128;
    uint32_t brow_off = (uint32_t)(warpN * 32 + (lane & 15)) * 128 + 2 * ARR_A;

    for (int kt = 0; kt < nkt; kt++) {
        int buf = kt & 1;
        mbar_wait(mb + buf * 8, (uint32_t)((kt >> 1) & 1));
        __syncthreads();                       // compute on buf^1 (iter kt-1) done
        if (tid == 0 && kt >= 1 && kt + 1 < nkt) fill(kt + 1);

        uint32_t st = sb + buf * STGB;
        #pragma unroll
        for (int kk = 0; kk < 4; kk++) {
            uint32_t ah[4][4], al[4][4];
            #pragma unroll
            for (int i = 0; i < 4; i++) {
                uint32_t addr = st + arow_off + i * 2048 + cb[kk];
                LDSMX4(ah[i], addr);
                if (T2) LDSMX4(al[i], addr + ARR_A);
            }
            #pragma unroll
            for (int jj = 0; jj < 2; jj++) {
                uint32_t bh[4];
                LDSMX4(bh, st + brow_off + jj * 2048 + cb[kk]);
                #pragma unroll
                for (int sel = 0; sel < 2; sel++) {
                    int j = jj * 2 + sel;
                    uint32_t b0 = bh[sel], b1 = bh[sel + 2];
                    #pragma unroll
                    for (int i = 0; i < 4; i++) {
                        mma16816(acc[i][j], ah[i][0], ah[i][1], ah[i][2], ah[i][3], b0, b1);
                        if (T2)
                            mma16816(acc[i][j], al[i][0], al[i][1], al[i][2], al[i][3], b0, b1);
                    }
                }
            }
        }
    }

    #pragma unroll
    for (int i = 0; i < 4; i++) {
        int m0 = bm + warpM * 64 + i * 16 + g;
        #pragma unroll
        for (int j = 0; j < 4; j++) {
            int n0 = bn + warpN * 32 + j * 8 + q * 2;
            float bx = bias ? bias[n0] : 0.f;
            float by = bias ? bias[n0 + 1] : 0.f;
            #pragma unroll
            for (int half = 0; half < 2; half++) {
                int m = m0 + half * 8;
                if (m >= M) continue;
                float v0 = acc[i][j][half * 2 + 0] + bx;
                float v1 = acc[i][j][half * 2 + 1] + by;
                if (RS) {
                    const float* rp = res + (size_t)m * N + n0;
                    v0 += rp[0]; v1 += rp[1];
                }
                if (ACT) {
                    v0 = gelu_f(v0);
                    v1 = gelu_f(v1);
                }
                if (OS) {
                    __half2 hp = __floats2half2_rn(v0, v1);
                    *(__half2*)&oH[tIdx(TQPAD, m, n0)] = hp;
                } else {
                    *(float2*)(outF + (size_t)m * N + n0) = make_float2(v0, v1);
                }
            }
        }
    }
}

// ---------------- cls-row attention device fn (hi plane only) ----------------
__device__ void cls_attn_dev(const float* __restrict__ qkv,
                             __half* __restrict__ oH,
                             int bh, float* ws) {
    float* sc = ws;
    float* qv = ws + 1600;
    float* op = ws + 1664;
    int b = bh / 12, h = bh % 12;
    int tid = threadIdx.x;
    size_t base = (size_t)(b * SQ) * 2304 + (size_t)h * 64;
    if (tid < 64) qv[tid] = qkv[base + tid] * SCALEQ;
    __syncthreads();
    float lmax = -1e30f;
    for (int s = tid; s < SQ; s += 256) {
        const float* kp = qkv + (size_t)(b * SQ + s) * 2304 + 768 + h * 64;
        float d = 0.f;
        #pragma unroll
        for (int i = 0; i < 64; i++) d += qv[i] * kp[i];
        sc[s] = d; lmax = fmaxf(lmax, d);
    }
    float mx = block_red(lmax, 1);
    float lsum = 0.f;
    for (int s = tid; s < SQ; s += 256) {
        float e = __expf(sc[s] - mx);
        sc[s] = e; lsum += e;
    }
    float den = block_red(lsum, 0);
    __syncthreads();
    int part = tid >> 6, d = tid & 63;
    float acc = 0.f;
    for (int s = part; s < SQ; s += 4)
        acc += sc[s] * qkv[(size_t)(b * SQ + s) * 2304 + 1536 + h * 64 + d];
    op[tid] = acc;
    __syncthreads();
    if (tid < 64) {
        float t = op[tid] + op[tid + 64] + op[tid + 128] + op[tid + 192];
        oH[tIdx(TQPAD, b * SQ, h * 64 + tid)] = __float2half_rn(t / den);
    }
}

// ---------------- fused time + cls attention (hi plane only) ----------------
#define CLS_WS_BYTES (1920*4)
__global__ void time_cls_k(const float* __restrict__ qkv,
                           __half* __restrict__ oH) {
    extern __shared__ float ws[];
    if (blockIdx.x >= 1176) {
        cls_attn_dev(qkv, oH, blockIdx.x - 1176, ws);
        return;
    }
    int g = blockIdx.x * 8 + (threadIdx.x >> 5);
    int lane = threadIdx.x & 31;
    int bh = g / 196, pos = g % 196;
    int b = bh / 12, h = bh % 12;
    float K0[9], K1[9], V0[9], V1[9];
    #pragma unroll
    for (int kk = 0; kk < 9; kk++) {
        int s = kk ? (1 + (kk - 1) * 196 + pos) : 0;
        size_t o = (size_t)(b * SQ + s) * 2304 + h * 64;
        K0[kk] = qkv[o + 768 + lane];  K1[kk] = qkv[o + 768 + lane + 32];
        V0[kk] = qkv[o + 1536 + lane]; V1[kk] = qkv[o + 1536 + lane + 32];
    }
    for (int fq = 0; fq < 8; fq++) {
        int sq = 1 + fq * 196 + pos;
        size_t oq = (size_t)(b * SQ + sq) * 2304 + h * 64;
        float q0 = qkv[oq + lane] * SCALEQ, q1 = qkv[oq + lane + 32] * SCALEQ;
        float sc[9];
        #pragma unroll
        for (int kk = 0; kk < 9; kk++) {
            float p = q0 * K0[kk] + q1 * K1[kk];
            #pragma unroll
            for (int o = 16; o; o >>= 1) p += __shfl_xor_sync(0xffffffffu, p, o);
            sc[kk] = p;
        }
        float mx = sc[0];
        #pragma unroll
        for (int kk = 1; kk < 9; kk++) mx = fmaxf(mx, sc[kk]);
        float den = 0.f;
        #pragma unroll
        for (int kk = 0; kk < 9; kk++) { sc[kk] = __expf(sc[kk] - mx); den += sc[kk]; }
        float inv = 1.f / den;
        float a0 = 0.f, a1 = 0.f;
        #pragma unroll
        for (int kk = 0; kk < 9; kk++) { a0 += sc[kk] * V0[kk]; a1 += sc[kk] * V1[kk]; }
        int m = b * SQ + sq;
        oH[tIdx(TQPAD, m, h * 64 + lane)]      = __float2half_rn(a0 * inv);
        oH[tIdx(TQPAD, m, h * 64 + lane + 32)] = __float2half_rn(a1 * inv);
    }
}

// ---------------- fused space + cls attention (hi plane only) ----------------
#define SPACE_SMEM ((197*65*2 + 8*197 + 8*64) * 4)
__global__ void space_cls_k(const float* __restrict__ qkv,
                            __half* __restrict__ oH) {
    extern __shared__ float sm[];
    if (blockIdx.x >= 384) {
        cls_attn_dev(qkv, oH, blockIdx.x - 384, sm);
        return;
    }
    float* Ks = sm;
    float* Vs = Ks + 197 * 65;
    float* pb = Vs + 197 * 65;
    float* qb = pb + 8 * 197;
    int blk = blockIdx.x;
    int fr = blk % 8, h = (blk / 8) % 12, b = blk / 96;
    int tid = threadIdx.x, lane = tid & 31, w = tid >> 5;
    for (int idx = tid; idx < 197 * 64; idx += 256) {
        int kk = idx >> 6, d = idx & 63;
        int s = kk ? (1 + fr * 196 + kk - 1) : 0;
        size_t o = (size_t)(b * SQ + s) * 2304 + h * 64;
        Ks[kk * 65 + d] = qkv[o + 768 + d];
        Vs[kk * 65 + d] = qkv[o + 1536 + d];
    }
    __syncthreads();
    for (int qi = w; qi < 196; qi += 8) {
        int sq = 1 + fr * 196 + qi;
        size_t oq = (size_t)(b * SQ + sq) * 2304 + h * 64;
        qb[w * 64 + lane]      = qkv[oq + lane] * SCALEQ;
        qb[w * 64 + lane + 32] = qkv[oq + lane + 32] * SCALEQ;
        __syncwarp();
        float ls[7];
        float lmax = -1e30f;
        int cnt = 0;
        for (int kk = lane; kk < 197; kk += 32) {
            float s = 0.f;
            #pragma unroll
            for (int d = 0; d < 64; d++) s += qb[w * 64 + d] * Ks[kk * 65 + d];
            ls[cnt++] = s; lmax = fmaxf(lmax, s);
        }
        #pragma unroll
        for (int o = 16; o; o >>= 1) lmax = fmaxf(lmax, __shfl_xor_sync(0xffffffffu, lmax, o));
        float lsum = 0.f; cnt = 0;
        for (int kk = lane; kk < 197; kk += 32) {
            float e = __expf(ls[cnt++] - lmax);
            pb[w * 197 + kk] = e; lsum += e;
        }
        #pragma unroll
        for (int o = 16; o; o >>= 1) lsum += __shfl_xor_sync(0xffffffffu, lsum, o);
        float inv = 1.f / lsum;
        __syncwarp();
        float a0 = 0.f, a1 = 0.f;
        for (int kk = 0; kk < 197; kk++) {
            float p = pb[w * 197 + kk];
            a0 += p * Vs[kk * 65 + lane];
            a1 += p * Vs[kk * 65 + lane + 32];
        }
        int m = b * SQ + sq;
        oH[tIdx(TQPAD, m, h * 64 + lane)]      = __float2half_rn(a0 * inv);
        oH[tIdx(TQPAD, m, h * 64 + lane + 32)] = __float2half_rn(a1 * inv);
        __syncwarp();
    }
}

// ================== host orchestration ==================
// mode: 0 fp32 out (2-term, patch), 2 gelu->fp16 hi (1-term),
//       3 fp32+res (1-term), 4 fp32 out (1-term)
static void gemm(const __half* aH, const __half* aL, const __half* wHp,
                 const float* bias, const float* res,
                 float* outF, __half* oH,
                 int M, int Mpad, int N, int K, int mode) {
    dim3 g(N / 128, (M + 127) / 128);
    if (mode == 0)
        gemm_k<0,0,0,1><<<g, 256, GT_SMEM>>>(aH, aL, wHp, bias, res, outF, oH, M, Mpad, N, K);
    else if (mode == 2)
        gemm_k<1,1,0,0><<<g, 256, GT_SMEM>>>(aH, aL, wHp, bias, res, outF, oH, M, Mpad, N, K);
    else if (mode == 3)
        gemm_k<0,0,1,0><<<g, 256, GT_SMEM>>>(aH, aL, wHp, bias, res, outF, oH, M, Mpad, N, K);
    else
        gemm_k<0,0,0,0><<<g, 256, GT_SMEM>>>(aH, aL, wHp, bias, res, outF, oH, M, Mpad, N, K);
}

extern "C" void kernel_launch(void* const* d_in, const int* in_sizes, int n_in,
                              void* d_out, int out_size) {
    const float* x       = (const float*)d_in[0];
    const float* patch_w = (const float*)d_in[1];
    const float* patch_b = (const float*)d_in[2];
    const float* cls_tok = (const float*)d_in[3];
    const float* pos     = (const float*)d_in[4];
    const float* temp    = (const float*)d_in[5];
    const float* n1s = (const float*)d_in[6],  *n1b = (const float*)d_in[7];
    const float* n2s = (const float*)d_in[8],  *n2b = (const float*)d_in[9];
    const float* n3s = (const float*)d_in[10], *n3b = (const float*)d_in[11];
    const float* aqw = (const float*)d_in[12], *aqb = (const float*)d_in[13];
    const float* apw = (const float*)d_in[14], *apb = (const float*)d_in[15];
    const float* tqw = (const float*)d_in[16], *tqb = (const float*)d_in[17];
    const float* tpw = (const float*)d_in[18], *tpb = (const float*)d_in[19];
    const float* f1w = (const float*)d_in[20], *f1b = (const float*)d_in[21];
    const float* f2w = (const float*)d_in[22], *f2b = (const float*)d_in[23];
    const float* nfs = (const float*)d_in[24], *nfb = (const float*)d_in[25];
    float* out = (float*)d_out;

    float *xt, *qkv, *res;
    __half *aH, *aL, *hH, *wp;
    cudaGetSymbolAddress((void**)&xt,  g_xt);
    cudaGetSymbolAddress((void**)&qkv, g_qkv);
    cudaGetSymbolAddress((void**)&res, g_res);
    cudaGetSymbolAddress((void**)&aH,  g_aH);
    cudaGetSymbolAddress((void**)&aL,  g_aL);
    cudaGetSymbolAddress((void**)&hH,  g_hH);
    cudaGetSymbolAddress((void**)&wp,  g_w);

    cudaFuncSetAttribute(space_cls_k, cudaFuncAttributeMaxDynamicSharedMemorySize, SPACE_SMEM);
    cudaFuncSetAttribute(gemm_k<0,0,0,1>, cudaFuncAttributeMaxDynamicSharedMemorySize, GT_SMEM);
    cudaFuncSetAttribute(gemm_k<1,1,0,0>, cudaFuncAttributeMaxDynamicSharedMemorySize, GT_SMEM);
    cudaFuncSetAttribute(gemm_k<0,0,1,0>, cudaFuncAttributeMaxDynamicSharedMemorySize, GT_SMEM);
    cudaFuncSetAttribute(gemm_k<0,0,0,0>, cudaFuncAttributeMaxDynamicSharedMemorySize, GT_SMEM);

    // ---- one-shot weight conversion, batched per weight type ----
    {
        auto launch = [&](const float* src, __half* dst, int N, int K, int layers) {
            int tot = layers * N * (K >> 2);
            cvtw_k<<<(tot + 255) / 256, 256>>>(src, dst, N, K, layers);
        };
        launch(patch_w, wp + W_PATCH, 768, 768, 1);
        launch(tqw, wp + W_TQW, 3 * DQ, DQ, LQ);
        launch(tpw, wp + W_TPW, DQ, DQ, LQ);
        launch(aqw, wp + W_AQW, 3 * DQ, DQ, LQ);
        launch(apw, wp + W_APW, DQ, DQ, LQ);
        launch(f1w, wp + W_F1W, HIDQ, DQ, LQ);
        launch(f2w, wp + W_F2W, DQ, HIDQ, LQ);
    }

    // ---- patch embedding (2-term) ----
    im2col_k<<<(6272 * 768 + 255) / 256, 256>>>(x, aH, aL);
    gemm(aH, aL, wp + W_PATCH, nullptr, nullptr, qkv, nullptr,
         6272, TQPAD, 768, 768, 0);
    assemble_k<<<(TQ * DQ + 255) / 256, 256>>>(qkv, patch_b, cls_tok, pos, temp, xt);

    for (int l = 0; l < LQ; l++) {
        // ---- time attention (all 1-term) ----
        ln_k<<<TQ, 256>>>(xt, n3s + (size_t)l * DQ, n3b + (size_t)l * DQ, aH);
        gemm(aH, nullptr, wp + W_TQW + (size_t)l * 3 * DQ * DQ, tqb + (size_t)l * 3 * DQ,
             nullptr, qkv, nullptr, TQ, TQPAD, 3 * DQ, DQ, 4);
        time_cls_k<<<1176 + 48, 256, CLS_WS_BYTES>>>(qkv, aH);
        gemm(aH, nullptr, wp + W_TPW + (size_t)l * DQ * DQ, tpb + (size_t)l * DQ,
             xt, res, nullptr, TQ, TQPAD, DQ, DQ, 3);               // time_res
        // ---- space attention (all 1-term) ----
        ln_k<<<TQ, 256>>>(res, n1s + (size_t)l * DQ, n1b + (size_t)l * DQ, aH);
        gemm(aH, nullptr, wp + W_AQW + (size_t)l * 3 * DQ * DQ, aqb + (size_t)l * 3 * DQ,
             nullptr, qkv, nullptr, TQ, TQPAD, 3 * DQ, DQ, 4);
        space_cls_k<<<384 + 48, 256, SPACE_SMEM>>>(qkv, aH);
        gemm(aH, nullptr, wp + W_APW + (size_t)l * DQ * DQ, apb + (size_t)l * DQ,
             xt, res, nullptr, TQ, TQPAD, DQ, DQ, 3);               // space_res
        // ---- MLP (1-term) ----
        ln_k<<<TQ, 256>>>(res, n2s + (size_t)l * DQ, n2b + (size_t)l * DQ, aH);
        gemm(aH, nullptr, wp + W_F1W + (size_t)l * HIDQ * DQ, f1b + (size_t)l * HIDQ,
             nullptr, nullptr, hH, TQ, TQPAD, HIDQ, DQ, 2);         // gelu -> fp16 hi
        gemm(hH, nullptr, wp + W_F2W + (size_t)l * DQ * HIDQ, f2b + (size_t)l * DQ,
             res, xt, nullptr, TQ, TQPAD, DQ, HIDQ, 3);             // xt = res + mlp
    }

    final_ln_k<<<BQ, 256>>>(xt, nfs, nfb, out);
}

// round 17
// speedup vs baseline: 1.5491x; 1.0403x over previous
#include <cuda_runtime.h>
#include <cuda_fp16.h>
#include <stdint.h>
#include <math.h>

// ---------------- problem constants ----------------
#define BQ 4
#define DQ 768
#define SQ 1569                  // 1 + 8*196
#define TQ (BQ*SQ)               // 6276 tokens
#define TQPAD 6400               // padded rows for tiled A operands
#define HIDQ 3072
#define LQ 12
#define EPSQ 1e-6f
#define SCALEQ 0.125f            // 64^-0.5

// weight pool offsets (halfs) -- tiled layouts
#define W_PATCH 0
#define W_TQW   (W_PATCH + 768*768)
#define W_TPW   (W_TQW + (size_t)LQ*3*DQ*DQ)
#define W_AQW   (W_TPW + (size_t)LQ*DQ*DQ)
#define W_APW   (W_AQW + (size_t)LQ*3*DQ*DQ)
#define W_F1W   (W_APW + (size_t)LQ*DQ*DQ)
#define W_F2W   (W_F1W + (size_t)LQ*HIDQ*DQ)
#define W_TOTAL (W_F2W + (size_t)LQ*DQ*HIDQ)

// ---------------- scratch (static device globals) ----------------
__device__ float  g_xt  [(size_t)TQ*DQ];
__device__ float  g_pe  [(size_t)6272*DQ];           // patch-embed staging (fp32)
__device__ float  g_res [(size_t)TQ*DQ];
__device__ __half g_qkvh[(size_t)TQ*3*DQ];           // qkv in fp16 (row-major)
__device__ __half g_aH[(size_t)TQPAD*DQ],  g_aL[(size_t)TQPAD*DQ];   // aL: patch embed only
__device__ __half g_hH[(size_t)TQPAD*HIDQ];
__device__ __half g_w [W_TOTAL];

// ---------------- tiled + swizzled index ----------------
__device__ __forceinline__ size_t tIdx(size_t rows, int m, int k) {
    return ((size_t)(k >> 6) * rows + m) * 64
         + ((((k >> 3) & 7) ^ (m & 7)) << 3) + (k & 7);
}

// ---------------- helpers ----------------
__device__ __forceinline__ uint32_t smem_u32(const void* p) {
    uint32_t a;
    asm("{ .reg .u64 t; cvta.to.shared.u64 t, %1; cvt.u32.u64 %0, t; }" : "=r"(a) : "l"(p));
    return a;
}

#define MBAR_INIT(addr, cnt) \
    asm volatile("mbarrier.init.shared.b64 [%0], %1;" :: "r"(addr), "r"((uint32_t)(cnt)) : "memory")
#define MBAR_EXPECT(addr, bytes) \
    asm volatile("mbarrier.arrive.expect_tx.shared.b64 _, [%0], %1;" :: "r"(addr), "r"((uint32_t)(bytes)) : "memory")
#define FENCE_ASYNC() asm volatile("fence.proxy.async.shared::cta;" ::: "memory")

__device__ __forceinline__ void mbar_wait(uint32_t mbar, uint32_t parity) {
    asm volatile(
        "{\n\t.reg .pred P;\n\t"
        "W_%=:\n\t"
        "mbarrier.try_wait.parity.acquire.cta.shared::cta.b64 P, [%0], %1, 0x989680;\n\t"
        "@P bra.uni D_%=;\n\t"
        "bra.uni W_%=;\n\t"
        "D_%=:\n\t}"
        :: "r"(mbar), "r"(parity) : "memory");
}

__device__ __forceinline__ void bulkcp(uint32_t dst, const void* src, uint32_t bytes, uint32_t mbar) {
    asm volatile("cp.async.bulk.shared::cluster.global.mbarrier::complete_tx::bytes "
                 "[%0], [%1], %2, [%3];"
                 :: "r"(dst), "l"(src), "r"(bytes), "r"(mbar) : "memory");
}

#define LDSMX4(r, addr) \
    asm volatile("ldmatrix.sync.aligned.m8n8.x4.shared.b16 {%0,%1,%2,%3}, [%4];" \
                 : "=r"((r)[0]), "=r"((r)[1]), "=r"((r)[2]), "=r"((r)[3]) : "r"(addr))

__device__ __forceinline__ void mma16816(float* c,
        uint32_t a0, uint32_t a1, uint32_t a2, uint32_t a3,
        uint32_t b0, uint32_t b1) {
    asm volatile(
        "mma.sync.aligned.m16n8k16.row.col.f32.f16.f16.f32 "
        "{%0,%1,%2,%3}, {%4,%5,%6,%7}, {%8,%9}, {%0,%1,%2,%3};\n"
        : "+f"(c[0]), "+f"(c[1]), "+f"(c[2]), "+f"(c[3])
        : "r"(a0), "r"(a1), "r"(a2), "r"(a3), "r"(b0), "r"(b1));
}

__device__ __forceinline__ void wsplit(__half* hi, __half* lo, size_t i, float v) {
    __half h = __float2half_rn(v);
    hi[i] = h;
    lo[i] = __float2half_rn(v - __half2float(h));
}

// branch-free GELU: erf via Abramowitz-Stegun 7.1.26 (abs err < 1.5e-7)
__device__ __forceinline__ float gelu_f(float v) {
    float z = fabsf(v) * 0.70710678118654752f;
    float t = __frcp_rn(1.f + 0.3275911f * z);
    float p = t * (0.254829592f + t * (-0.284496736f + t * (1.421413741f
            + t * (-1.453152027f + t * 1.061405429f))));
    float erfz = 1.f - p * __expf(-z * z);
    erfz = copysignf(erfz, v);
    return 0.5f * v * (1.f + erfz);
}

__device__ __forceinline__ float block_red(float v, int isMax) {
    __shared__ float red[8];
    int lane = threadIdx.x & 31, w = threadIdx.x >> 5;
    #pragma unroll
    for (int o = 16; o; o >>= 1) {
        float t = __shfl_xor_sync(0xffffffffu, v, o);
        v = isMax ? fmaxf(v, t) : (v + t);
    }
    __syncthreads();
    if (lane == 0) red[w] = v;
    __syncthreads();
    float t = red[0];
    #pragma unroll
    for (int i = 1; i < 8; i++) t = isMax ? fmaxf(t, red[i]) : (t + red[i]);
    return t;
}

// ---------------- batched weight convert fp32 -> tiled/swizzled fp16 ----------------
__global__ void cvtw_k(const float* __restrict__ w, __half* __restrict__ o,
                       int N, int K, int layers) {
    int perL4 = N * (K >> 2);
    int idx = blockIdx.x * 256 + threadIdx.x;
    if (idx >= layers * perL4) return;
    int l = idx / perL4, rem = idx - l * perL4;
    int K4 = K >> 2;
    int n = rem / K4, kq = rem - n * K4;
    int k = kq * 4;
    float4 v = ((const float4*)w)[idx];
    __half2 a = __floats2half2_rn(v.x, v.y);
    __half2 b = __floats2half2_rn(v.z, v.w);
    uint2 r;
    r.x = *(uint32_t*)&a; r.y = *(uint32_t*)&b;
    *(uint2*)&o[(size_t)l * N * K + tIdx(N, n, k)] = r;
}

// ---------------- im2col -> tiled split fp16 (2-term for patch embed) ----------------
__global__ void im2col_k(const float* __restrict__ x,
                         __half* __restrict__ oH, __half* __restrict__ oL) {
    int idx = blockIdx.x * 256 + threadIdx.x;
    if (idx >= 6272 * 768) return;
    int r = idx / 768, c = idx % 768;
    int bf = r / 196, p = r % 196;
    int ph = p / 14, pw = p % 14;
    int ch = c >> 8, rem = c & 255;
    int i = rem >> 4, j = rem & 15;
    size_t off = (((size_t)bf * 3 + ch) * 224 + ph * 16 + i) * 224 + pw * 16 + j;
    wsplit(oH, oL, tIdx(TQPAD, r, c), x[off]);
}

// ---------------- assemble tokens (fp32 xt) ----------------
__global__ void assemble_k(const float* __restrict__ pe,
                           const float* __restrict__ patch_b,
                           const float* __restrict__ cls_tok,
                           const float* __restrict__ pos,
                           const float* __restrict__ temp,
                           float* __restrict__ xt) {
    int idx = blockIdx.x * 256 + threadIdx.x;
    if (idx >= TQ * DQ) return;
    int t = idx / DQ, dd = idx % DQ;
    int b = t / SQ, s = t % SQ;
    float v;
    if (s == 0) {
        v = cls_tok[dd] + pos[dd];
    } else {
        int sp = s - 1, fr = sp / 196, p = sp % 196;
        v = pe[((size_t)(b * 8 + fr) * 196 + p) * 768 + dd] + patch_b[dd]
            + pos[(size_t)(1 + p) * 768 + dd] + temp[(size_t)fr * 768 + dd];
    }
    xt[idx] = v;
}

// ---------------- layernorm -> tiled fp16 (hi plane only) ----------------
__global__ void ln_k(const float* __restrict__ x, const float* __restrict__ sc,
                     const float* __restrict__ bi,
                     __half* __restrict__ oH) {
    int row = blockIdx.x, tid = threadIdx.x;
    const float* xr = x + (size_t)row * DQ;
    float r0 = xr[tid], r1 = xr[tid + 256], r2 = xr[tid + 512];
    float mean = block_red(r0 + r1 + r2, 0) * (1.f / 768.f);
    float d0 = r0 - mean, d1 = r1 - mean, d2 = r2 - mean;
    float var = block_red(d0 * d0 + d1 * d1 + d2 * d2, 0) * (1.f / 768.f);
    float inv = rsqrtf(var + EPSQ);
    oH[tIdx(TQPAD, row, tid)]       = __float2half_rn(d0 * inv * sc[tid]       + bi[tid]);
    oH[tIdx(TQPAD, row, tid + 256)] = __float2half_rn(d1 * inv * sc[tid + 256] + bi[tid + 256]);
    oH[tIdx(TQPAD, row, tid + 512)] = __float2half_rn(d2 * inv * sc[tid + 512] + bi[tid + 512]);
}

__global__ void final_ln_k(const float* __restrict__ xt, const float* __restrict__ sc,
                           const float* __restrict__ bi, float* __restrict__ out) {
    int b = blockIdx.x, tid = threadIdx.x;
    const float* xr = xt + (size_t)(b * SQ) * DQ;
    float r0 = xr[tid], r1 = xr[tid + 256], r2 = xr[tid + 512];
    float mean = block_red(r0 + r1 + r2, 0) * (1.f / 768.f);
    float d0 = r0 - mean, d1 = r1 - mean, d2 = r2 - mean;
    float var = block_red(d0 * d0 + d1 * d1 + d2 * d2, 0) * (1.f / 768.f);
    float inv = rsqrtf(var + EPSQ);
    float* yr = out + (size_t)b * DQ;
    yr[tid]       = d0 * inv * sc[tid]       + bi[tid];
    yr[tid + 256] = d1 * inv * sc[tid + 256] + bi[tid + 256];
    yr[tid + 512] = d2 * inv * sc[tid + 512] + bi[tid + 512];
}

// ============== HMMA GEMM v12 ==============
// T2=1: 2-term A, 2-stage (patch only). T2=0: 1-term A, 3-stage. Both 2 CTAs/SM.
// OS: 0 = fp32 row-major, 1 = tiled fp16 hi-plane, 2 = plain fp16 row-major.
#define ARR_A 16384
#define ARR_B 16384
#define GT_SMEM 98304                 // = 2*(2A+B) = 3*(A+B)

template<int ACT, int OS, int RS, int T2>
__global__ void __launch_bounds__(256, 2) gemm_k(
    const __half* __restrict__ aH, const __half* __restrict__ aL,
    const __half* __restrict__ wH,
    const float* __restrict__ bias, const float* __restrict__ res,
    float* __restrict__ outF,
    __half* __restrict__ oH,
    int M, int Mpad, int N, int K) {
    extern __shared__ char smem[];
    __shared__ __align__(8) uint64_t mbar_store[3];
    uint32_t sb = smem_u32(smem);
    uint32_t mb = smem_u32(mbar_store);
    int tid = threadIdx.x;
    int lane = tid & 31, w = tid >> 5;
    int warpM = w >> 2, warpN = w & 3;
    int g = lane >> 2, q = lane & 3;
    int bm = blockIdx.y * 128, bn = blockIdx.x * 128;
    const int nkt = K >> 6;

    constexpr int NS = T2 ? 2 : 3;
    constexpr uint32_t STGB = T2 ? (2 * ARR_A + ARR_B) : (ARR_A + ARR_B);
    constexpr uint32_t WOFF = T2 ? (2 * ARR_A) : ARR_A;

    if (tid == 0) {
        #pragma unroll
        for (int s = 0; s < NS; s++) MBAR_INIT(mb + s * 8, 1);
        FENCE_ASYNC();
    }
    __syncthreads();

    auto fill = [&](int j) {
        int fb = j % NS;
        uint32_t st = sb + fb * STGB;
        uint32_t m = mb + fb * 8;
        MBAR_EXPECT(m, STGB);
        bulkcp(st,        aH + ((size_t)j * Mpad + bm) * 64, ARR_A, m);
        if (T2)
            bulkcp(st + ARR_A, aL + ((size_t)j * Mpad + bm) * 64, ARR_A, m);
        bulkcp(st + WOFF, wH + ((size_t)j * N + bn) * 64,    ARR_B, m);
    };

    if (tid == 0) { fill(0); fill(1); }

    float acc[4][4][4];
    #pragma unroll
    for (int i = 0; i < 4; i++)
        #pragma unroll
        for (int j = 0; j < 4; j++)
            #pragma unroll
            for (int c = 0; c < 4; c++) acc[i][j][c] = 0.f;

    int lane7 = lane & 7, hi = lane >> 4;
    uint32_t cb[4];
    #pragma unroll
    for (int kk = 0; kk < 4; kk++) cb[kk] = (uint32_t)(((kk * 2 + hi) ^ lane7) << 4);
    uint32_t arow_off = (uint32_t)(warpM * 64 + (lane & 15)) * 128;
    uint32_t brow_off = (uint32_t)(warpN * 32 + (lane & 15)) * 128 + WOFF;

    for (int kt = 0; kt < nkt; kt++) {
        int d = kt / NS;
        int buf = kt - d * NS;
        mbar_wait(mb + buf * 8, (uint32_t)(d & 1));
        __syncthreads();
        if (T2) {
            if (tid == 0 && kt >= 1 && kt + 1 < nkt) fill(kt + 1);
        } else {
            if (tid == 0 && kt + 2 < nkt) fill(kt + 2);
        }

        uint32_t st = sb + buf * STGB;
        #pragma unroll
        for (int kk = 0; kk < 4; kk++) {
            uint32_t ah[4][4], al[4][4];
            #pragma unroll
            for (int i = 0; i < 4; i++) {
                uint32_t addr = st + arow_off + i * 2048 + cb[kk];
                LDSMX4(ah[i], addr);
                if (T2) LDSMX4(al[i], addr + ARR_A);
            }
            #pragma unroll
            for (int jj = 0; jj < 2; jj++) {
                uint32_t bh[4];
                LDSMX4(bh, st + brow_off + jj * 2048 + cb[kk]);
                #pragma unroll
                for (int sel = 0; sel < 2; sel++) {
                    int j = jj * 2 + sel;
                    uint32_t b0 = bh[sel], b1 = bh[sel + 2];
                    #pragma unroll
                    for (int i = 0; i < 4; i++) {
                        mma16816(acc[i][j], ah[i][0], ah[i][1], ah[i][2], ah[i][3], b0, b1);
                        if (T2)
                            mma16816(acc[i][j], al[i][0], al[i][1], al[i][2], al[i][3], b0, b1);
                    }
                }
            }
        }
    }

    #pragma unroll
    for (int i = 0; i < 4; i++) {
        int m0 = bm + warpM * 64 + i * 16 + g;
        #pragma unroll
        for (int j = 0; j < 4; j++) {
            int n0 = bn + warpN * 32 + j * 8 + q * 2;
            float bx = bias ? bias[n0] : 0.f;
            float by = bias ? bias[n0 + 1] : 0.f;
            #pragma unroll
            for (int half = 0; half < 2; half++) {
                int m = m0 + half * 8;
                if (m >= M) continue;
                float v0 = acc[i][j][half * 2 + 0] + bx;
                float v1 = acc[i][j][half * 2 + 1] + by;
                if (RS) {
                    const float* rp = res + (size_t)m * N + n0;
                    v0 += rp[0]; v1 += rp[1];
                }
                if (ACT) {
                    v0 = gelu_f(v0);
                    v1 = gelu_f(v1);
                }
                if (OS == 1) {
                    __half2 hp = __floats2half2_rn(v0, v1);
                    *(__half2*)&oH[tIdx(TQPAD, m, n0)] = hp;
                } else if (OS == 2) {
                    __half2 hp = __floats2half2_rn(v0, v1);
                    *(__half2*)&oH[(size_t)m * N + n0] = hp;
                } else {
                    *(float2*)(outF + (size_t)m * N + n0) = make_float2(v0, v1);
                }
            }
        }
    }
}

// ---------------- cls-row attention device fn (fp16 qkv in, hi plane out) ----------------
__device__ void cls_attn_dev(const __half* __restrict__ qkv,
                             __half* __restrict__ oH,
                             int bh, float* ws) {
    float* sc = ws;
    float* qv = ws + 1600;
    float* op = ws + 1664;
    int b = bh / 12, h = bh % 12;
    int tid = threadIdx.x;
    size_t base = (size_t)(b * SQ) * 2304 + (size_t)h * 64;
    if (tid < 64) qv[tid] = __half2float(qkv[base + tid]) * SCALEQ;
    __syncthreads();
    float lmax = -1e30f;
    for (int s = tid; s < SQ; s += 256) {
        const __half* kp = qkv + (size_t)(b * SQ + s) * 2304 + 768 + h * 64;
        float d = 0.f;
        #pragma unroll
        for (int i = 0; i < 64; i += 2) {
            __half2 kv = *(const __half2*)(kp + i);
            float2 kf = __half22float2(kv);
            d += qv[i] * kf.x + qv[i + 1] * kf.y;
        }
        sc[s] = d; lmax = fmaxf(lmax, d);
    }
    float mx = block_red(lmax, 1);
    float lsum = 0.f;
    for (int s = tid; s < SQ; s += 256) {
        float e = __expf(sc[s] - mx);
        sc[s] = e; lsum += e;
    }
    float den = block_red(lsum, 0);
    __syncthreads();
    int part = tid >> 6, d = tid & 63;
    float acc = 0.f;
    for (int s = part; s < SQ; s += 4)
        acc += sc[s] * __half2float(qkv[(size_t)(b * SQ + s) * 2304 + 1536 + h * 64 + d]);
    op[tid] = acc;
    __syncthreads();
    if (tid < 64) {
        float t = op[tid] + op[tid + 64] + op[tid + 128] + op[tid + 192];
        oH[tIdx(TQPAD, b * SQ, h * 64 + tid)] = __float2half_rn(t / den);
    }
}

// ---------------- fused time + cls attention ----------------
#define CLS_WS_BYTES (1920*4)
__global__ void time_cls_k(const __half* __restrict__ qkv,
                           __half* __restrict__ oH) {
    extern __shared__ float ws[];
    if (blockIdx.x >= 1176) {
        cls_attn_dev(qkv, oH, blockIdx.x - 1176, ws);
        return;
    }
    int g = blockIdx.x * 8 + (threadIdx.x >> 5);
    int lane = threadIdx.x & 31;
    int bh = g / 196, pos = g % 196;
    int b = bh / 12, h = bh % 12;
    float K0[9], K1[9], V0[9], V1[9];
    #pragma unroll
    for (int kk = 0; kk < 9; kk++) {
        int s = kk ? (1 + (kk - 1) * 196 + pos) : 0;
        size_t o = (size_t)(b * SQ + s) * 2304 + h * 64;
        K0[kk] = __half2float(qkv[o + 768 + lane]);
        K1[kk] = __half2float(qkv[o + 768 + lane + 32]);
        V0[kk] = __half2float(qkv[o + 1536 + lane]);
        V1[kk] = __half2float(qkv[o + 1536 + lane + 32]);
    }
    for (int fq = 0; fq < 8; fq++) {
        int sq = 1 + fq * 196 + pos;
        size_t oq = (size_t)(b * SQ + sq) * 2304 + h * 64;
        float q0 = __half2float(qkv[oq + lane]) * SCALEQ;
        float q1 = __half2float(qkv[oq + lane + 32]) * SCALEQ;
        float sc[9];
        #pragma unroll
        for (int kk = 0; kk < 9; kk++) {
            float p = q0 * K0[kk] + q1 * K1[kk];
            #pragma unroll
            for (int o = 16; o; o >>= 1) p += __shfl_xor_sync(0xffffffffu, p, o);
            sc[kk] = p;
        }
        float mx = sc[0];
        #pragma unroll
        for (int kk = 1; kk < 9; kk++) mx = fmaxf(mx, sc[kk]);
        float den = 0.f;
        #pragma unroll
        for (int kk = 0; kk < 9; kk++) { sc[kk] = __expf(sc[kk] - mx); den += sc[kk]; }
        float inv = 1.f / den;
        float a0 = 0.f, a1 = 0.f;
        #pragma unroll
        for (int kk = 0; kk < 9; kk++) { a0 += sc[kk] * V0[kk]; a1 += sc[kk] * V1[kk]; }
        int m = b * SQ + sq;
        oH[tIdx(TQPAD, m, h * 64 + lane)]      = __float2half_rn(a0 * inv);
        oH[tIdx(TQPAD, m, h * 64 + lane + 32)] = __float2half_rn(a1 * inv);
    }
}

// ---------------- fused space + cls attention ----------------
#define SPACE_SMEM ((197*65*2 + 8*197 + 8*64) * 4)
__global__ void space_cls_k(const __half* __restrict__ qkv,
                            __half* __restrict__ oH) {
    extern __shared__ float sm[];
    if (blockIdx.x >= 384) {
        cls_attn_dev(qkv, oH, blockIdx.x - 384, sm);
        return;
    }
    float* Ks = sm;
    float* Vs = Ks + 197 * 65;
    float* pb = Vs + 197 * 65;
    float* qb = pb + 8 * 197;
    int blk = blockIdx.x;
    int fr = blk % 8, h = (blk / 8) % 12, b = blk / 96;
    int tid = threadIdx.x, lane = tid & 31, w = tid >> 5;
    for (int idx = tid; idx < 197 * 64; idx += 256) {
        int kk = idx >> 6, d = idx & 63;
        int s = kk ? (1 + fr * 196 + kk - 1) : 0;
        size_t o = (size_t)(b * SQ + s) * 2304 + h * 64;
        Ks[kk * 65 + d] = __half2float(qkv[o + 768 + d]);
        Vs[kk * 65 + d] = __half2float(qkv[o + 1536 + d]);
    }
    __syncthreads();
    for (int qi = w; qi < 196; qi += 8) {
        int sq = 1 + fr * 196 + qi;
        size_t oq = (size_t)(b * SQ + sq) * 2304 + h * 64;
        qb[w * 64 + lane]      = __half2float(qkv[oq + lane]) * SCALEQ;
        qb[w * 64 + lane + 32] = __half2float(qkv[oq + lane + 32]) * SCALEQ;
        __syncwarp();
        float ls[7];
        float lmax = -1e30f;
        int cnt = 0;
        for (int kk = lane; kk < 197; kk += 32) {
            float s = 0.f;
            #pragma unroll
            for (int d = 0; d < 64; d++) s += qb[w * 64 + d] * Ks[kk * 65 + d];
            ls[cnt++] = s; lmax = fmaxf(lmax, s);
        }
        #pragma unroll
        for (int o = 16; o; o >>= 1) lmax = fmaxf(lmax, __shfl_xor_sync(0xffffffffu, lmax, o));
        float lsum = 0.f; cnt = 0;
        for (int kk = lane; kk < 197; kk += 32) {
            float e = __expf(ls[cnt++] - lmax);
            pb[w * 197 + kk] = e; lsum += e;
        }
        #pragma unroll
        for (int o = 16; o; o >>= 1) lsum += __shfl_xor_sync(0xffffffffu, lsum, o);
        float inv = 1.f / lsum;
        __syncwarp();
        float a0 = 0.f, a1 = 0.f;
        for (int kk = 0; kk < 197; kk++) {
            float p = pb[w * 197 + kk];
            a0 += p * Vs[kk * 65 + lane];
            a1 += p * Vs[kk * 65 + lane + 32];
        }
        int m = b * SQ + sq;
        oH[tIdx(TQPAD, m, h * 64 + lane)]      = __float2half_rn(a0 * inv);
        oH[tIdx(TQPAD, m, h * 64 + lane + 32)] = __float2half_rn(a1 * inv);
        __syncwarp();
    }
}

// ================== host orchestration ==================
// mode: 0 fp32 out (2-term, patch), 2 gelu->tiled fp16 (1-term),
//       3 fp32+res (1-term), 5 plain fp16 out (1-term, qkv)
static void gemm(const __half* aH, const __half* aL, const __half* wHp,
                 const float* bias, const float* res,
                 float* outF, __half* oH,
                 int M, int Mpad, int N, int K, int mode) {
    dim3 g(N / 128, (M + 127) / 128);
    if (mode == 0)
        gemm_k<0,0,0,1><<<g, 256, GT_SMEM>>>(aH, aL, wHp, bias, res, outF, oH, M, Mpad, N, K);
    else if (mode == 2)
        gemm_k<1,1,0,0><<<g, 256, GT_SMEM>>>(aH, aL, wHp, bias, res, outF, oH, M, Mpad, N, K);
    else if (mode == 3)
        gemm_k<0,0,1,0><<<g, 256, GT_SMEM>>>(aH, aL, wHp, bias, res, outF, oH, M, Mpad, N, K);
    else
        gemm_k<0,2,0,0><<<g, 256, GT_SMEM>>>(aH, aL, wHp, bias, res, outF, oH, M, Mpad, N, K);
}

extern "C" void kernel_launch(void* const* d_in, const int* in_sizes, int n_in,
                              void* d_out, int out_size) {
    const float* x       = (const float*)d_in[0];
    const float* patch_w = (const float*)d_in[1];
    const float* patch_b = (const float*)d_in[2];
    const float* cls_tok = (const float*)d_in[3];
    const float* pos     = (const float*)d_in[4];
    const float* temp    = (const float*)d_in[5];
    const float* n1s = (const float*)d_in[6],  *n1b = (const float*)d_in[7];
    const float* n2s = (const float*)d_in[8],  *n2b = (const float*)d_in[9];
    const float* n3s = (const float*)d_in[10], *n3b = (const float*)d_in[11];
    const float* aqw = (const float*)d_in[12], *aqb = (const float*)d_in[13];
    const float* apw = (const float*)d_in[14], *apb = (const float*)d_in[15];
    const float* tqw = (const float*)d_in[16], *tqb = (const float*)d_in[17];
    const float* tpw = (const float*)d_in[18], *tpb = (const float*)d_in[19];
    const float* f1w = (const float*)d_in[20], *f1b = (const float*)d_in[21];
    const float* f2w = (const float*)d_in[22], *f2b = (const float*)d_in[23];
    const float* nfs = (const float*)d_in[24], *nfb = (const float*)d_in[25];
    float* out = (float*)d_out;

    float *xt, *pe, *res;
    __half *qkvh, *aH, *aL, *hH, *wp;
    cudaGetSymbolAddress((void**)&xt,   g_xt);
    cudaGetSymbolAddress((void**)&pe,   g_pe);
    cudaGetSymbolAddress((void**)&res,  g_res);
    cudaGetSymbolAddress((void**)&qkvh, g_qkvh);
    cudaGetSymbolAddress((void**)&aH,   g_aH);
    cudaGetSymbolAddress((void**)&aL,   g_aL);
    cudaGetSymbolAddress((void**)&hH,   g_hH);
    cudaGetSymbolAddress((void**)&wp,   g_w);

    cudaFuncSetAttribute(space_cls_k, cudaFuncAttributeMaxDynamicSharedMemorySize, SPACE_SMEM);
    cudaFuncSetAttribute(gemm_k<0,0,0,1>, cudaFuncAttributeMaxDynamicSharedMemorySize, GT_SMEM);
    cudaFuncSetAttribute(gemm_k<1,1,0,0>, cudaFuncAttributeMaxDynamicSharedMemorySize, GT_SMEM);
    cudaFuncSetAttribute(gemm_k<0,0,1,0>, cudaFuncAttributeMaxDynamicSharedMemorySize, GT_SMEM);
    cudaFuncSetAttribute(gemm_k<0,2,0,0>, cudaFuncAttributeMaxDynamicSharedMemorySize, GT_SMEM);

    // ---- one-shot weight conversion, batched per weight type ----
    {
        auto launch = [&](const float* src, __half* dst, int N, int K, int layers) {
            int tot = layers * N * (K >> 2);
            cvtw_k<<<(tot + 255) / 256, 256>>>(src, dst, N, K, layers);
        };
        launch(patch_w, wp + W_PATCH, 768, 768, 1);
        launch(tqw, wp + W_TQW, 3 * DQ, DQ, LQ);
        launch(tpw, wp + W_TPW, DQ, DQ, LQ);
        launch(aqw, wp + W_AQW, 3 * DQ, DQ, LQ);
        launch(apw, wp + W_APW, DQ, DQ, LQ);
        launch(f1w, wp + W_F1W, HIDQ, DQ, LQ);
        launch(f2w, wp + W_F2W, DQ, HIDQ, LQ);
    }

    // ---- patch embedding (2-term, fp32 out) ----
    im2col_k<<<(6272 * 768 + 255) / 256, 256>>>(x, aH, aL);
    gemm(aH, aL, wp + W_PATCH, nullptr, nullptr, pe, nullptr,
         6272, TQPAD, 768, 768, 0);
    assemble_k<<<(TQ * DQ + 255) / 256, 256>>>(pe, patch_b, cls_tok, pos, temp, xt);

    for (int l = 0; l < LQ; l++) {
        // ---- time attention ----
        ln_k<<<TQ, 256>>>(xt, n3s + (size_t)l * DQ, n3b + (size_t)l * DQ, aH);
        gemm(aH, nullptr, wp + W_TQW + (size_t)l * 3 * DQ * DQ, tqb + (size_t)l * 3 * DQ,
             nullptr, nullptr, qkvh, TQ, TQPAD, 3 * DQ, DQ, 5);     // qkv -> fp16
        time_cls_k<<<1176 + 48, 256, CLS_WS_BYTES>>>(qkvh, aH);
        gemm(aH, nullptr, wp + W_TPW + (size_t)l * DQ * DQ, tpb + (size_t)l * DQ,
             xt, res, nullptr, TQ, TQPAD, DQ, DQ, 3);               // time_res
        // ---- space attention ----
        ln_k<<<TQ, 256>>>(res, n1s + (size_t)l * DQ, n1b + (size_t)l * DQ, aH);
        gemm(aH, nullptr, wp + W_AQW + (size_t)l * 3 * DQ * DQ, aqb + (size_t)l * 3 * DQ,
             nullptr, nullptr, qkvh, TQ, TQPAD, 3 * DQ, DQ, 5);
        space_cls_k<<<384 + 48, 256, SPACE_SMEM>>>(qkvh, aH);
        gemm(aH, nullptr, wp + W_APW + (size_t)l * DQ * DQ, apb + (size_t)l * DQ,
             xt, res, nullptr, TQ, TQPAD, DQ, DQ, 3);               // space_res
        // ---- MLP ----
        ln_k<<<TQ, 256>>>(res, n2s + (size_t)l * DQ, n2b + (size_t)l * DQ, aH);
        gemm(aH, nullptr, wp + W_F1W + (size_t)l * HIDQ * DQ, f1b + (size_t)l * HIDQ,
             nullptr, nullptr, hH, TQ, TQPAD, HIDQ, DQ, 2);         // gelu -> tiled fp16
        gemm(hH, nullptr, wp + W_F2W + (size_t)l * DQ * HIDQ, f2b + (size_t)l * DQ,
             res, xt, nullptr, TQ, TQPAD, DQ, HIDQ, 3);             // xt = res + mlp
    }

    final_ln_k<<<BQ, 256>>>(xt, nfs, nfb, out);
}